// round 12
// baseline (speedup 1.0000x reference)
#include <cuda_runtime.h>
#include <cuda_bf16.h>
#include <cstdint>

// Problem constants
#define NL   6
#define NH   8
#define DMOD 512
#define DKV  64
#define DFF  2048
#define NB   8
#define SEQ  512
#define NTOK 4096          // NB*SEQ
#define NHB  64            // NH*NB

#define X_ELEMS   (NTOK*DMOD)                 // 2,097,152
#define ATT_PER_L ((size_t)NHB*SEQ*SEQ)       // 16,777,216
#define SLF_OFF   ((size_t)X_ELEMS)
#define ENC_OFF   (SLF_OFF + (size_t)NL*ATT_PER_L)
#define FULL_OUT  (ENC_OFF + (size_t)NL*ATT_PER_L)   // 203,423,744

// per-layer bf16 weight bank layout (element offsets)
#define WOFF_SQ   0
#define WOFF_SK   262144
#define WOFF_SV   524288
#define WOFF_SPW  786432
#define WOFF_EQ   1048576
#define WOFF_EK   1310720
#define WOFF_EV   1572864
#define WOFF_EPW  1835008
#define WOFF_W1   2097152
#define WOFF_W2   3145728
#define WL_SIZE   4194304

// ---------------- scratch (no allocations allowed) ----------------
__device__ float g_x  [NTOK*DMOD];
__device__ float g_y  [NTOK*DMOD];
__device__ __nv_bfloat16 g_qkvh[3*NHB*SEQ*DKV];   // q|k|v hi, head-major [hb][t][e]
__device__ __nv_bfloat16 g_qkvl[3*NHB*SEQ*DKV];   // q|k|v lo
__device__ __nv_bfloat16 g_xhi [NTOK*DMOD];
__device__ __nv_bfloat16 g_xlo [NTOK*DMOD];
__device__ __nv_bfloat16 g_ehi [NTOK*DMOD];
__device__ __nv_bfloat16 g_elo [NTOK*DMOD];
__device__ __nv_bfloat16 g_aohi[NTOK*DMOD];
__device__ __nv_bfloat16 g_aolo[NTOK*DMOD];
__device__ __nv_bfloat16 g_hhi [NTOK*DFF];
__device__ __nv_bfloat16 g_hlo [NTOK*DFF];
__device__ __nv_bfloat16 g_wbhi[(size_t)NL*WL_SIZE];
__device__ __nv_bfloat16 g_wblo[(size_t)NL*WL_SIZE];

struct P6 { const float* p[6]; };

// ---------------- helpers (baseline PTX only: sm_80-class) ----------------
__device__ __forceinline__ uint32_t smem_u32(const void* p) {
    uint32_t a;
    asm("{ .reg .u64 t; cvta.to.shared.u64 t, %1; cvt.u32.u64 %0, t; }" : "=r"(a) : "l"(p));
    return a;
}
__device__ __forceinline__ void cp16(uint32_t saddr, const void* g) {
    asm volatile("cp.async.cg.shared.global [%0], [%1], 16;" :: "r"(saddr), "l"(g));
}
#define CP_COMMIT() asm volatile("cp.async.commit_group;" ::: "memory")
#define CP_WAIT1()  asm volatile("cp.async.wait_group 1;" ::: "memory")
#define CP_WAIT0()  asm volatile("cp.async.wait_group 0;" ::: "memory")

__device__ __forceinline__ void ldsm_x4(uint32_t* r, uint32_t addr) {
    asm volatile("ldmatrix.sync.aligned.m8n8.x4.shared.b16 {%0,%1,%2,%3}, [%4];"
                 : "=r"(r[0]), "=r"(r[1]), "=r"(r[2]), "=r"(r[3]) : "r"(addr));
}
__device__ __forceinline__ void ldsm_x4_t(uint32_t* r, uint32_t addr) {
    asm volatile("ldmatrix.sync.aligned.m8n8.x4.trans.shared.b16 {%0,%1,%2,%3}, [%4];"
                 : "=r"(r[0]), "=r"(r[1]), "=r"(r[2]), "=r"(r[3]) : "r"(addr));
}
__device__ __forceinline__ void mma16816(float* d, const uint32_t* a, const uint32_t* b) {
    asm volatile("mma.sync.aligned.m16n8k16.row.col.f32.bf16.bf16.f32 "
                 "{%0,%1,%2,%3}, {%4,%5,%6,%7}, {%8,%9}, {%0,%1,%2,%3};"
                 : "+f"(d[0]), "+f"(d[1]), "+f"(d[2]), "+f"(d[3])
                 : "r"(a[0]), "r"(a[1]), "r"(a[2]), "r"(a[3]), "r"(b[0]), "r"(b[1]));
}

__device__ __forceinline__ void fsplit(float v, __nv_bfloat16& h, __nv_bfloat16& l) {
    h = __float2bfloat16(v);
    l = __float2bfloat16(v - __bfloat162float(h));
}

// ---------------- embedding (fp32 x + bf16 hi/lo) ----------------
__global__ void embed_k(const int* __restrict__ seq, const int* __restrict__ pos,
                        const float* __restrict__ wemb, const float* __restrict__ pemb,
                        float* __restrict__ x,
                        __nv_bfloat16* __restrict__ xhi, __nv_bfloat16* __restrict__ xlo) {
    int n = blockIdx.x;
    int s = seq[n], p = pos[n];
    const float* we = wemb + (size_t)s * DMOD;
    const float* pe = pemb + (size_t)p * DMOD;
    for (int c = threadIdx.x; c < DMOD; c += blockDim.x) {
        float v = we[c] + pe[c];
        x[(size_t)n * DMOD + c] = v;
        __nv_bfloat16 h, l; fsplit(v, h, l);
        xhi[(size_t)n * DMOD + c] = h;
        xlo[(size_t)n * DMOD + c] = l;
    }
}

// ---------------- fp32 -> bf16 hi/lo split (for enc_output) ----------------
__global__ void conv_split_k(const float* __restrict__ src,
                             __nv_bfloat16* __restrict__ hi, __nv_bfloat16* __restrict__ lo,
                             int n) {
    int i = blockIdx.x * blockDim.x + threadIdx.x;
    if (i < n) {
        __nv_bfloat16 h, l; fsplit(src[i], h, l);
        hi[i] = h; lo[i] = l;
    }
}

// ---------------- batched qkv weight repack (all 6 tensors x 6 layers) ----------------
__global__ void qkv_repack_all(P6 srcs,
                               __nv_bfloat16* __restrict__ dhi_b,
                               __nv_bfloat16* __restrict__ dlo_b) {
    __shared__ float t[64][65];
    const int woff[6] = {WOFF_SQ, WOFF_SK, WOFF_SV, WOFF_EQ, WOFF_EK, WOFF_EV};
    int ti = blockIdx.y, l = blockIdx.z;
    const float* src = srcs.p[ti] + (size_t)l * (NH * DMOD * DKV);
    __nv_bfloat16* dhi = dhi_b + (size_t)l * WL_SIZE + woff[ti];
    __nv_bfloat16* dlo = dlo_b + (size_t)l * WL_SIZE + woff[ti];

    int h = blockIdx.x >> 3, dt = blockIdx.x & 7;
    int d0 = dt * 64;
    int tid = threadIdx.x;
    for (int i = tid; i < 4096; i += 256) {
        int d = i >> 6, e = i & 63;
        t[e][d] = src[h * (DMOD * DKV) + (d0 + d) * DKV + e];
    }
    __syncthreads();
    for (int i = tid; i < 4096; i += 256) {
        int e = i >> 6, d = i & 63;
        __nv_bfloat16 hh, ll; fsplit(t[e][d], hh, ll);
        size_t o = (size_t)(h * 64 + e) * DMOD + d0 + d;
        dhi[o] = hh; dlo[o] = ll;
    }
}

// ---------------- batched projection-weight transpose (slf_pw + enc_pw, all layers) ----------------
__global__ void pw_repack_all(const float* __restrict__ slf_pw, const float* __restrict__ enc_pw,
                              __nv_bfloat16* __restrict__ dhi_b, __nv_bfloat16* __restrict__ dlo_b) {
    __shared__ float t[32][33];
    int z = blockIdx.z, l = z >> 1, te = z & 1;
    const float* src = (te ? enc_pw : slf_pw) + (size_t)l * DMOD * DMOD;
    size_t doff = (size_t)l * WL_SIZE + (te ? WOFF_EPW : WOFF_SPW);
    __nv_bfloat16* dhi = dhi_b + doff;
    __nv_bfloat16* dlo = dlo_b + doff;

    int c0 = blockIdx.x * 32, r0 = blockIdx.y * 32;
    int x = threadIdx.x, y = threadIdx.y;        // 32 x 8
    for (int yy = y; yy < 32; yy += 8)
        t[yy][x] = src[(size_t)(r0 + yy) * DMOD + c0 + x];
    __syncthreads();
    for (int yy = y; yy < 32; yy += 8) {
        __nv_bfloat16 hh, ll; fsplit(t[x][yy], hh, ll);
        size_t o = (size_t)(c0 + yy) * DMOD + r0 + x;
        dhi[o] = hh; dlo[o] = ll;
    }
}

// ---------------- batched FFN weight transpose: [R,C] -> [C,R], all layers via z ----------------
__global__ void ffn_repack_all(const float* __restrict__ w,
                               __nv_bfloat16* __restrict__ dhi_b, __nv_bfloat16* __restrict__ dlo_b,
                               int R, int C, int woff) {
    __shared__ float t[32][33];
    int l = blockIdx.z;
    const float* src = w + (size_t)l * R * C;
    size_t doff = (size_t)l * WL_SIZE + woff;
    __nv_bfloat16* dhi = dhi_b + doff;
    __nv_bfloat16* dlo = dlo_b + doff;

    int c0 = blockIdx.x * 32, r0 = blockIdx.y * 32;
    int x = threadIdx.x, y = threadIdx.y;        // 32 x 8
    for (int yy = y; yy < 32; yy += 8)
        t[yy][x] = src[(size_t)(r0 + yy) * C + c0 + x];
    __syncthreads();
    for (int yy = y; yy < 32; yy += 8) {
        __nv_bfloat16 hh, ll; fsplit(t[x][yy], hh, ll);
        size_t o = (size_t)(c0 + yy) * R + r0 + x;
        dhi[o] = hh; dlo[o] = ll;
    }
}

// ---------------- mma.sync bf16-split GEMM: C[M,N] = A[M,K] @ B[N,K]^T ----------------
// 4 warps, 2x2 warp grid, warp tile 64x64; 2 CTAs/SM for latency hiding.
// 3 passes: Ahi*Bhi + Ahi*Blo + Alo*Bhi, fp32 register accumulators.
// mode 1: +bias -> fp32 Cf;  mode 2: +bias,relu -> bf16 Chi/Clo;
// mode 3: qkv scatter -> bf16 hi/lo Chi/Clo head-major.
#define GM_PITCH 40                  // bf16 elems per smem row (80B, conflict-free ldmatrix)
#define GM_TILEB (128*GM_PITCH*2)    // 10240 B per 128x32 tile
#define GM_STAGE (4*GM_TILEB)        // Ahi|Alo|Bhi|Blo = 40960 B
#define GM_SMEM  (2*GM_STAGE)        // 81920 B double buffered

__global__ __launch_bounds__(128, 2) void gemm_mma_k(
    const __nv_bfloat16* __restrict__ Ahi, const __nv_bfloat16* __restrict__ Alo,
    const __nv_bfloat16* __restrict__ Bhi, const __nv_bfloat16* __restrict__ Blo,
    const float* __restrict__ bias,
    float* __restrict__ Cf,
    __nv_bfloat16* __restrict__ Chi, __nv_bfloat16* __restrict__ Clo,
    int M, int N, int K, int mode)
{
    extern __shared__ __align__(16) char smem[];
    uint32_t sb = smem_u32(smem);
    const int tid = threadIdx.x, lane = tid & 31, w = tid >> 5;
    const int wm = w >> 1, wn = w & 1;          // warp grid 2 x 2 -> 64 x 64 tiles
    const int n0 = blockIdx.x * 128, m0 = blockIdx.y * 128;

    const __nv_bfloat16* srcs[4] = {
        Ahi + (size_t)m0 * K, Alo + (size_t)m0 * K,
        Bhi + (size_t)n0 * K, Blo + (size_t)n0 * K };

    // loader: 128 threads, each 4 rows x 4 tensors, 16B segs (coalesced 64B groups)
    const int lrow = tid >> 2, lc8 = (tid & 3) * 8;

    auto load_chunk = [&](int kc, int st) {
        const int k0 = kc * 32;
        uint32_t stb = sb + st * GM_STAGE;
#pragma unroll
        for (int t = 0; t < 4; t++) {
            uint32_t tb = stb + t * GM_TILEB;
            const __nv_bfloat16* src = srcs[t] + k0 + lc8;
#pragma unroll
            for (int j = 0; j < 4; j++) {
                int r = lrow + j * 32;
                cp16(tb + (r * GM_PITCH + lc8) * 2, src + (size_t)r * K);
            }
        }
    };

    float acc[4][8][4];
#pragma unroll
    for (int a = 0; a < 4; a++)
#pragma unroll
        for (int b = 0; b < 8; b++)
#pragma unroll
            for (int c = 0; c < 4; c++) acc[a][b][c] = 0.f;

    const int nch = K >> 5;
    load_chunk(0, 0); CP_COMMIT();

    const uint32_t a_off = ((wm * 64 + (lane & 15)) * GM_PITCH + ((lane >> 4) << 3)) * 2;
    const int b_lrow = (lane & 7) + ((lane & 16) ? 8 : 0);
    const int b_lcol = ((lane & 8) ? 8 : 0);

    for (int kc = 0; kc < nch; kc++) {
        if (kc + 1 < nch) { load_chunk(kc + 1, (kc + 1) & 1); CP_COMMIT(); CP_WAIT1(); }
        else { CP_WAIT0(); }
        __syncthreads();

        uint32_t stb = sb + (kc & 1) * GM_STAGE;
#pragma unroll
        for (int ks = 0; ks < 2; ks++) {
            const uint32_t kso = ks * 32;   // 16 elems * 2B
            uint32_t ah[4][4], al[4][4];
#pragma unroll
            for (int mi = 0; mi < 4; mi++) {
                uint32_t off = a_off + mi * 16 * GM_PITCH * 2 + kso;
                ldsm_x4(ah[mi], stb + 0 * GM_TILEB + off);
                ldsm_x4(al[mi], stb + 1 * GM_TILEB + off);
            }
#pragma unroll
            for (int ng = 0; ng < 2; ng++) {
                uint32_t bh[2][4], bl[2][4];
#pragma unroll
                for (int np = 0; np < 2; np++) {
                    uint32_t off = ((wn * 64 + ng * 32 + np * 16 + b_lrow) * GM_PITCH
                                    + b_lcol) * 2 + kso;
                    ldsm_x4(bh[np], stb + 2 * GM_TILEB + off);
                    ldsm_x4(bl[np], stb + 3 * GM_TILEB + off);
                }
#pragma unroll
                for (int mi = 0; mi < 4; mi++)
#pragma unroll
                    for (int nt = 0; nt < 4; nt++) {
                        const uint32_t* bhf = &bh[nt >> 1][(nt & 1) * 2];
                        const uint32_t* blf = &bl[nt >> 1][(nt & 1) * 2];
                        float* ac = acc[mi][ng * 4 + nt];
                        mma16816(ac, ah[mi], bhf);
                        mma16816(ac, ah[mi], blf);
                        mma16816(ac, al[mi], bhf);
                    }
            }
        }
        __syncthreads();
    }

    // epilogue
#pragma unroll
    for (int mi = 0; mi < 4; mi++) {
        int r0 = m0 + wm * 64 + mi * 16 + (lane >> 2);
#pragma unroll
        for (int nj = 0; nj < 8; nj++) {
            int col = n0 + wn * 64 + nj * 8 + (lane & 3) * 2;
            float c0 = acc[mi][nj][0], c1 = acc[mi][nj][1];
            float c2 = acc[mi][nj][2], c3 = acc[mi][nj][3];
            if (mode == 3) {
                int m = col >> 9, hh_ = (col >> 6) & 7, e = col & 63;
#pragma unroll
                for (int rr = 0; rr < 2; rr++) {
                    int row = r0 + rr * 8;
                    int b_ = row >> 9, t = row & 511;
                    size_t off = (size_t)m * 2097152 +
                                 (((size_t)(hh_ * NB + b_) * SEQ + t) * DKV + e);
                    float v0 = rr ? c2 : c0, v1 = rr ? c3 : c1;
                    __nv_bfloat16 h0, l0, h1, l1;
                    fsplit(v0, h0, l0); fsplit(v1, h1, l1);
                    __nv_bfloat162 ph; ph.x = h0; ph.y = h1;
                    __nv_bfloat162 pl; pl.x = l0; pl.y = l1;
                    *(__nv_bfloat162*)(Chi + off) = ph;
                    *(__nv_bfloat162*)(Clo + off) = pl;
                }
            } else if (mode == 1) {
                float2 bv = *(const float2*)(bias + col);
                float2 v0; v0.x = c0 + bv.x; v0.y = c1 + bv.y;
                float2 v1; v1.x = c2 + bv.x; v1.y = c3 + bv.y;
                *(float2*)(Cf + (size_t)r0 * N + col)       = v0;
                *(float2*)(Cf + (size_t)(r0 + 8) * N + col) = v1;
            } else {
                float2 bv = *(const float2*)(bias + col);
                float p0 = fmaxf(c0 + bv.x, 0.f), p1 = fmaxf(c1 + bv.y, 0.f);
                float p2 = fmaxf(c2 + bv.x, 0.f), p3 = fmaxf(c3 + bv.y, 0.f);
                __nv_bfloat16 h0, l0, h1, l1, h2, l2, h3, l3;
                fsplit(p0, h0, l0); fsplit(p1, h1, l1);
                fsplit(p2, h2, l2); fsplit(p3, h3, l3);
                __nv_bfloat162 ph0; ph0.x = h0; ph0.y = h1;
                __nv_bfloat162 ph1; ph1.x = h2; ph1.y = h3;
                __nv_bfloat162 pl0; pl0.x = l0; pl0.y = l1;
                __nv_bfloat162 pl1; pl1.x = l2; pl1.y = l3;
                *(__nv_bfloat162*)(Chi + (size_t)r0 * N + col)       = ph0;
                *(__nv_bfloat162*)(Chi + (size_t)(r0 + 8) * N + col) = ph1;
                *(__nv_bfloat162*)(Clo + (size_t)r0 * N + col)       = pl0;
                *(__nv_bfloat162*)(Clo + (size_t)(r0 + 8) * N + col) = pl1;
            }
        }
    }
}

// ---------------- MMA attention ----------------
// Block = (qt, hb): 64 queries x 512 keys. 8 warps: wm = w&3 (16 rows), wn = w>>2 (half).
#define PT 72                      // bf16 pitch (144 B, 16B-phase conflict-free)
#define SC_PITCH 520
#define SC_OFF   0                 // fp32 [64][520] = 133120 B
#define QH_OFF   133120            // bf16 [64][72] = 9216 B
#define QL_OFF   (QH_OFF + 9216)
#define KV_OFF   (QL_OFF + 9216)   // 2 stages x (hi 9216 + lo 9216)
#define KV_STAGE 18432
#define PTH_OFF  (KV_OFF + 2*KV_STAGE)
#define PTL_OFF  (PTH_OFF + 9216)
#define BIAS_OFF (PTL_OFF + 9216)  // fp32 [512]
#define ATTN2_SMEM (BIAS_OFF + 2048)   // 208896 B

__global__ __launch_bounds__(256, 1) void attn_mma_k(
    const __nv_bfloat16* __restrict__ Qh, const __nv_bfloat16* __restrict__ Ql,
    const __nv_bfloat16* __restrict__ Kh, const __nv_bfloat16* __restrict__ Kl,
    const __nv_bfloat16* __restrict__ Vh, const __nv_bfloat16* __restrict__ Vl,
    const int* __restrict__ seq, float* __restrict__ probs,
    __nv_bfloat16* __restrict__ Ohi, __nv_bfloat16* __restrict__ Olo,
    int causal, int writeProbs)
{
    extern __shared__ __align__(16) char sm2[];
    uint32_t sbase = smem_u32(sm2);
    float* Sc = (float*)(sm2 + SC_OFF);
    float* biasS = (float*)(sm2 + BIAS_OFF);
    const int hb = blockIdx.y, qt = blockIdx.x;
    const int h = hb >> 3, b = hb & 7;
    const int tid = threadIdx.x, lane = tid & 31, w = tid >> 5;
    const int wm = w & 3, wn = w >> 2;
    const float scale = 0.044194173824159216f;   // 1/sqrt(512)

    for (int i = tid; i < 512; i += 256)
        biasS[i] = (seq[b * SEQ + i] == 0) ? -1e30f : 0.f;

    // Q tile -> smem (hi/lo)
    {
        int row = tid >> 2, s0 = (tid & 3) * 16;
        size_t gq = ((size_t)hb * SEQ + qt * 64 + row) * DKV + s0;
        *(uint4*)(sm2 + QH_OFF + (row * PT + s0) * 2)     = *(const uint4*)(Qh + gq);
        *(uint4*)(sm2 + QH_OFF + (row * PT + s0 + 8) * 2) = *(const uint4*)(Qh + gq + 8);
        *(uint4*)(sm2 + QL_OFF + (row * PT + s0) * 2)     = *(const uint4*)(Ql + gq);
        *(uint4*)(sm2 + QL_OFF + (row * PT + s0 + 8) * 2) = *(const uint4*)(Ql + gq + 8);
    }

    auto load_kv = [&](const __nv_bfloat16* Hs, const __nv_bfloat16* Ls, int st, int stage) {
        uint32_t sbst = sbase + KV_OFF + stage * KV_STAGE;
        size_t gbase = ((size_t)hb * SEQ + st * 64) * DKV;
#pragma unroll
        for (int j = 0; j < 2; j++) {
            int seg = tid + j * 256;
            int row = seg >> 3, c = (seg & 7) * 8;
            uint32_t so = sbst + (row * PT + c) * 2;
            cp16(so,        Hs + gbase + row * DKV + c);
            cp16(so + 9216, Ls + gbase + row * DKV + c);
        }
    };

    load_kv(Kh, Kl, 0, 0); CP_COMMIT();
    __syncthreads();

    // resident Q fragments
    uint32_t qhf[4][4], qlf[4][4];
#pragma unroll
    for (int ks = 0; ks < 4; ks++) {
        uint32_t addr = sbase + QH_OFF +
            ((wm * 16 + (lane & 15)) * PT + ks * 16 + ((lane >> 4) << 3)) * 2;
        ldsm_x4(qhf[ks], addr);
        ldsm_x4(qlf[ks], addr + 9216);
    }

    // ---- score phase ----
    for (int st = 0; st < 8; st++) {
        __syncthreads();
        if (st < 7) { load_kv(Kh, Kl, st + 1, (st + 1) & 1); CP_COMMIT(); CP_WAIT1(); }
        else { CP_WAIT0(); }
        __syncthreads();

        uint32_t kb = sbase + KV_OFF + (st & 1) * KV_STAGE;
        float acc[4][4];
#pragma unroll
        for (int i = 0; i < 4; i++)
#pragma unroll
            for (int j = 0; j < 4; j++) acc[i][j] = 0.f;

#pragma unroll
        for (int ks = 0; ks < 4; ks++) {
            uint32_t bh[2][4], bl[2][4];
#pragma unroll
            for (int np = 0; np < 2; np++) {
                uint32_t addr = kb + ((wn * 32 + np * 16 + (lane & 7) + ((lane & 16) ? 8 : 0)) * PT
                                      + ks * 16 + ((lane & 8) ? 8 : 0)) * 2;
                ldsm_x4(bh[np], addr);
                ldsm_x4(bl[np], addr + 9216);
            }
#pragma unroll
            for (int nt = 0; nt < 4; nt++) {
                const uint32_t* bhf = &bh[nt >> 1][(nt & 1) * 2];
                const uint32_t* blf = &bl[nt >> 1][(nt & 1) * 2];
                mma16816(acc[nt], qhf[ks], bhf);
                mma16816(acc[nt], qhf[ks], blf);
                mma16816(acc[nt], qlf[ks], bhf);
            }
        }

        int r0 = wm * 16 + (lane >> 2);
#pragma unroll
        for (int nt = 0; nt < 4; nt++) {
            int col = st * 64 + wn * 32 + nt * 8 + (lane & 3) * 2;
            float b0 = biasS[col], b1 = biasS[col + 1];
#pragma unroll
            for (int rr = 0; rr < 2; rr++) {
                int row = r0 + rr * 8;
                int tg = qt * 64 + row;
                float v0 = acc[nt][rr * 2 + 0] * scale + b0;
                float v1 = acc[nt][rr * 2 + 1] * scale + b1;
                if (causal) {
                    if (col > tg)     v0 = -1e30f;
                    if (col + 1 > tg) v1 = -1e30f;
                }
                float2 vv; vv.x = v0; vv.y = v1;
                *(float2*)(Sc + row * SC_PITCH + col) = vv;
            }
        }
    }
    __syncthreads();

    // ---- softmax (warp per 8 rows) + probs write ----
    {
        for (int r = 0; r < 8; r++) {
            int q = w * 8 + r;
            float* row = Sc + q * SC_PITCH;
            float mx = -3.0e38f;
            for (int c = lane; c < 512; c += 32) mx = fmaxf(mx, row[c]);
#pragma unroll
            for (int o = 16; o; o >>= 1) mx = fmaxf(mx, __shfl_xor_sync(0xffffffffu, mx, o));
            float sum = 0.f;
            for (int c = lane; c < 512; c += 32) {
                float e = __expf(row[c] - mx);
                row[c] = e;
                sum += e;
            }
#pragma unroll
            for (int o = 16; o; o >>= 1) sum += __shfl_xor_sync(0xffffffffu, sum, o);
            float inv = 1.f / sum;
            float* prow = probs + ((size_t)hb * SEQ + qt * 64 + q) * SEQ;
            for (int c = lane; c < 512; c += 32) {
                float p = row[c] * inv;
                row[c] = p;
                if (writeProbs) prow[c] = p;
            }
        }
    }

    // ---- P @ V phase ----
    load_kv(Vh, Vl, 0, 0); CP_COMMIT();
    float oacc[4][4];
#pragma unroll
    for (int i = 0; i < 4; i++)
#pragma unroll
        for (int j = 0; j < 4; j++) oacc[i][j] = 0.f;

    for (int st = 0; st < 8; st++) {
        __syncthreads();
        if (st < 7) { load_kv(Vh, Vl, st + 1, (st + 1) & 1); CP_COMMIT(); CP_WAIT1(); }
        else { CP_WAIT0(); }

        // convert P tile st -> bf16 hi/lo
        {
            int row = tid >> 2, cb = (tid & 3) * 16;
            const float* srow = Sc + row * SC_PITCH + st * 64 + cb;
            __nv_bfloat16* ph = (__nv_bfloat16*)(sm2 + PTH_OFF) + row * PT + cb;
            __nv_bfloat16* pl = (__nv_bfloat16*)(sm2 + PTL_OFF) + row * PT + cb;
#pragma unroll
            for (int j2 = 0; j2 < 16; j2 += 4) {
                float4 p4 = *(const float4*)(srow + j2);
                __nv_bfloat16 h0, l0, h1, l1, h2, l2, h3, l3;
                fsplit(p4.x, h0, l0); fsplit(p4.y, h1, l1);
                fsplit(p4.z, h2, l2); fsplit(p4.w, h3, l3);
                __nv_bfloat162 ha; ha.x = h0; ha.y = h1;
                __nv_bfloat162 hb2; hb2.x = h2; hb2.y = h3;
                __nv_bfloat162 la; la.x = l0; la.y = l1;
                __nv_bfloat162 lb; lb.x = l2; lb.y = l3;
                *(__nv_bfloat162*)(ph + j2)     = ha;
                *(__nv_bfloat162*)(ph + j2 + 2) = hb2;
                *(__nv_bfloat162*)(pl + j2)     = la;
                *(__nv_bfloat162*)(pl + j2 + 2) = lb;
            }
        }
        __syncthreads();

        uint32_t vb = sbase + KV_OFF + (st & 1) * KV_STAGE;
#pragma unroll
        for (int ks = 0; ks < 4; ks++) {
            uint32_t afh[4], afl[4], vbh[2][4], vbl[2][4];
            uint32_t aaddr = sbase + PTH_OFF +
                ((wm * 16 + (lane & 15)) * PT + ks * 16 + ((lane >> 4) << 3)) * 2;
            ldsm_x4(afh, aaddr);
            ldsm_x4(afl, aaddr + 9216);
#pragma unroll
            for (int np = 0; np < 2; np++) {
                uint32_t addr = vb + ((ks * 16 + (lane & 7) + ((lane & 8) ? 8 : 0)) * PT
                                      + wn * 32 + np * 16 + ((lane & 16) ? 8 : 0)) * 2;
                ldsm_x4_t(vbh[np], addr);
                ldsm_x4_t(vbl[np], addr + 9216);
            }
#pragma unroll
            for (int nt = 0; nt < 4; nt++) {
                const uint32_t* bhf = &vbh[nt >> 1][(nt & 1) * 2];
                const uint32_t* blf = &vbl[nt >> 1][(nt & 1) * 2];
                mma16816(oacc[nt], afh, bhf);
                mma16816(oacc[nt], afh, blf);
                mma16816(oacc[nt], afl, bhf);
            }
        }
    }

    // O epilogue -> bf16 hi/lo, layout [b*SEQ+t][h*64+e]
    int r0 = wm * 16 + (lane >> 2);
#pragma unroll
    for (int nt = 0; nt < 4; nt++) {
        int gc = h * DKV + wn * 32 + nt * 8 + (lane & 3) * 2;
#pragma unroll
        for (int rr = 0; rr < 2; rr++) {
            int row = b * SEQ + qt * 64 + r0 + rr * 8;
            float v0 = oacc[nt][rr * 2 + 0], v1 = oacc[nt][rr * 2 + 1];
            __nv_bfloat16 h0, l0, h1, l1;
            fsplit(v0, h0, l0); fsplit(v1, h1, l1);
            __nv_bfloat162 ph; ph.x = h0; ph.y = h1;
            __nv_bfloat162 pl; pl.x = l0; pl.y = l1;
            *(__nv_bfloat162*)(Ohi + (size_t)row * DMOD + gc) = ph;
            *(__nv_bfloat162*)(Olo + (size_t)row * DMOD + gc) = pl;
        }
    }
}

// ---------------- layernorm(y + res) -> fp32 out + bf16 hi/lo ----------------
__global__ __launch_bounds__(128) void ln_k(
    const float* __restrict__ y, const float* __restrict__ res,
    const float* __restrict__ g, const float* __restrict__ b,
    float* __restrict__ out,
    __nv_bfloat16* __restrict__ ohi, __nv_bfloat16* __restrict__ olo)
{
    __shared__ float red[8];
    int n = blockIdx.x, tid = threadIdx.x;
    int c = tid * 4;
    float4 yv = *(const float4*)(y   + (size_t)n * DMOD + c);
    float4 rv = *(const float4*)(res + (size_t)n * DMOD + c);
    float v0 = yv.x + rv.x, v1 = yv.y + rv.y, v2 = yv.z + rv.z, v3 = yv.w + rv.w;

    float s = v0 + v1 + v2 + v3;
    int lane = tid & 31, warp = tid >> 5;
#pragma unroll
    for (int o = 16; o; o >>= 1) s += __shfl_xor_sync(0xffffffffu, s, o);
    if (lane == 0) red[warp] = s;
    __syncthreads();
    float mu = (red[0] + red[1] + red[2] + red[3]) * (1.f / DMOD);

    float d0 = v0 - mu, d1 = v1 - mu, d2 = v2 - mu, d3 = v3 - mu;
    float ss = d0 * d0 + d1 * d1 + d2 * d2 + d3 * d3;
#pragma unroll
    for (int o = 16; o; o >>= 1) ss += __shfl_xor_sync(0xffffffffu, ss, o);
    if (lane == 0) red[4 + warp] = ss;
    __syncthreads();
    float var = (red[4] + red[5] + red[6] + red[7]) * (1.f / DMOD);
    float is = rsqrtf(var + 1e-5f);

    float4 gv = *(const float4*)(g + c);
    float4 bv = *(const float4*)(b + c);
    float4 ov;
    ov.x = d0 * is * gv.x + bv.x;
    ov.y = d1 * is * gv.y + bv.y;
    ov.z = d2 * is * gv.z + bv.z;
    ov.w = d3 * is * gv.w + bv.w;
    *(float4*)(out + (size_t)n * DMOD + c) = ov;

    __nv_bfloat16 h0, l0, h1, l1, h2, l2, h3, l3;
    fsplit(ov.x, h0, l0); fsplit(ov.y, h1, l1);
    fsplit(ov.z, h2, l2); fsplit(ov.w, h3, l3);
    __nv_bfloat162 ph0; ph0.x = h0; ph0.y = h1;
    __nv_bfloat162 ph1; ph1.x = h2; ph1.y = h3;
    __nv_bfloat162 pl0; pl0.x = l0; pl0.y = l1;
    __nv_bfloat162 pl1; pl1.x = l2; pl1.y = l3;
    *(__nv_bfloat162*)(ohi + (size_t)n * DMOD + c)     = ph0;
    *(__nv_bfloat162*)(ohi + (size_t)n * DMOD + c + 2) = ph1;
    *(__nv_bfloat162*)(olo + (size_t)n * DMOD + c)     = pl0;
    *(__nv_bfloat162*)(olo + (size_t)n * DMOD + c + 2) = pl1;
}

// ---------------- host ----------------
extern "C" void kernel_launch(void* const* d_in, const int* in_sizes, int n_in,
                              void* d_out, int out_size)
{
    const int*   tgt_seq = (const int*)d_in[0];
    const int*   tgt_pos = (const int*)d_in[1];
    const int*   src_seq = (const int*)d_in[2];
    const float* enc_out = (const float*)d_in[3];
    const float* tgt_emb = (const float*)d_in[4];
    const float* pos_emb = (const float*)d_in[5];
    const float* slf_wq  = (const float*)d_in[6];
    const float* slf_wk  = (const float*)d_in[7];
    const float* slf_wv  = (const float*)d_in[8];
    const float* slf_pw  = (const float*)d_in[9];
    const float* slf_pb  = (const float*)d_in[10];
    const float* slf_g   = (const float*)d_in[11];
    const float* slf_b   = (const float*)d_in[12];
    const float* enc_wq  = (const float*)d_in[13];
    const float* enc_wk  = (const float*)d_in[14];
    const float* enc_wv  = (const float*)d_in[15];
    const float* enc_pw  = (const float*)d_in[16];
    const float* enc_pb  = (const float*)d_in[17];
    const float* enc_g   = (const float*)d_in[18];
    const float* enc_b   = (const float*)d_in[19];
    const float* ffn_w1  = (const float*)d_in[20];
    const float* ffn_b1  = (const float*)d_in[21];
    const float* ffn_w2  = (const float*)d_in[22];
    const float* ffn_b2  = (const float*)d_in[23];
    const float* ffn_g   = (const float*)d_in[24];
    const float* ffn_b   = (const float*)d_in[25];

    float *xp, *yp;
    __nv_bfloat16 *qkvh, *qkvl, *xhi, *xlo, *ehi, *elo, *aohi, *aolo, *hhi, *hlo, *wbhi, *wblo;
    cudaGetSymbolAddress((void**)&xp,   g_x);
    cudaGetSymbolAddress((void**)&yp,   g_y);
    cudaGetSymbolAddress((void**)&qkvh, g_qkvh);
    cudaGetSymbolAddress((void**)&qkvl, g_qkvl);
    cudaGetSymbolAddress((void**)&xhi,  g_xhi);
    cudaGetSymbolAddress((void**)&xlo,  g_xlo);
    cudaGetSymbolAddress((void**)&ehi,  g_ehi);
    cudaGetSymbolAddress((void**)&elo,  g_elo);
    cudaGetSymbolAddress((void**)&aohi, g_aohi);
    cudaGetSymbolAddress((void**)&aolo, g_aolo);
    cudaGetSymbolAddress((void**)&hhi,  g_hhi);
    cudaGetSymbolAddress((void**)&hlo,  g_hlo);
    cudaGetSymbolAddress((void**)&wbhi, g_wbhi);
    cudaGetSymbolAddress((void**)&wblo, g_wblo);

    cudaFuncSetAttribute(attn_mma_k, cudaFuncAttributeMaxDynamicSharedMemorySize, ATTN2_SMEM);
    cudaFuncSetAttribute(gemm_mma_k, cudaFuncAttributeMaxDynamicSharedMemorySize, GM_SMEM);

    const int full = (out_size >= (int)FULL_OUT) ? 1 : 0;
    float* out_f = (float*)d_out;
    float* probs_slf = out_f + SLF_OFF;
    float* probs_enc = out_f + ENC_OFF;

    __nv_bfloat16* qh = qkvh;
    __nv_bfloat16* kh = qkvh + 2097152;
    __nv_bfloat16* vh = qkvh + 4194304;
    __nv_bfloat16* ql = qkvl;
    __nv_bfloat16* kl = qkvl + 2097152;
    __nv_bfloat16* vl = qkvl + 4194304;

    embed_k<<<NTOK, 128>>>(tgt_seq, tgt_pos, tgt_emb, pos_emb, xp, xhi, xlo);
    conv_split_k<<<(NTOK * DMOD) / 256, 256>>>(enc_out, ehi, elo, NTOK * DMOD);

    // ---- batched weight prep: 4 launches for all 60 repacks ----
    {
        P6 srcs;
        srcs.p[0] = slf_wq; srcs.p[1] = slf_wk; srcs.p[2] = slf_wv;
        srcs.p[3] = enc_wq; srcs.p[4] = enc_wk; srcs.p[5] = enc_wv;
        qkv_repack_all<<<dim3(64, 6, 6), 256>>>(srcs, wbhi, wblo);
        pw_repack_all<<<dim3(16, 16, 12), dim3(32, 8)>>>(slf_pw, enc_pw, wbhi, wblo);
        ffn_repack_all<<<dim3(64, 16, 6), dim3(32, 8)>>>(ffn_w1, wbhi, wblo, DMOD, DFF, WOFF_W1);
        ffn_repack_all<<<dim3(16, 64, 6), dim3(32, 8)>>>(ffn_w2, wbhi, wblo, DFF, DMOD, WOFF_W2);
    }

    dim3 gAttn(8, NHB);

    for (int l = 0; l < NL; l++) {
        size_t LB = (size_t)l * WL_SIZE;

        // ---- self attention: fused QKV (N=1536) ----
        gemm_mma_k<<<dim3(12, 32), 128, GM_SMEM>>>(xhi, xlo,
            wbhi + LB + WOFF_SQ, wblo + LB + WOFF_SQ,
            nullptr, nullptr, qkvh, qkvl, NTOK, 1536, DMOD, 3);
        attn_mma_k<<<gAttn, 256, ATTN2_SMEM>>>(qh, ql, kh, kl, vh, vl, tgt_seq,
            probs_slf + (size_t)l * ATT_PER_L, aohi, aolo, 1, full);
        gemm_mma_k<<<dim3(4, 32), 128, GM_SMEM>>>(aohi, aolo,
            wbhi + LB + WOFF_SPW, wblo + LB + WOFF_SPW,
            slf_pb + (size_t)l * DMOD, yp, nullptr, nullptr, NTOK, DMOD, DMOD, 1);
        ln_k<<<NTOK, 128>>>(yp, xp, slf_g + (size_t)l * DMOD, slf_b + (size_t)l * DMOD,
                            xp, xhi, xlo);

        // ---- cross attention: Q from x (N=512), fused KV from enc (N=1024) ----
        gemm_mma_k<<<dim3(4, 32), 128, GM_SMEM>>>(xhi, xlo,
            wbhi + LB + WOFF_EQ, wblo + LB + WOFF_EQ,
            nullptr, nullptr, qkvh, qkvl, NTOK, DMOD, DMOD, 3);
        gemm_mma_k<<<dim3(8, 32), 128, GM_SMEM>>>(ehi, elo,
            wbhi + LB + WOFF_EK, wblo + LB + WOFF_EK,
            nullptr, nullptr, qkvh + 2097152, qkvl + 2097152, NTOK, 1024, DMOD, 3);
        attn_mma_k<<<gAttn, 256, ATTN2_SMEM>>>(qh, ql, kh, kl, vh, vl, src_seq,
            probs_enc + (size_t)l * ATT_PER_L, aohi, aolo, 0, full);
        gemm_mma_k<<<dim3(4, 32), 128, GM_SMEM>>>(aohi, aolo,
            wbhi + LB + WOFF_EPW, wblo + LB + WOFF_EPW,
            enc_pb + (size_t)l * DMOD, yp, nullptr, nullptr, NTOK, DMOD, DMOD, 1);
        ln_k<<<NTOK, 128>>>(yp, xp, enc_g + (size_t)l * DMOD, enc_b + (size_t)l * DMOD,
                            xp, xhi, xlo);

        // ---- FFN ----
        gemm_mma_k<<<dim3(16, 32), 128, GM_SMEM>>>(xhi, xlo,
            wbhi + LB + WOFF_W1, wblo + LB + WOFF_W1,
            ffn_b1 + (size_t)l * DFF, nullptr, hhi, hlo, NTOK, DFF, DMOD, 2);
        gemm_mma_k<<<dim3(4, 32), 128, GM_SMEM>>>(hhi, hlo,
            wbhi + LB + WOFF_W2, wblo + LB + WOFF_W2,
            ffn_b2 + (size_t)l * DMOD, yp, nullptr, nullptr, NTOK, DMOD, DFF, 1);
        ln_k<<<NTOK, 128>>>(yp, xp, ffn_g + (size_t)l * DMOD, ffn_b + (size_t)l * DMOD,
                            xp, xhi, xlo);
    }

    size_t copy_elems = (size_t)out_size < (size_t)X_ELEMS ? (size_t)out_size : (size_t)X_ELEMS;
    cudaMemcpyAsync(d_out, xp, copy_elems * sizeof(float), cudaMemcpyDeviceToDevice);
}

// round 13
// speedup vs baseline: 1.5403x; 1.5403x over previous
#include <cuda_runtime.h>
#include <cuda_bf16.h>
#include <cstdint>

// Problem constants
#define NL   6
#define NH   8
#define DMOD 512
#define DKV  64
#define DFF  2048
#define NB   8
#define SEQ  512
#define NTOK 4096          // NB*SEQ
#define NHB  64            // NH*NB

#define X_ELEMS   (NTOK*DMOD)                 // 2,097,152
#define ATT_PER_L ((size_t)NHB*SEQ*SEQ)       // 16,777,216
#define SLF_OFF   ((size_t)X_ELEMS)
#define ENC_OFF   (SLF_OFF + (size_t)NL*ATT_PER_L)
#define FULL_OUT  (ENC_OFF + (size_t)NL*ATT_PER_L)   // 203,423,744

// per-layer bf16 weight bank layout (element offsets)
#define WOFF_SQ   0
#define WOFF_SK   262144
#define WOFF_SV   524288
#define WOFF_SPW  786432
#define WOFF_EQ   1048576
#define WOFF_EK   1310720
#define WOFF_EV   1572864
#define WOFF_EPW  1835008
#define WOFF_W1   2097152
#define WOFF_W2   3145728
#define WL_SIZE   4194304

// ---------------- scratch (no allocations allowed) ----------------
__device__ float g_x  [NTOK*DMOD];
__device__ float g_y  [NTOK*DMOD];
__device__ __nv_bfloat16 g_qkvh[3*NHB*SEQ*DKV];   // q|k|v hi, head-major [hb][t][e]
__device__ __nv_bfloat16 g_qkvl[3*NHB*SEQ*DKV];   // q|k|v lo
__device__ __nv_bfloat16 g_xhi [NTOK*DMOD];
__device__ __nv_bfloat16 g_xlo [NTOK*DMOD];
__device__ __nv_bfloat16 g_ehi [NTOK*DMOD];
__device__ __nv_bfloat16 g_elo [NTOK*DMOD];
__device__ __nv_bfloat16 g_aohi[NTOK*DMOD];
__device__ __nv_bfloat16 g_aolo[NTOK*DMOD];
__device__ __nv_bfloat16 g_hhi [NTOK*DFF];
__device__ __nv_bfloat16 g_hlo [NTOK*DFF];
__device__ __nv_bfloat16 g_wbhi[(size_t)NL*WL_SIZE];
__device__ __nv_bfloat16 g_wblo[(size_t)NL*WL_SIZE];

struct P6 { const float* p[6]; };

// ---------------- helpers (baseline PTX only: sm_80-class) ----------------
__device__ __forceinline__ uint32_t smem_u32(const void* p) {
    uint32_t a;
    asm("{ .reg .u64 t; cvta.to.shared.u64 t, %1; cvt.u32.u64 %0, t; }" : "=r"(a) : "l"(p));
    return a;
}
__device__ __forceinline__ void cp16(uint32_t saddr, const void* g) {
    asm volatile("cp.async.cg.shared.global [%0], [%1], 16;" :: "r"(saddr), "l"(g));
}
#define CP_COMMIT() asm volatile("cp.async.commit_group;" ::: "memory")
#define CP_WAIT1()  asm volatile("cp.async.wait_group 1;" ::: "memory")
#define CP_WAIT0()  asm volatile("cp.async.wait_group 0;" ::: "memory")

__device__ __forceinline__ void ldsm_x4(uint32_t* r, uint32_t addr) {
    asm volatile("ldmatrix.sync.aligned.m8n8.x4.shared.b16 {%0,%1,%2,%3}, [%4];"
                 : "=r"(r[0]), "=r"(r[1]), "=r"(r[2]), "=r"(r[3]) : "r"(addr));
}
__device__ __forceinline__ void ldsm_x4_t(uint32_t* r, uint32_t addr) {
    asm volatile("ldmatrix.sync.aligned.m8n8.x4.trans.shared.b16 {%0,%1,%2,%3}, [%4];"
                 : "=r"(r[0]), "=r"(r[1]), "=r"(r[2]), "=r"(r[3]) : "r"(addr));
}
__device__ __forceinline__ void mma16816(float* d, const uint32_t* a, const uint32_t* b) {
    asm volatile("mma.sync.aligned.m16n8k16.row.col.f32.bf16.bf16.f32 "
                 "{%0,%1,%2,%3}, {%4,%5,%6,%7}, {%8,%9}, {%0,%1,%2,%3};"
                 : "+f"(d[0]), "+f"(d[1]), "+f"(d[2]), "+f"(d[3])
                 : "r"(a[0]), "r"(a[1]), "r"(a[2]), "r"(a[3]), "r"(b[0]), "r"(b[1]));
}

__device__ __forceinline__ void fsplit(float v, __nv_bfloat16& h, __nv_bfloat16& l) {
    h = __float2bfloat16(v);
    l = __float2bfloat16(v - __bfloat162float(h));
}

// ---------------- embedding (fp32 x + bf16 hi/lo) ----------------
__global__ void embed_k(const int* __restrict__ seq, const int* __restrict__ pos,
                        const float* __restrict__ wemb, const float* __restrict__ pemb,
                        float* __restrict__ x,
                        __nv_bfloat16* __restrict__ xhi, __nv_bfloat16* __restrict__ xlo) {
    int n = blockIdx.x;
    int s = seq[n], p = pos[n];
    const float* we = wemb + (size_t)s * DMOD;
    const float* pe = pemb + (size_t)p * DMOD;
    for (int c = threadIdx.x; c < DMOD; c += blockDim.x) {
        float v = we[c] + pe[c];
        x[(size_t)n * DMOD + c] = v;
        __nv_bfloat16 h, l; fsplit(v, h, l);
        xhi[(size_t)n * DMOD + c] = h;
        xlo[(size_t)n * DMOD + c] = l;
    }
}

// ---------------- fp32 -> bf16 hi/lo split (for enc_output) ----------------
__global__ void conv_split_k(const float* __restrict__ src,
                             __nv_bfloat16* __restrict__ hi, __nv_bfloat16* __restrict__ lo,
                             int n) {
    int i = blockIdx.x * blockDim.x + threadIdx.x;
    if (i < n) {
        __nv_bfloat16 h, l; fsplit(src[i], h, l);
        hi[i] = h; lo[i] = l;
    }
}

// ---------------- batched qkv weight repack (all 6 tensors x 6 layers) ----------------
__global__ void qkv_repack_all(P6 srcs,
                               __nv_bfloat16* __restrict__ dhi_b,
                               __nv_bfloat16* __restrict__ dlo_b) {
    __shared__ float t[64][65];
    const int woff[6] = {WOFF_SQ, WOFF_SK, WOFF_SV, WOFF_EQ, WOFF_EK, WOFF_EV};
    int ti = blockIdx.y, l = blockIdx.z;
    const float* src = srcs.p[ti] + (size_t)l * (NH * DMOD * DKV);
    __nv_bfloat16* dhi = dhi_b + (size_t)l * WL_SIZE + woff[ti];
    __nv_bfloat16* dlo = dlo_b + (size_t)l * WL_SIZE + woff[ti];

    int h = blockIdx.x >> 3, dt = blockIdx.x & 7;
    int d0 = dt * 64;
    int tid = threadIdx.x;
    for (int i = tid; i < 4096; i += 256) {
        int d = i >> 6, e = i & 63;
        t[e][d] = src[h * (DMOD * DKV) + (d0 + d) * DKV + e];
    }
    __syncthreads();
    for (int i = tid; i < 4096; i += 256) {
        int e = i >> 6, d = i & 63;
        __nv_bfloat16 hh, ll; fsplit(t[e][d], hh, ll);
        size_t o = (size_t)(h * 64 + e) * DMOD + d0 + d;
        dhi[o] = hh; dlo[o] = ll;
    }
}

// ---------------- batched projection-weight transpose (slf_pw + enc_pw, all layers) ----------------
__global__ void pw_repack_all(const float* __restrict__ slf_pw, const float* __restrict__ enc_pw,
                              __nv_bfloat16* __restrict__ dhi_b, __nv_bfloat16* __restrict__ dlo_b) {
    __shared__ float t[32][33];
    int z = blockIdx.z, l = z >> 1, te = z & 1;
    const float* src = (te ? enc_pw : slf_pw) + (size_t)l * DMOD * DMOD;
    size_t doff = (size_t)l * WL_SIZE + (te ? WOFF_EPW : WOFF_SPW);
    __nv_bfloat16* dhi = dhi_b + doff;
    __nv_bfloat16* dlo = dlo_b + doff;

    int c0 = blockIdx.x * 32, r0 = blockIdx.y * 32;
    int x = threadIdx.x, y = threadIdx.y;        // 32 x 8
    for (int yy = y; yy < 32; yy += 8)
        t[yy][x] = src[(size_t)(r0 + yy) * DMOD + c0 + x];
    __syncthreads();
    for (int yy = y; yy < 32; yy += 8) {
        __nv_bfloat16 hh, ll; fsplit(t[x][yy], hh, ll);
        size_t o = (size_t)(c0 + yy) * DMOD + r0 + x;
        dhi[o] = hh; dlo[o] = ll;
    }
}

// ---------------- batched FFN weight transpose: [R,C] -> [C,R], all layers via z ----------------
__global__ void ffn_repack_all(const float* __restrict__ w,
                               __nv_bfloat16* __restrict__ dhi_b, __nv_bfloat16* __restrict__ dlo_b,
                               int R, int C, int woff) {
    __shared__ float t[32][33];
    int l = blockIdx.z;
    const float* src = w + (size_t)l * R * C;
    size_t doff = (size_t)l * WL_SIZE + woff;
    __nv_bfloat16* dhi = dhi_b + doff;
    __nv_bfloat16* dlo = dlo_b + doff;

    int c0 = blockIdx.x * 32, r0 = blockIdx.y * 32;
    int x = threadIdx.x, y = threadIdx.y;        // 32 x 8
    for (int yy = y; yy < 32; yy += 8)
        t[yy][x] = src[(size_t)(r0 + yy) * C + c0 + x];
    __syncthreads();
    for (int yy = y; yy < 32; yy += 8) {
        __nv_bfloat16 hh, ll; fsplit(t[x][yy], hh, ll);
        size_t o = (size_t)(c0 + yy) * R + r0 + x;
        dhi[o] = hh; dlo[o] = ll;
    }
}

// ---------------- mma.sync bf16-split GEMM: C[M,N] = A[M,K] @ B[N,K]^T ----------------
// 4 warps, 2x2 warp grid, warp tile 64x64; K-chunk 64 (pitch 72), 2-stage double buffer.
// 3 passes: Ahi*Bhi + Ahi*Blo + Alo*Bhi, fp32 register accumulators.
// mode 1: +bias -> fp32 Cf;  mode 2: +bias,relu -> bf16 Chi/Clo;
// mode 3: qkv scatter -> bf16 hi/lo Chi/Clo head-major.
#define GM_PITCH 72                  // bf16 elems per smem row (144B, conflict-free ldmatrix)
#define GM_TILEB (128*GM_PITCH*2)    // 18432 B per 128x64 tile
#define GM_STAGE (4*GM_TILEB)        // Ahi|Alo|Bhi|Blo = 73728 B
#define GM_SMEM  (2*GM_STAGE)        // 147456 B double buffered

__global__ __launch_bounds__(128, 1) void gemm_mma_k(
    const __nv_bfloat16* __restrict__ Ahi, const __nv_bfloat16* __restrict__ Alo,
    const __nv_bfloat16* __restrict__ Bhi, const __nv_bfloat16* __restrict__ Blo,
    const float* __restrict__ bias,
    float* __restrict__ Cf,
    __nv_bfloat16* __restrict__ Chi, __nv_bfloat16* __restrict__ Clo,
    int M, int N, int K, int mode)
{
    extern __shared__ __align__(16) char smem[];
    uint32_t sb = smem_u32(smem);
    const int tid = threadIdx.x, lane = tid & 31, w = tid >> 5;
    const int wm = w >> 1, wn = w & 1;          // warp grid 2 x 2 -> 64 x 64 tiles
    const int n0 = blockIdx.x * 128, m0 = blockIdx.y * 128;

    const __nv_bfloat16* srcs[4] = {
        Ahi + (size_t)m0 * K, Alo + (size_t)m0 * K,
        Bhi + (size_t)n0 * K, Blo + (size_t)n0 * K };

    // loader: 128 threads; per tensor 128 rows x 64 cols = 1024 16B segs -> 8/thread
    const int lrow = tid >> 3, lc8 = (tid & 7) * 8;

    auto load_chunk = [&](int kc, int st) {
        const int k0 = kc * 64;
        uint32_t stb = sb + st * GM_STAGE;
#pragma unroll
        for (int t = 0; t < 4; t++) {
            uint32_t tb = stb + t * GM_TILEB;
            const __nv_bfloat16* src = srcs[t] + k0 + lc8;
#pragma unroll
            for (int j = 0; j < 8; j++) {
                int r = lrow + j * 16;
                cp16(tb + (r * GM_PITCH + lc8) * 2, src + (size_t)r * K);
            }
        }
    };

    float acc[4][8][4];
#pragma unroll
    for (int a = 0; a < 4; a++)
#pragma unroll
        for (int b = 0; b < 8; b++)
#pragma unroll
            for (int c = 0; c < 4; c++) acc[a][b][c] = 0.f;

    const int nch = K >> 6;
    load_chunk(0, 0); CP_COMMIT();

    const uint32_t a_off = ((wm * 64 + (lane & 15)) * GM_PITCH + ((lane >> 4) << 3)) * 2;
    const int b_lrow = (lane & 7) + ((lane & 16) ? 8 : 0);
    const int b_lcol = ((lane & 8) ? 8 : 0);

    for (int kc = 0; kc < nch; kc++) {
        if (kc + 1 < nch) { load_chunk(kc + 1, (kc + 1) & 1); CP_COMMIT(); CP_WAIT1(); }
        else { CP_WAIT0(); }
        __syncthreads();

        uint32_t stb = sb + (kc & 1) * GM_STAGE;
#pragma unroll
        for (int ks = 0; ks < 4; ks++) {
            const uint32_t kso = ks * 32;   // 16 elems * 2B
            uint32_t ah[4][4], al[4][4];
#pragma unroll
            for (int mi = 0; mi < 4; mi++) {
                uint32_t off = a_off + mi * 16 * GM_PITCH * 2 + kso;
                ldsm_x4(ah[mi], stb + 0 * GM_TILEB + off);
                ldsm_x4(al[mi], stb + 1 * GM_TILEB + off);
            }
#pragma unroll
            for (int ng = 0; ng < 2; ng++) {
                uint32_t bh[2][4], bl[2][4];
#pragma unroll
                for (int np = 0; np < 2; np++) {
                    uint32_t off = ((wn * 64 + ng * 32 + np * 16 + b_lrow) * GM_PITCH
                                    + b_lcol) * 2 + kso;
                    ldsm_x4(bh[np], stb + 2 * GM_TILEB + off);
                    ldsm_x4(bl[np], stb + 3 * GM_TILEB + off);
                }
#pragma unroll
                for (int mi = 0; mi < 4; mi++)
#pragma unroll
                    for (int nt = 0; nt < 4; nt++) {
                        const uint32_t* bhf = &bh[nt >> 1][(nt & 1) * 2];
                        const uint32_t* blf = &bl[nt >> 1][(nt & 1) * 2];
                        float* ac = acc[mi][ng * 4 + nt];
                        mma16816(ac, ah[mi], bhf);
                        mma16816(ac, ah[mi], blf);
                        mma16816(ac, al[mi], bhf);
                    }
            }
        }
        __syncthreads();
    }

    // epilogue
#pragma unroll
    for (int mi = 0; mi < 4; mi++) {
        int r0 = m0 + wm * 64 + mi * 16 + (lane >> 2);
#pragma unroll
        for (int nj = 0; nj < 8; nj++) {
            int col = n0 + wn * 64 + nj * 8 + (lane & 3) * 2;
            float c0 = acc[mi][nj][0], c1 = acc[mi][nj][1];
            float c2 = acc[mi][nj][2], c3 = acc[mi][nj][3];
            if (mode == 3) {
                int m = col >> 9, hh_ = (col >> 6) & 7, e = col & 63;
#pragma unroll
                for (int rr = 0; rr < 2; rr++) {
                    int row = r0 + rr * 8;
                    int b_ = row >> 9, t = row & 511;
                    size_t off = (size_t)m * 2097152 +
                                 (((size_t)(hh_ * NB + b_) * SEQ + t) * DKV + e);
                    float v0 = rr ? c2 : c0, v1 = rr ? c3 : c1;
                    __nv_bfloat16 h0, l0, h1, l1;
                    fsplit(v0, h0, l0); fsplit(v1, h1, l1);
                    __nv_bfloat162 ph; ph.x = h0; ph.y = h1;
                    __nv_bfloat162 pl; pl.x = l0; pl.y = l1;
                    *(__nv_bfloat162*)(Chi + off) = ph;
                    *(__nv_bfloat162*)(Clo + off) = pl;
                }
            } else if (mode == 1) {
                float2 bv = *(const float2*)(bias + col);
                float2 v0; v0.x = c0 + bv.x; v0.y = c1 + bv.y;
                float2 v1; v1.x = c2 + bv.x; v1.y = c3 + bv.y;
                *(float2*)(Cf + (size_t)r0 * N + col)       = v0;
                *(float2*)(Cf + (size_t)(r0 + 8) * N + col) = v1;
            } else {
                float2 bv = *(const float2*)(bias + col);
                float p0 = fmaxf(c0 + bv.x, 0.f), p1 = fmaxf(c1 + bv.y, 0.f);
                float p2 = fmaxf(c2 + bv.x, 0.f), p3 = fmaxf(c3 + bv.y, 0.f);
                __nv_bfloat16 h0, l0, h1, l1, h2, l2, h3, l3;
                fsplit(p0, h0, l0); fsplit(p1, h1, l1);
                fsplit(p2, h2, l2); fsplit(p3, h3, l3);
                __nv_bfloat162 ph0; ph0.x = h0; ph0.y = h1;
                __nv_bfloat162 ph1; ph1.x = h2; ph1.y = h3;
                __nv_bfloat162 pl0; pl0.x = l0; pl0.y = l1;
                __nv_bfloat162 pl1; pl1.x = l2; pl1.y = l3;
                *(__nv_bfloat162*)(Chi + (size_t)r0 * N + col)       = ph0;
                *(__nv_bfloat162*)(Chi + (size_t)(r0 + 8) * N + col) = ph1;
                *(__nv_bfloat162*)(Clo + (size_t)r0 * N + col)       = pl0;
                *(__nv_bfloat162*)(Clo + (size_t)(r0 + 8) * N + col) = pl1;
            }
        }
    }
}

// ---------------- MMA attention ----------------
// Block = (qt, hb): 64 queries x 512 keys. 8 warps: wm = w&3 (16 rows), wn = w>>2 (half).
#define PT 72                      // bf16 pitch (144 B, 16B-phase conflict-free)
#define SC_PITCH 520
#define SC_OFF   0                 // fp32 [64][520] = 133120 B
#define QH_OFF   133120            // bf16 [64][72] = 9216 B
#define QL_OFF   (QH_OFF + 9216)
#define KV_OFF   (QL_OFF + 9216)   // 2 stages x (hi 9216 + lo 9216)
#define KV_STAGE 18432
#define PTH_OFF  (KV_OFF + 2*KV_STAGE)
#define PTL_OFF  (PTH_OFF + 9216)
#define BIAS_OFF (PTL_OFF + 9216)  // fp32 [512]
#define ATTN2_SMEM (BIAS_OFF + 2048)   // 208896 B

__global__ __launch_bounds__(256, 1) void attn_mma_k(
    const __nv_bfloat16* __restrict__ Qh, const __nv_bfloat16* __restrict__ Ql,
    const __nv_bfloat16* __restrict__ Kh, const __nv_bfloat16* __restrict__ Kl,
    const __nv_bfloat16* __restrict__ Vh, const __nv_bfloat16* __restrict__ Vl,
    const int* __restrict__ seq, float* __restrict__ probs,
    __nv_bfloat16* __restrict__ Ohi, __nv_bfloat16* __restrict__ Olo,
    int causal, int writeProbs)
{
    extern __shared__ __align__(16) char sm2[];
    uint32_t sbase = smem_u32(sm2);
    float* Sc = (float*)(sm2 + SC_OFF);
    float* biasS = (float*)(sm2 + BIAS_OFF);
    const int hb = blockIdx.y, qt = blockIdx.x;
    const int h = hb >> 3, b = hb & 7;
    const int tid = threadIdx.x, lane = tid & 31, w = tid >> 5;
    const int wm = w & 3, wn = w >> 2;
    const float scale = 0.044194173824159216f;   // 1/sqrt(512)

    for (int i = tid; i < 512; i += 256)
        biasS[i] = (seq[b * SEQ + i] == 0) ? -1e30f : 0.f;

    // Q tile -> smem (hi/lo)
    {
        int row = tid >> 2, s0 = (tid & 3) * 16;
        size_t gq = ((size_t)hb * SEQ + qt * 64 + row) * DKV + s0;
        *(uint4*)(sm2 + QH_OFF + (row * PT + s0) * 2)     = *(const uint4*)(Qh + gq);
        *(uint4*)(sm2 + QH_OFF + (row * PT + s0 + 8) * 2) = *(const uint4*)(Qh + gq + 8);
        *(uint4*)(sm2 + QL_OFF + (row * PT + s0) * 2)     = *(const uint4*)(Ql + gq);
        *(uint4*)(sm2 + QL_OFF + (row * PT + s0 + 8) * 2) = *(const uint4*)(Ql + gq + 8);
    }

    auto load_kv = [&](const __nv_bfloat16* Hs, const __nv_bfloat16* Ls, int st, int stage) {
        uint32_t sbst = sbase + KV_OFF + stage * KV_STAGE;
        size_t gbase = ((size_t)hb * SEQ + st * 64) * DKV;
#pragma unroll
        for (int j = 0; j < 2; j++) {
            int seg = tid + j * 256;
            int row = seg >> 3, c = (seg & 7) * 8;
            uint32_t so = sbst + (row * PT + c) * 2;
            cp16(so,        Hs + gbase + row * DKV + c);
            cp16(so + 9216, Ls + gbase + row * DKV + c);
        }
    };

    load_kv(Kh, Kl, 0, 0); CP_COMMIT();
    __syncthreads();

    // resident Q fragments
    uint32_t qhf[4][4], qlf[4][4];
#pragma unroll
    for (int ks = 0; ks < 4; ks++) {
        uint32_t addr = sbase + QH_OFF +
            ((wm * 16 + (lane & 15)) * PT + ks * 16 + ((lane >> 4) << 3)) * 2;
        ldsm_x4(qhf[ks], addr);
        ldsm_x4(qlf[ks], addr + 9216);
    }

    // ---- score phase ----
    for (int st = 0; st < 8; st++) {
        __syncthreads();
        if (st < 7) { load_kv(Kh, Kl, st + 1, (st + 1) & 1); CP_COMMIT(); CP_WAIT1(); }
        else { CP_WAIT0(); }
        __syncthreads();

        uint32_t kb = sbase + KV_OFF + (st & 1) * KV_STAGE;
        float acc[4][4];
#pragma unroll
        for (int i = 0; i < 4; i++)
#pragma unroll
            for (int j = 0; j < 4; j++) acc[i][j] = 0.f;

#pragma unroll
        for (int ks = 0; ks < 4; ks++) {
            uint32_t bh[2][4], bl[2][4];
#pragma unroll
            for (int np = 0; np < 2; np++) {
                uint32_t addr = kb + ((wn * 32 + np * 16 + (lane & 7) + ((lane & 16) ? 8 : 0)) * PT
                                      + ks * 16 + ((lane & 8) ? 8 : 0)) * 2;
                ldsm_x4(bh[np], addr);
                ldsm_x4(bl[np], addr + 9216);
            }
#pragma unroll
            for (int nt = 0; nt < 4; nt++) {
                const uint32_t* bhf = &bh[nt >> 1][(nt & 1) * 2];
                const uint32_t* blf = &bl[nt >> 1][(nt & 1) * 2];
                mma16816(acc[nt], qhf[ks], bhf);
                mma16816(acc[nt], qhf[ks], blf);
                mma16816(acc[nt], qlf[ks], bhf);
            }
        }

        int r0 = wm * 16 + (lane >> 2);
#pragma unroll
        for (int nt = 0; nt < 4; nt++) {
            int col = st * 64 + wn * 32 + nt * 8 + (lane & 3) * 2;
            float b0 = biasS[col], b1 = biasS[col + 1];
#pragma unroll
            for (int rr = 0; rr < 2; rr++) {
                int row = r0 + rr * 8;
                int tg = qt * 64 + row;
                float v0 = acc[nt][rr * 2 + 0] * scale + b0;
                float v1 = acc[nt][rr * 2 + 1] * scale + b1;
                if (causal) {
                    if (col > tg)     v0 = -1e30f;
                    if (col + 1 > tg) v1 = -1e30f;
                }
                float2 vv; vv.x = v0; vv.y = v1;
                *(float2*)(Sc + row * SC_PITCH + col) = vv;
            }
        }
    }
    __syncthreads();

    // ---- softmax (warp per 8 rows) + probs write ----
    {
        for (int r = 0; r < 8; r++) {
            int q = w * 8 + r;
            float* row = Sc + q * SC_PITCH;
            float mx = -3.0e38f;
            for (int c = lane; c < 512; c += 32) mx = fmaxf(mx, row[c]);
#pragma unroll
            for (int o = 16; o; o >>= 1) mx = fmaxf(mx, __shfl_xor_sync(0xffffffffu, mx, o));
            float sum = 0.f;
            for (int c = lane; c < 512; c += 32) {
                float e = __expf(row[c] - mx);
                row[c] = e;
                sum += e;
            }
#pragma unroll
            for (int o = 16; o; o >>= 1) sum += __shfl_xor_sync(0xffffffffu, sum, o);
            float inv = 1.f / sum;
            float* prow = probs + ((size_t)hb * SEQ + qt * 64 + q) * SEQ;
            for (int c = lane; c < 512; c += 32) {
                float p = row[c] * inv;
                row[c] = p;
                if (writeProbs) prow[c] = p;
            }
        }
    }

    // ---- P @ V phase ----
    load_kv(Vh, Vl, 0, 0); CP_COMMIT();
    float oacc[4][4];
#pragma unroll
    for (int i = 0; i < 4; i++)
#pragma unroll
        for (int j = 0; j < 4; j++) oacc[i][j] = 0.f;

    for (int st = 0; st < 8; st++) {
        __syncthreads();
        if (st < 7) { load_kv(Vh, Vl, st + 1, (st + 1) & 1); CP_COMMIT(); CP_WAIT1(); }
        else { CP_WAIT0(); }

        // convert P tile st -> bf16 hi/lo
        {
            int row = tid >> 2, cb = (tid & 3) * 16;
            const float* srow = Sc + row * SC_PITCH + st * 64 + cb;
            __nv_bfloat16* ph = (__nv_bfloat16*)(sm2 + PTH_OFF) + row * PT + cb;
            __nv_bfloat16* pl = (__nv_bfloat16*)(sm2 + PTL_OFF) + row * PT + cb;
#pragma unroll
            for (int j2 = 0; j2 < 16; j2 += 4) {
                float4 p4 = *(const float4*)(srow + j2);
                __nv_bfloat16 h0, l0, h1, l1, h2, l2, h3, l3;
                fsplit(p4.x, h0, l0); fsplit(p4.y, h1, l1);
                fsplit(p4.z, h2, l2); fsplit(p4.w, h3, l3);
                __nv_bfloat162 ha; ha.x = h0; ha.y = h1;
                __nv_bfloat162 hb2; hb2.x = h2; hb2.y = h3;
                __nv_bfloat162 la; la.x = l0; la.y = l1;
                __nv_bfloat162 lb; lb.x = l2; lb.y = l3;
                *(__nv_bfloat162*)(ph + j2)     = ha;
                *(__nv_bfloat162*)(ph + j2 + 2) = hb2;
                *(__nv_bfloat162*)(pl + j2)     = la;
                *(__nv_bfloat162*)(pl + j2 + 2) = lb;
            }
        }
        __syncthreads();

        uint32_t vb = sbase + KV_OFF + (st & 1) * KV_STAGE;
#pragma unroll
        for (int ks = 0; ks < 4; ks++) {
            uint32_t afh[4], afl[4], vbh[2][4], vbl[2][4];
            uint32_t aaddr = sbase + PTH_OFF +
                ((wm * 16 + (lane & 15)) * PT + ks * 16 + ((lane >> 4) << 3)) * 2;
            ldsm_x4(afh, aaddr);
            ldsm_x4(afl, aaddr + 9216);
#pragma unroll
            for (int np = 0; np < 2; np++) {
                uint32_t addr = vb + ((ks * 16 + (lane & 7) + ((lane & 8) ? 8 : 0)) * PT
                                      + wn * 32 + np * 16 + ((lane & 16) ? 8 : 0)) * 2;
                ldsm_x4_t(vbh[np], addr);
                ldsm_x4_t(vbl[np], addr + 9216);
            }
#pragma unroll
            for (int nt = 0; nt < 4; nt++) {
                const uint32_t* bhf = &vbh[nt >> 1][(nt & 1) * 2];
                const uint32_t* blf = &vbl[nt >> 1][(nt & 1) * 2];
                mma16816(oacc[nt], afh, bhf);
                mma16816(oacc[nt], afh, blf);
                mma16816(oacc[nt], afl, bhf);
            }
        }
    }

    // O epilogue -> bf16 hi/lo, layout [b*SEQ+t][h*64+e]
    int r0 = wm * 16 + (lane >> 2);
#pragma unroll
    for (int nt = 0; nt < 4; nt++) {
        int gc = h * DKV + wn * 32 + nt * 8 + (lane & 3) * 2;
#pragma unroll
        for (int rr = 0; rr < 2; rr++) {
            int row = b * SEQ + qt * 64 + r0 + rr * 8;
            float v0 = oacc[nt][rr * 2 + 0], v1 = oacc[nt][rr * 2 + 1];
            __nv_bfloat16 h0, l0, h1, l1;
            fsplit(v0, h0, l0); fsplit(v1, h1, l1);
            __nv_bfloat162 ph; ph.x = h0; ph.y = h1;
            __nv_bfloat162 pl; pl.x = l0; pl.y = l1;
            *(__nv_bfloat162*)(Ohi + (size_t)row * DMOD + gc) = ph;
            *(__nv_bfloat162*)(Olo + (size_t)row * DMOD + gc) = pl;
        }
    }
}

// ---------------- layernorm(y + res) -> fp32 out + bf16 hi/lo ----------------
__global__ __launch_bounds__(128) void ln_k(
    const float* __restrict__ y, const float* __restrict__ res,
    const float* __restrict__ g, const float* __restrict__ b,
    float* __restrict__ out,
    __nv_bfloat16* __restrict__ ohi, __nv_bfloat16* __restrict__ olo)
{
    __shared__ float red[8];
    int n = blockIdx.x, tid = threadIdx.x;
    int c = tid * 4;
    float4 yv = *(const float4*)(y   + (size_t)n * DMOD + c);
    float4 rv = *(const float4*)(res + (size_t)n * DMOD + c);
    float v0 = yv.x + rv.x, v1 = yv.y + rv.y, v2 = yv.z + rv.z, v3 = yv.w + rv.w;

    float s = v0 + v1 + v2 + v3;
    int lane = tid & 31, warp = tid >> 5;
#pragma unroll
    for (int o = 16; o; o >>= 1) s += __shfl_xor_sync(0xffffffffu, s, o);
    if (lane == 0) red[warp] = s;
    __syncthreads();
    float mu = (red[0] + red[1] + red[2] + red[3]) * (1.f / DMOD);

    float d0 = v0 - mu, d1 = v1 - mu, d2 = v2 - mu, d3 = v3 - mu;
    float ss = d0 * d0 + d1 * d1 + d2 * d2 + d3 * d3;
#pragma unroll
    for (int o = 16; o; o >>= 1) ss += __shfl_xor_sync(0xffffffffu, ss, o);
    if (lane == 0) red[4 + warp] = ss;
    __syncthreads();
    float var = (red[4] + red[5] + red[6] + red[7]) * (1.f / DMOD);
    float is = rsqrtf(var + 1e-5f);

    float4 gv = *(const float4*)(g + c);
    float4 bv = *(const float4*)(b + c);
    float4 ov;
    ov.x = d0 * is * gv.x + bv.x;
    ov.y = d1 * is * gv.y + bv.y;
    ov.z = d2 * is * gv.z + bv.z;
    ov.w = d3 * is * gv.w + bv.w;
    *(float4*)(out + (size_t)n * DMOD + c) = ov;

    __nv_bfloat16 h0, l0, h1, l1, h2, l2, h3, l3;
    fsplit(ov.x, h0, l0); fsplit(ov.y, h1, l1);
    fsplit(ov.z, h2, l2); fsplit(ov.w, h3, l3);
    __nv_bfloat162 ph0; ph0.x = h0; ph0.y = h1;
    __nv_bfloat162 ph1; ph1.x = h2; ph1.y = h3;
    __nv_bfloat162 pl0; pl0.x = l0; pl0.y = l1;
    __nv_bfloat162 pl1; pl1.x = l2; pl1.y = l3;
    *(__nv_bfloat162*)(ohi + (size_t)n * DMOD + c)     = ph0;
    *(__nv_bfloat162*)(ohi + (size_t)n * DMOD + c + 2) = ph1;
    *(__nv_bfloat162*)(olo + (size_t)n * DMOD + c)     = pl0;
    *(__nv_bfloat162*)(olo + (size_t)n * DMOD + c + 2) = pl1;
}

// ---------------- host ----------------
extern "C" void kernel_launch(void* const* d_in, const int* in_sizes, int n_in,
                              void* d_out, int out_size)
{
    const int*   tgt_seq = (const int*)d_in[0];
    const int*   tgt_pos = (const int*)d_in[1];
    const int*   src_seq = (const int*)d_in[2];
    const float* enc_out = (const float*)d_in[3];
    const float* tgt_emb = (const float*)d_in[4];
    const float* pos_emb = (const float*)d_in[5];
    const float* slf_wq  = (const float*)d_in[6];
    const float* slf_wk  = (const float*)d_in[7];
    const float* slf_wv  = (const float*)d_in[8];
    const float* slf_pw  = (const float*)d_in[9];
    const float* slf_pb  = (const float*)d_in[10];
    const float* slf_g   = (const float*)d_in[11];
    const float* slf_b   = (const float*)d_in[12];
    const float* enc_wq  = (const float*)d_in[13];
    const float* enc_wk  = (const float*)d_in[14];
    const float* enc_wv  = (const float*)d_in[15];
    const float* enc_pw  = (const float*)d_in[16];
    const float* enc_pb  = (const float*)d_in[17];
    const float* enc_g   = (const float*)d_in[18];
    const float* enc_b   = (const float*)d_in[19];
    const float* ffn_w1  = (const float*)d_in[20];
    const float* ffn_b1  = (const float*)d_in[21];
    const float* ffn_w2  = (const float*)d_in[22];
    const float* ffn_b2  = (const float*)d_in[23];
    const float* ffn_g   = (const float*)d_in[24];
    const float* ffn_b   = (const float*)d_in[25];

    float *xp, *yp;
    __nv_bfloat16 *qkvh, *qkvl, *xhi, *xlo, *ehi, *elo, *aohi, *aolo, *hhi, *hlo, *wbhi, *wblo;
    cudaGetSymbolAddress((void**)&xp,   g_x);
    cudaGetSymbolAddress((void**)&yp,   g_y);
    cudaGetSymbolAddress((void**)&qkvh, g_qkvh);
    cudaGetSymbolAddress((void**)&qkvl, g_qkvl);
    cudaGetSymbolAddress((void**)&xhi,  g_xhi);
    cudaGetSymbolAddress((void**)&xlo,  g_xlo);
    cudaGetSymbolAddress((void**)&ehi,  g_ehi);
    cudaGetSymbolAddress((void**)&elo,  g_elo);
    cudaGetSymbolAddress((void**)&aohi, g_aohi);
    cudaGetSymbolAddress((void**)&aolo, g_aolo);
    cudaGetSymbolAddress((void**)&hhi,  g_hhi);
    cudaGetSymbolAddress((void**)&hlo,  g_hlo);
    cudaGetSymbolAddress((void**)&wbhi, g_wbhi);
    cudaGetSymbolAddress((void**)&wblo, g_wblo);

    cudaFuncSetAttribute(attn_mma_k, cudaFuncAttributeMaxDynamicSharedMemorySize, ATTN2_SMEM);
    cudaFuncSetAttribute(gemm_mma_k, cudaFuncAttributeMaxDynamicSharedMemorySize, GM_SMEM);

    const int full = (out_size >= (int)FULL_OUT) ? 1 : 0;
    float* out_f = (float*)d_out;
    float* probs_slf = out_f + SLF_OFF;
    float* probs_enc = out_f + ENC_OFF;

    __nv_bfloat16* qh = qkvh;
    __nv_bfloat16* kh = qkvh + 2097152;
    __nv_bfloat16* vh = qkvh + 4194304;
    __nv_bfloat16* ql = qkvl;
    __nv_bfloat16* kl = qkvl + 2097152;
    __nv_bfloat16* vl = qkvl + 4194304;

    embed_k<<<NTOK, 128>>>(tgt_seq, tgt_pos, tgt_emb, pos_emb, xp, xhi, xlo);
    conv_split_k<<<(NTOK * DMOD) / 256, 256>>>(enc_out, ehi, elo, NTOK * DMOD);

    // ---- batched weight prep: 4 launches for all 60 repacks ----
    {
        P6 srcs;
        srcs.p[0] = slf_wq; srcs.p[1] = slf_wk; srcs.p[2] = slf_wv;
        srcs.p[3] = enc_wq; srcs.p[4] = enc_wk; srcs.p[5] = enc_wv;
        qkv_repack_all<<<dim3(64, 6, 6), 256>>>(srcs, wbhi, wblo);
        pw_repack_all<<<dim3(16, 16, 12), dim3(32, 8)>>>(slf_pw, enc_pw, wbhi, wblo);
        ffn_repack_all<<<dim3(64, 16, 6), dim3(32, 8)>>>(ffn_w1, wbhi, wblo, DMOD, DFF, WOFF_W1);
        ffn_repack_all<<<dim3(16, 64, 6), dim3(32, 8)>>>(ffn_w2, wbhi, wblo, DFF, DMOD, WOFF_W2);
    }

    dim3 gAttn(8, NHB);

    for (int l = 0; l < NL; l++) {
        size_t LB = (size_t)l * WL_SIZE;

        // ---- self attention: fused QKV (N=1536) ----
        gemm_mma_k<<<dim3(12, 32), 128, GM_SMEM>>>(xhi, xlo,
            wbhi + LB + WOFF_SQ, wblo + LB + WOFF_SQ,
            nullptr, nullptr, qkvh, qkvl, NTOK, 1536, DMOD, 3);
        attn_mma_k<<<gAttn, 256, ATTN2_SMEM>>>(qh, ql, kh, kl, vh, vl, tgt_seq,
            probs_slf + (size_t)l * ATT_PER_L, aohi, aolo, 1, full);
        gemm_mma_k<<<dim3(4, 32), 128, GM_SMEM>>>(aohi, aolo,
            wbhi + LB + WOFF_SPW, wblo + LB + WOFF_SPW,
            slf_pb + (size_t)l * DMOD, yp, nullptr, nullptr, NTOK, DMOD, DMOD, 1);
        ln_k<<<NTOK, 128>>>(yp, xp, slf_g + (size_t)l * DMOD, slf_b + (size_t)l * DMOD,
                            xp, xhi, xlo);

        // ---- cross attention: Q from x (N=512), fused KV from enc (N=1024) ----
        gemm_mma_k<<<dim3(4, 32), 128, GM_SMEM>>>(xhi, xlo,
            wbhi + LB + WOFF_EQ, wblo + LB + WOFF_EQ,
            nullptr, nullptr, qkvh, qkvl, NTOK, DMOD, DMOD, 3);
        gemm_mma_k<<<dim3(8, 32), 128, GM_SMEM>>>(ehi, elo,
            wbhi + LB + WOFF_EK, wblo + LB + WOFF_EK,
            nullptr, nullptr, qkvh + 2097152, qkvl + 2097152, NTOK, 1024, DMOD, 3);
        attn_mma_k<<<gAttn, 256, ATTN2_SMEM>>>(qh, ql, kh, kl, vh, vl, src_seq,
            probs_enc + (size_t)l * ATT_PER_L, aohi, aolo, 0, full);
        gemm_mma_k<<<dim3(4, 32), 128, GM_SMEM>>>(aohi, aolo,
            wbhi + LB + WOFF_EPW, wblo + LB + WOFF_EPW,
            enc_pb + (size_t)l * DMOD, yp, nullptr, nullptr, NTOK, DMOD, DMOD, 1);
        ln_k<<<NTOK, 128>>>(yp, xp, enc_g + (size_t)l * DMOD, enc_b + (size_t)l * DMOD,
                            xp, xhi, xlo);

        // ---- FFN ----
        gemm_mma_k<<<dim3(16, 32), 128, GM_SMEM>>>(xhi, xlo,
            wbhi + LB + WOFF_W1, wblo + LB + WOFF_W1,
            ffn_b1 + (size_t)l * DFF, nullptr, hhi, hlo, NTOK, DFF, DMOD, 2);
        gemm_mma_k<<<dim3(4, 32), 128, GM_SMEM>>>(hhi, hlo,
            wbhi + LB + WOFF_W2, wblo + LB + WOFF_W2,
            ffn_b2 + (size_t)l * DMOD, yp, nullptr, nullptr, NTOK, DMOD, DFF, 1);
        ln_k<<<NTOK, 128>>>(yp, xp, ffn_g + (size_t)l * DMOD, ffn_b + (size_t)l * DMOD,
                            xp, xhi, xlo);
    }

    size_t copy_elems = (size_t)out_size < (size_t)X_ELEMS ? (size_t)out_size : (size_t)X_ELEMS;
    cudaMemcpyAsync(d_out, xp, copy_elems * sizeof(float), cudaMemcpyDeviceToDevice);
}

// round 14
// speedup vs baseline: 2.2870x; 1.4848x over previous
#include <cuda_runtime.h>
#include <cuda_fp16.h>
#include <cstdint>

// Problem constants
#define NL   6
#define NH   8
#define DMOD 512
#define DKV  64
#define DFF  2048
#define NB   8
#define SEQ  512
#define NTOK 4096          // NB*SEQ
#define NHB  64            // NH*NB

#define X_ELEMS   (NTOK*DMOD)                 // 2,097,152
#define ATT_PER_L ((size_t)NHB*SEQ*SEQ)       // 16,777,216
#define SLF_OFF   ((size_t)X_ELEMS)
#define ENC_OFF   (SLF_OFF + (size_t)NL*ATT_PER_L)
#define FULL_OUT  (ENC_OFF + (size_t)NL*ATT_PER_L)   // 203,423,744

// per-layer fp16 weight bank layout (element offsets)
#define WOFF_SQ   0
#define WOFF_SK   262144
#define WOFF_SV   524288
#define WOFF_SPW  786432
#define WOFF_EQ   1048576
#define WOFF_EK   1310720
#define WOFF_EV   1572864
#define WOFF_EPW  1835008
#define WOFF_W1   2097152
#define WOFF_W2   3145728
#define WL_SIZE   4194304

// ---------------- scratch (no allocations allowed) ----------------
__device__ float g_x  [NTOK*DMOD];
__device__ float g_y  [NTOK*DMOD];
__device__ __half g_qkvh[3*NHB*SEQ*DKV];   // q|k|v fp16, head-major [hb][t][e]
__device__ __half g_xh [NTOK*DMOD];
__device__ __half g_eh [NTOK*DMOD];
__device__ __half g_aoh[NTOK*DMOD];
__device__ __half g_hh [NTOK*DFF];
__device__ __half g_wbhi[(size_t)NL*WL_SIZE];
__device__ __half g_wblo[(size_t)NL*WL_SIZE];

struct P6 { const float* p[6]; };

// ---------------- helpers (baseline PTX only: sm_80-class) ----------------
__device__ __forceinline__ uint32_t smem_u32(const void* p) {
    uint32_t a;
    asm("{ .reg .u64 t; cvta.to.shared.u64 t, %1; cvt.u32.u64 %0, t; }" : "=r"(a) : "l"(p));
    return a;
}
__device__ __forceinline__ void cp16(uint32_t saddr, const void* g) {
    asm volatile("cp.async.cg.shared.global [%0], [%1], 16;" :: "r"(saddr), "l"(g));
}
#define CP_COMMIT() asm volatile("cp.async.commit_group;" ::: "memory")
#define CP_WAIT1()  asm volatile("cp.async.wait_group 1;" ::: "memory")
#define CP_WAIT0()  asm volatile("cp.async.wait_group 0;" ::: "memory")

__device__ __forceinline__ void ldsm_x4(uint32_t* r, uint32_t addr) {
    asm volatile("ldmatrix.sync.aligned.m8n8.x4.shared.b16 {%0,%1,%2,%3}, [%4];"
                 : "=r"(r[0]), "=r"(r[1]), "=r"(r[2]), "=r"(r[3]) : "r"(addr));
}
__device__ __forceinline__ void ldsm_x4_t(uint32_t* r, uint32_t addr) {
    asm volatile("ldmatrix.sync.aligned.m8n8.x4.trans.shared.b16 {%0,%1,%2,%3}, [%4];"
                 : "=r"(r[0]), "=r"(r[1]), "=r"(r[2]), "=r"(r[3]) : "r"(addr));
}
__device__ __forceinline__ void mma16816(float* d, const uint32_t* a, const uint32_t* b) {
    asm volatile("mma.sync.aligned.m16n8k16.row.col.f32.f16.f16.f32 "
                 "{%0,%1,%2,%3}, {%4,%5,%6,%7}, {%8,%9}, {%0,%1,%2,%3};"
                 : "+f"(d[0]), "+f"(d[1]), "+f"(d[2]), "+f"(d[3])
                 : "r"(a[0]), "r"(a[1]), "r"(a[2]), "r"(a[3]), "r"(b[0]), "r"(b[1]));
}

__device__ __forceinline__ void hsplit(float v, __half& h, __half& l) {
    h = __float2half(v);
    l = __float2half(v - __half2float(h));
}
__device__ __forceinline__ __half2 pack2(float a, float b) {
    return __floats2half2_rn(a, b);
}

// ---------------- embedding (fp32 x + fp16) ----------------
__global__ void embed_k(const int* __restrict__ seq, const int* __restrict__ pos,
                        const float* __restrict__ wemb, const float* __restrict__ pemb,
                        float* __restrict__ x, __half* __restrict__ xh) {
    int n = blockIdx.x;
    int s = seq[n], p = pos[n];
    const float* we = wemb + (size_t)s * DMOD;
    const float* pe = pemb + (size_t)p * DMOD;
    for (int c = threadIdx.x; c < DMOD; c += blockDim.x) {
        float v = we[c] + pe[c];
        x[(size_t)n * DMOD + c] = v;
        xh[(size_t)n * DMOD + c] = __float2half(v);
    }
}

// ---------------- fp32 -> fp16 (enc_output) ----------------
__global__ void conv_h_k(const float* __restrict__ src, __half* __restrict__ dst, int n) {
    int i = blockIdx.x * blockDim.x + threadIdx.x;
    if (i < n) dst[i] = __float2half(src[i]);
}

// ---------------- batched qkv weight repack (all 6 tensors x 6 layers) ----------------
__global__ void qkv_repack_all(P6 srcs,
                               __half* __restrict__ dhi_b, __half* __restrict__ dlo_b) {
    __shared__ float t[64][65];
    const int woff[6] = {WOFF_SQ, WOFF_SK, WOFF_SV, WOFF_EQ, WOFF_EK, WOFF_EV};
    int ti = blockIdx.y, l = blockIdx.z;
    const float* src = srcs.p[ti] + (size_t)l * (NH * DMOD * DKV);
    __half* dhi = dhi_b + (size_t)l * WL_SIZE + woff[ti];
    __half* dlo = dlo_b + (size_t)l * WL_SIZE + woff[ti];

    int h = blockIdx.x >> 3, dt = blockIdx.x & 7;
    int d0 = dt * 64;
    int tid = threadIdx.x;
    for (int i = tid; i < 4096; i += 256) {
        int d = i >> 6, e = i & 63;
        t[e][d] = src[h * (DMOD * DKV) + (d0 + d) * DKV + e];
    }
    __syncthreads();
    for (int i = tid; i < 4096; i += 256) {
        int e = i >> 6, d = i & 63;
        __half hh, ll; hsplit(t[e][d], hh, ll);
        size_t o = (size_t)(h * 64 + e) * DMOD + d0 + d;
        dhi[o] = hh; dlo[o] = ll;
    }
}

// ---------------- batched projection-weight transpose ----------------
__global__ void pw_repack_all(const float* __restrict__ slf_pw, const float* __restrict__ enc_pw,
                              __half* __restrict__ dhi_b, __half* __restrict__ dlo_b) {
    __shared__ float t[32][33];
    int z = blockIdx.z, l = z >> 1, te = z & 1;
    const float* src = (te ? enc_pw : slf_pw) + (size_t)l * DMOD * DMOD;
    size_t doff = (size_t)l * WL_SIZE + (te ? WOFF_EPW : WOFF_SPW);
    __half* dhi = dhi_b + doff;
    __half* dlo = dlo_b + doff;

    int c0 = blockIdx.x * 32, r0 = blockIdx.y * 32;
    int x = threadIdx.x, y = threadIdx.y;        // 32 x 8
    for (int yy = y; yy < 32; yy += 8)
        t[yy][x] = src[(size_t)(r0 + yy) * DMOD + c0 + x];
    __syncthreads();
    for (int yy = y; yy < 32; yy += 8) {
        __half hh, ll; hsplit(t[x][yy], hh, ll);
        size_t o = (size_t)(c0 + yy) * DMOD + r0 + x;
        dhi[o] = hh; dlo[o] = ll;
    }
}

// ---------------- batched FFN weight transpose: [R,C] -> [C,R] ----------------
__global__ void ffn_repack_all(const float* __restrict__ w,
                               __half* __restrict__ dhi_b, __half* __restrict__ dlo_b,
                               int R, int C, int woff) {
    __shared__ float t[32][33];
    int l = blockIdx.z;
    const float* src = w + (size_t)l * R * C;
    size_t doff = (size_t)l * WL_SIZE + woff;
    __half* dhi = dhi_b + doff;
    __half* dlo = dlo_b + doff;

    int c0 = blockIdx.x * 32, r0 = blockIdx.y * 32;
    int x = threadIdx.x, y = threadIdx.y;        // 32 x 8
    for (int yy = y; yy < 32; yy += 8)
        t[yy][x] = src[(size_t)(r0 + yy) * C + c0 + x];
    __syncthreads();
    for (int yy = y; yy < 32; yy += 8) {
        __half hh, ll; hsplit(t[x][yy], hh, ll);
        size_t o = (size_t)(c0 + yy) * R + r0 + x;
        dhi[o] = hh; dlo[o] = ll;
    }
}

// ---------------- mma.sync fp16 GEMM: C[M,N] = A[M,K] @ (Bhi+Blo)[N,K]^T ----------------
// A single fp16, weights hi/lo fp16 -> 2 MMA passes. 4 warps, warp tile 64x64, K-chunk 64.
// mode 1: +bias -> fp32 Cf;  mode 2: +bias,relu -> fp16 Ch;  mode 3: qkv scatter -> fp16 Ch.
#define GM_PITCH 72                  // fp16 elems per smem row (144B, conflict-free ldmatrix)
#define GM_TILEB (128*GM_PITCH*2)    // 18432 B per 128x64 tile
#define GM_STAGE (3*GM_TILEB)        // A|Bhi|Blo = 55296 B
#define GM_SMEM  (2*GM_STAGE)        // 110592 B double buffered

__global__ __launch_bounds__(128, 1) void gemm_mma_k(
    const __half* __restrict__ A,
    const __half* __restrict__ Bhi, const __half* __restrict__ Blo,
    const float* __restrict__ bias,
    float* __restrict__ Cf, __half* __restrict__ Ch,
    int M, int N, int K, int mode)
{
    extern __shared__ __align__(16) char smem[];
    uint32_t sb = smem_u32(smem);
    const int tid = threadIdx.x, lane = tid & 31, w = tid >> 5;
    const int wm = w >> 1, wn = w & 1;          // warp grid 2 x 2 -> 64 x 64 tiles
    const int n0 = blockIdx.x * 128, m0 = blockIdx.y * 128;

    const __half* srcs[3] = {
        A + (size_t)m0 * K, Bhi + (size_t)n0 * K, Blo + (size_t)n0 * K };

    const int lrow = tid >> 3, lc8 = (tid & 7) * 8;

    auto load_chunk = [&](int kc, int st) {
        const int k0 = kc * 64;
        uint32_t stb = sb + st * GM_STAGE;
#pragma unroll
        for (int t = 0; t < 3; t++) {
            uint32_t tb = stb + t * GM_TILEB;
            const __half* src = srcs[t] + k0 + lc8;
#pragma unroll
            for (int j = 0; j < 8; j++) {
                int r = lrow + j * 16;
                cp16(tb + (r * GM_PITCH + lc8) * 2, src + (size_t)r * K);
            }
        }
    };

    float acc[4][8][4];
#pragma unroll
    for (int a = 0; a < 4; a++)
#pragma unroll
        for (int b = 0; b < 8; b++)
#pragma unroll
            for (int c = 0; c < 4; c++) acc[a][b][c] = 0.f;

    const int nch = K >> 6;
    load_chunk(0, 0); CP_COMMIT();

    const uint32_t a_off = ((wm * 64 + (lane & 15)) * GM_PITCH + ((lane >> 4) << 3)) * 2;
    const int b_lrow = (lane & 7) + ((lane & 16) ? 8 : 0);
    const int b_lcol = ((lane & 8) ? 8 : 0);

    for (int kc = 0; kc < nch; kc++) {
        if (kc + 1 < nch) { load_chunk(kc + 1, (kc + 1) & 1); CP_COMMIT(); CP_WAIT1(); }
        else { CP_WAIT0(); }
        __syncthreads();

        uint32_t stb = sb + (kc & 1) * GM_STAGE;
#pragma unroll
        for (int ks = 0; ks < 4; ks++) {
            const uint32_t kso = ks * 32;   // 16 elems * 2B
            uint32_t af[4][4];
#pragma unroll
            for (int mi = 0; mi < 4; mi++) {
                uint32_t off = a_off + mi * 16 * GM_PITCH * 2 + kso;
                ldsm_x4(af[mi], stb + off);
            }
#pragma unroll
            for (int ng = 0; ng < 2; ng++) {
                uint32_t bh[2][4], bl[2][4];
#pragma unroll
                for (int np = 0; np < 2; np++) {
                    uint32_t off = ((wn * 64 + ng * 32 + np * 16 + b_lrow) * GM_PITCH
                                    + b_lcol) * 2 + kso;
                    ldsm_x4(bh[np], stb + 1 * GM_TILEB + off);
                    ldsm_x4(bl[np], stb + 2 * GM_TILEB + off);
                }
#pragma unroll
                for (int mi = 0; mi < 4; mi++)
#pragma unroll
                    for (int nt = 0; nt < 4; nt++) {
                        const uint32_t* bhf = &bh[nt >> 1][(nt & 1) * 2];
                        const uint32_t* blf = &bl[nt >> 1][(nt & 1) * 2];
                        float* ac = acc[mi][ng * 4 + nt];
                        mma16816(ac, af[mi], bhf);
                        mma16816(ac, af[mi], blf);
                    }
            }
        }
        __syncthreads();
    }

    // epilogue
#pragma unroll
    for (int mi = 0; mi < 4; mi++) {
        int r0 = m0 + wm * 64 + mi * 16 + (lane >> 2);
#pragma unroll
        for (int nj = 0; nj < 8; nj++) {
            int col = n0 + wn * 64 + nj * 8 + (lane & 3) * 2;
            float c0 = acc[mi][nj][0], c1 = acc[mi][nj][1];
            float c2 = acc[mi][nj][2], c3 = acc[mi][nj][3];
            if (mode == 3) {
                int m = col >> 9, hh_ = (col >> 6) & 7, e = col & 63;
#pragma unroll
                for (int rr = 0; rr < 2; rr++) {
                    int row = r0 + rr * 8;
                    int b_ = row >> 9, t = row & 511;
                    size_t off = (size_t)m * 2097152 +
                                 (((size_t)(hh_ * NB + b_) * SEQ + t) * DKV + e);
                    *(__half2*)(Ch + off) = pack2(rr ? c2 : c0, rr ? c3 : c1);
                }
            } else if (mode == 1) {
                float2 bv = *(const float2*)(bias + col);
                float2 v0; v0.x = c0 + bv.x; v0.y = c1 + bv.y;
                float2 v1; v1.x = c2 + bv.x; v1.y = c3 + bv.y;
                *(float2*)(Cf + (size_t)r0 * N + col)       = v0;
                *(float2*)(Cf + (size_t)(r0 + 8) * N + col) = v1;
            } else {
                float2 bv = *(const float2*)(bias + col);
                float p0 = fmaxf(c0 + bv.x, 0.f), p1 = fmaxf(c1 + bv.y, 0.f);
                float p2 = fmaxf(c2 + bv.x, 0.f), p3 = fmaxf(c3 + bv.y, 0.f);
                *(__half2*)(Ch + (size_t)r0 * N + col)       = pack2(p0, p1);
                *(__half2*)(Ch + (size_t)(r0 + 8) * N + col) = pack2(p2, p3);
            }
        }
    }
}

// ---------------- MMA attention (single-pass fp16) ----------------
// Block = (qt, hb): 64 queries x 512 keys. 8 warps: wm = w&3 (16 rows), wn = w>>2 (half).
#define PT 72                      // fp16 pitch (144 B)
#define SC_PITCH 520
#define SC_OFF   0                 // fp32 [64][520] = 133120 B
#define Q_OFF    133120            // fp16 [64][72] = 9216 B
#define KV_OFF   (Q_OFF + 9216)    // 2 stages x 9216
#define KV_STAGE 9216
#define PT_OFF   (KV_OFF + 2*KV_STAGE)
#define BIAS_OFF (PT_OFF + 9216)   // fp32 [512]
#define ATTN2_SMEM (BIAS_OFF + 2048)   // 172032 B

__global__ __launch_bounds__(256, 1) void attn_mma_k(
    const __half* __restrict__ Qh, const __half* __restrict__ Kh, const __half* __restrict__ Vh,
    const int* __restrict__ seq, float* __restrict__ probs,
    __half* __restrict__ Oh, int causal, int writeProbs)
{
    extern __shared__ __align__(16) char sm2[];
    uint32_t sbase = smem_u32(sm2);
    float* Sc = (float*)(sm2 + SC_OFF);
    float* biasS = (float*)(sm2 + BIAS_OFF);
    const int hb = blockIdx.y, qt = blockIdx.x;
    const int h = hb >> 3, b = hb & 7;
    const int tid = threadIdx.x, lane = tid & 31, w = tid >> 5;
    const int wm = w & 3, wn = w >> 2;
    const float scale = 0.044194173824159216f;   // 1/sqrt(512)

    for (int i = tid; i < 512; i += 256)
        biasS[i] = (seq[b * SEQ + i] == 0) ? -1e30f : 0.f;

    // Q tile -> smem
    {
        int row = tid >> 2, s0 = (tid & 3) * 16;
        size_t gq = ((size_t)hb * SEQ + qt * 64 + row) * DKV + s0;
        *(uint4*)(sm2 + Q_OFF + (row * PT + s0) * 2)     = *(const uint4*)(Qh + gq);
        *(uint4*)(sm2 + Q_OFF + (row * PT + s0 + 8) * 2) = *(const uint4*)(Qh + gq + 8);
    }

    auto load_kv = [&](const __half* Src, int st, int stage) {
        uint32_t sbst = sbase + KV_OFF + stage * KV_STAGE;
        size_t gbase = ((size_t)hb * SEQ + st * 64) * DKV;
#pragma unroll
        for (int j = 0; j < 2; j++) {
            int seg = tid + j * 256;
            int row = seg >> 3, c = (seg & 7) * 8;
            cp16(sbst + (row * PT + c) * 2, Src + gbase + row * DKV + c);
        }
    };

    load_kv(Kh, 0, 0); CP_COMMIT();
    __syncthreads();

    // resident Q fragments
    uint32_t qf[4][4];
#pragma unroll
    for (int ks = 0; ks < 4; ks++) {
        uint32_t addr = sbase + Q_OFF +
            ((wm * 16 + (lane & 15)) * PT + ks * 16 + ((lane >> 4) << 3)) * 2;
        ldsm_x4(qf[ks], addr);
    }

    // ---- score phase ----
    for (int st = 0; st < 8; st++) {
        __syncthreads();
        if (st < 7) { load_kv(Kh, st + 1, (st + 1) & 1); CP_COMMIT(); CP_WAIT1(); }
        else { CP_WAIT0(); }
        __syncthreads();

        uint32_t kb = sbase + KV_OFF + (st & 1) * KV_STAGE;
        float acc[4][4];
#pragma unroll
        for (int i = 0; i < 4; i++)
#pragma unroll
            for (int j = 0; j < 4; j++) acc[i][j] = 0.f;

#pragma unroll
        for (int ks = 0; ks < 4; ks++) {
            uint32_t bh[2][4];
#pragma unroll
            for (int np = 0; np < 2; np++) {
                uint32_t addr = kb + ((wn * 32 + np * 16 + (lane & 7) + ((lane & 16) ? 8 : 0)) * PT
                                      + ks * 16 + ((lane & 8) ? 8 : 0)) * 2;
                ldsm_x4(bh[np], addr);
            }
#pragma unroll
            for (int nt = 0; nt < 4; nt++)
                mma16816(acc[nt], qf[ks], &bh[nt >> 1][(nt & 1) * 2]);
        }

        int r0 = wm * 16 + (lane >> 2);
#pragma unroll
        for (int nt = 0; nt < 4; nt++) {
            int col = st * 64 + wn * 32 + nt * 8 + (lane & 3) * 2;
            float b0 = biasS[col], b1 = biasS[col + 1];
#pragma unroll
            for (int rr = 0; rr < 2; rr++) {
                int row = r0 + rr * 8;
                int tg = qt * 64 + row;
                float v0 = acc[nt][rr * 2 + 0] * scale + b0;
                float v1 = acc[nt][rr * 2 + 1] * scale + b1;
                if (causal) {
                    if (col > tg)     v0 = -1e30f;
                    if (col + 1 > tg) v1 = -1e30f;
                }
                float2 vv; vv.x = v0; vv.y = v1;
                *(float2*)(Sc + row * SC_PITCH + col) = vv;
            }
        }
    }
    __syncthreads();

    // ---- softmax (warp per 8 rows) + probs write ----
    {
        for (int r = 0; r < 8; r++) {
            int q = w * 8 + r;
            float* row = Sc + q * SC_PITCH;
            float mx = -3.0e38f;
            for (int c = lane; c < 512; c += 32) mx = fmaxf(mx, row[c]);
#pragma unroll
            for (int o = 16; o; o >>= 1) mx = fmaxf(mx, __shfl_xor_sync(0xffffffffu, mx, o));
            float sum = 0.f;
            for (int c = lane; c < 512; c += 32) {
                float e = __expf(row[c] - mx);
                row[c] = e;
                sum += e;
            }
#pragma unroll
            for (int o = 16; o; o >>= 1) sum += __shfl_xor_sync(0xffffffffu, sum, o);
            float inv = 1.f / sum;
            float* prow = probs + ((size_t)hb * SEQ + qt * 64 + q) * SEQ;
            for (int c = lane; c < 512; c += 32) {
                float p = row[c] * inv;
                row[c] = p;
                if (writeProbs) prow[c] = p;
            }
        }
    }

    // ---- P @ V phase ----
    load_kv(Vh, 0, 0); CP_COMMIT();
    float oacc[4][4];
#pragma unroll
    for (int i = 0; i < 4; i++)
#pragma unroll
        for (int j = 0; j < 4; j++) oacc[i][j] = 0.f;

    for (int st = 0; st < 8; st++) {
        __syncthreads();
        if (st < 7) { load_kv(Vh, st + 1, (st + 1) & 1); CP_COMMIT(); CP_WAIT1(); }
        else { CP_WAIT0(); }

        // convert P tile st -> fp16
        {
            int row = tid >> 2, cb = (tid & 3) * 16;
            const float* srow = Sc + row * SC_PITCH + st * 64 + cb;
            __half* ph = (__half*)(sm2 + PT_OFF) + row * PT + cb;
#pragma unroll
            for (int j2 = 0; j2 < 16; j2 += 4) {
                float4 p4 = *(const float4*)(srow + j2);
                *(__half2*)(ph + j2)     = pack2(p4.x, p4.y);
                *(__half2*)(ph + j2 + 2) = pack2(p4.z, p4.w);
            }
        }
        __syncthreads();

        uint32_t vb = sbase + KV_OFF + (st & 1) * KV_STAGE;
#pragma unroll
        for (int ks = 0; ks < 4; ks++) {
            uint32_t af[4], vbf[2][4];
            uint32_t aaddr = sbase + PT_OFF +
                ((wm * 16 + (lane & 15)) * PT + ks * 16 + ((lane >> 4) << 3)) * 2;
            ldsm_x4(af, aaddr);
#pragma unroll
            for (int np = 0; np < 2; np++) {
                uint32_t addr = vb + ((ks * 16 + (lane & 7) + ((lane & 8) ? 8 : 0)) * PT
                                      + wn * 32 + np * 16 + ((lane & 16) ? 8 : 0)) * 2;
                ldsm_x4_t(vbf[np], addr);
            }
#pragma unroll
            for (int nt = 0; nt < 4; nt++)
                mma16816(oacc[nt], af, &vbf[nt >> 1][(nt & 1) * 2]);
        }
    }

    // O epilogue -> fp16, layout [b*SEQ+t][h*64+e]
    int r0 = wm * 16 + (lane >> 2);
#pragma unroll
    for (int nt = 0; nt < 4; nt++) {
        int gc = h * DKV + wn * 32 + nt * 8 + (lane & 3) * 2;
#pragma unroll
        for (int rr = 0; rr < 2; rr++) {
            int row = b * SEQ + qt * 64 + r0 + rr * 8;
            *(__half2*)(Oh + (size_t)row * DMOD + gc) =
                pack2(oacc[nt][rr * 2 + 0], oacc[nt][rr * 2 + 1]);
        }
    }
}

// ---------------- layernorm(y + res) -> fp32 out + fp16 ----------------
__global__ __launch_bounds__(128) void ln_k(
    const float* __restrict__ y, const float* __restrict__ res,
    const float* __restrict__ g, const float* __restrict__ b,
    float* __restrict__ out, __half* __restrict__ oh)
{
    __shared__ float red[8];
    int n = blockIdx.x, tid = threadIdx.x;
    int c = tid * 4;
    float4 yv = *(const float4*)(y   + (size_t)n * DMOD + c);
    float4 rv = *(const float4*)(res + (size_t)n * DMOD + c);
    float v0 = yv.x + rv.x, v1 = yv.y + rv.y, v2 = yv.z + rv.z, v3 = yv.w + rv.w;

    float s = v0 + v1 + v2 + v3;
    int lane = tid & 31, warp = tid >> 5;
#pragma unroll
    for (int o = 16; o; o >>= 1) s += __shfl_xor_sync(0xffffffffu, s, o);
    if (lane == 0) red[warp] = s;
    __syncthreads();
    float mu = (red[0] + red[1] + red[2] + red[3]) * (1.f / DMOD);

    float d0 = v0 - mu, d1 = v1 - mu, d2 = v2 - mu, d3 = v3 - mu;
    float ss = d0 * d0 + d1 * d1 + d2 * d2 + d3 * d3;
#pragma unroll
    for (int o = 16; o; o >>= 1) ss += __shfl_xor_sync(0xffffffffu, ss, o);
    if (lane == 0) red[4 + warp] = ss;
    __syncthreads();
    float var = (red[4] + red[5] + red[6] + red[7]) * (1.f / DMOD);
    float is = rsqrtf(var + 1e-5f);

    float4 gv = *(const float4*)(g + c);
    float4 bv = *(const float4*)(b + c);
    float4 ov;
    ov.x = d0 * is * gv.x + bv.x;
    ov.y = d1 * is * gv.y + bv.y;
    ov.z = d2 * is * gv.z + bv.z;
    ov.w = d3 * is * gv.w + bv.w;
    *(float4*)(out + (size_t)n * DMOD + c) = ov;
    *(__half2*)(oh + (size_t)n * DMOD + c)     = pack2(ov.x, ov.y);
    *(__half2*)(oh + (size_t)n * DMOD + c + 2) = pack2(ov.z, ov.w);
}

// ---------------- host ----------------
extern "C" void kernel_launch(void* const* d_in, const int* in_sizes, int n_in,
                              void* d_out, int out_size)
{
    const int*   tgt_seq = (const int*)d_in[0];
    const int*   tgt_pos = (const int*)d_in[1];
    const int*   src_seq = (const int*)d_in[2];
    const float* enc_out = (const float*)d_in[3];
    const float* tgt_emb = (const float*)d_in[4];
    const float* pos_emb = (const float*)d_in[5];
    const float* slf_wq  = (const float*)d_in[6];
    const float* slf_wk  = (const float*)d_in[7];
    const float* slf_wv  = (const float*)d_in[8];
    const float* slf_pw  = (const float*)d_in[9];
    const float* slf_pb  = (const float*)d_in[10];
    const float* slf_g   = (const float*)d_in[11];
    const float* slf_b   = (const float*)d_in[12];
    const float* enc_wq  = (const float*)d_in[13];
    const float* enc_wk  = (const float*)d_in[14];
    const float* enc_wv  = (const float*)d_in[15];
    const float* enc_pw  = (const float*)d_in[16];
    const float* enc_pb  = (const float*)d_in[17];
    const float* enc_g   = (const float*)d_in[18];
    const float* enc_b   = (const float*)d_in[19];
    const float* ffn_w1  = (const float*)d_in[20];
    const float* ffn_b1  = (const float*)d_in[21];
    const float* ffn_w2  = (const float*)d_in[22];
    const float* ffn_b2  = (const float*)d_in[23];
    const float* ffn_g   = (const float*)d_in[24];
    const float* ffn_b   = (const float*)d_in[25];

    float *xp, *yp;
    __half *qkvh, *xh, *eh, *aoh, *hh, *wbhi, *wblo;
    cudaGetSymbolAddress((void**)&xp,   g_x);
    cudaGetSymbolAddress((void**)&yp,   g_y);
    cudaGetSymbolAddress((void**)&qkvh, g_qkvh);
    cudaGetSymbolAddress((void**)&xh,   g_xh);
    cudaGetSymbolAddress((void**)&eh,   g_eh);
    cudaGetSymbolAddress((void**)&aoh,  g_aoh);
    cudaGetSymbolAddress((void**)&hh,   g_hh);
    cudaGetSymbolAddress((void**)&wbhi, g_wbhi);
    cudaGetSymbolAddress((void**)&wblo, g_wblo);

    cudaFuncSetAttribute(attn_mma_k, cudaFuncAttributeMaxDynamicSharedMemorySize, ATTN2_SMEM);
    cudaFuncSetAttribute(gemm_mma_k, cudaFuncAttributeMaxDynamicSharedMemorySize, GM_SMEM);

    const int full = (out_size >= (int)FULL_OUT) ? 1 : 0;
    float* out_f = (float*)d_out;
    float* probs_slf = out_f + SLF_OFF;
    float* probs_enc = out_f + ENC_OFF;

    __half* qh = qkvh;
    __half* kh = qkvh + 2097152;
    __half* vh = qkvh + 4194304;

    embed_k<<<NTOK, 128>>>(tgt_seq, tgt_pos, tgt_emb, pos_emb, xp, xh);
    conv_h_k<<<(NTOK * DMOD) / 256, 256>>>(enc_out, eh, NTOK * DMOD);

    // ---- batched weight prep: 4 launches for all 60 repacks ----
    {
        P6 srcs;
        srcs.p[0] = slf_wq; srcs.p[1] = slf_wk; srcs.p[2] = slf_wv;
        srcs.p[3] = enc_wq; srcs.p[4] = enc_wk; srcs.p[5] = enc_wv;
        qkv_repack_all<<<dim3(64, 6, 6), 256>>>(srcs, wbhi, wblo);
        pw_repack_all<<<dim3(16, 16, 12), dim3(32, 8)>>>(slf_pw, enc_pw, wbhi, wblo);
        ffn_repack_all<<<dim3(64, 16, 6), dim3(32, 8)>>>(ffn_w1, wbhi, wblo, DMOD, DFF, WOFF_W1);
        ffn_repack_all<<<dim3(16, 64, 6), dim3(32, 8)>>>(ffn_w2, wbhi, wblo, DFF, DMOD, WOFF_W2);
    }

    dim3 gAttn(8, NHB);

    for (int l = 0; l < NL; l++) {
        size_t LB = (size_t)l * WL_SIZE;

        // ---- self attention: fused QKV (N=1536) ----
        gemm_mma_k<<<dim3(12, 32), 128, GM_SMEM>>>(xh,
            wbhi + LB + WOFF_SQ, wblo + LB + WOFF_SQ,
            nullptr, nullptr, qkvh, NTOK, 1536, DMOD, 3);
        attn_mma_k<<<gAttn, 256, ATTN2_SMEM>>>(qh, kh, vh, tgt_seq,
            probs_slf + (size_t)l * ATT_PER_L, aoh, 1, full);
        gemm_mma_k<<<dim3(4, 32), 128, GM_SMEM>>>(aoh,
            wbhi + LB + WOFF_SPW, wblo + LB + WOFF_SPW,
            slf_pb + (size_t)l * DMOD, yp, nullptr, NTOK, DMOD, DMOD, 1);
        ln_k<<<NTOK, 128>>>(yp, xp, slf_g + (size_t)l * DMOD, slf_b + (size_t)l * DMOD,
                            xp, xh);

        // ---- cross attention: Q from x (N=512), fused KV from enc (N=1024) ----
        gemm_mma_k<<<dim3(4, 32), 128, GM_SMEM>>>(xh,
            wbhi + LB + WOFF_EQ, wblo + LB + WOFF_EQ,
            nullptr, nullptr, qkvh, NTOK, DMOD, DMOD, 3);
        gemm_mma_k<<<dim3(8, 32), 128, GM_SMEM>>>(eh,
            wbhi + LB + WOFF_EK, wblo + LB + WOFF_EK,
            nullptr, nullptr, qkvh + 2097152, NTOK, 1024, DMOD, 3);
        attn_mma_k<<<gAttn, 256, ATTN2_SMEM>>>(qh, kh, vh, src_seq,
            probs_enc + (size_t)l * ATT_PER_L, aoh, 0, full);
        gemm_mma_k<<<dim3(4, 32), 128, GM_SMEM>>>(aoh,
            wbhi + LB + WOFF_EPW, wblo + LB + WOFF_EPW,
            enc_pb + (size_t)l * DMOD, yp, nullptr, NTOK, DMOD, DMOD, 1);
        ln_k<<<NTOK, 128>>>(yp, xp, enc_g + (size_t)l * DMOD, enc_b + (size_t)l * DMOD,
                            xp, xh);

        // ---- FFN ----
        gemm_mma_k<<<dim3(16, 32), 128, GM_SMEM>>>(xh,
            wbhi + LB + WOFF_W1, wblo + LB + WOFF_W1,
            ffn_b1 + (size_t)l * DFF, nullptr, hh, NTOK, DFF, DMOD, 2);
        gemm_mma_k<<<dim3(4, 32), 128, GM_SMEM>>>(hh,
            wbhi + LB + WOFF_W2, wblo + LB + WOFF_W2,
            ffn_b2 + (size_t)l * DMOD, yp, nullptr, NTOK, DMOD, DFF, 1);
        ln_k<<<NTOK, 128>>>(yp, xp, ffn_g + (size_t)l * DMOD, ffn_b + (size_t)l * DMOD,
                            xp, xh);
    }

    size_t copy_elems = (size_t)out_size < (size_t)X_ELEMS ? (size_t)out_size : (size_t)X_ELEMS;
    cudaMemcpyAsync(d_out, xp, copy_elems * sizeof(float), cudaMemcpyDeviceToDevice);
}

// round 15
// speedup vs baseline: 2.9388x; 1.2850x over previous
#include <cuda_runtime.h>
#include <cuda_fp16.h>
#include <cstdint>

// Problem constants
#define NL   6
#define NH   8
#define DMOD 512
#define DKV  64
#define DFF  2048
#define NB   8
#define SEQ  512
#define NTOK 4096          // NB*SEQ
#define NHB  64            // NH*NB

#define X_ELEMS   (NTOK*DMOD)                 // 2,097,152
#define ATT_PER_L ((size_t)NHB*SEQ*SEQ)       // 16,777,216
#define SLF_OFF   ((size_t)X_ELEMS)
#define ENC_OFF   (SLF_OFF + (size_t)NL*ATT_PER_L)
#define FULL_OUT  (ENC_OFF + (size_t)NL*ATT_PER_L)   // 203,423,744

// per-layer fp16 weight bank layout (element offsets)
#define WOFF_SQ   0
#define WOFF_SK   262144
#define WOFF_SV   524288
#define WOFF_SPW  786432
#define WOFF_EQ   1048576
#define WOFF_EK   1310720
#define WOFF_EV   1572864
#define WOFF_EPW  1835008
#define WOFF_W1   2097152
#define WOFF_W2   3145728
#define WL_SIZE   4194304

// ---------------- scratch (no allocations allowed) ----------------
__device__ float g_x  [NTOK*DMOD];
__device__ float g_y  [NTOK*DMOD];
__device__ __half g_qkvh[3*NHB*SEQ*DKV];   // q|k|v fp16, head-major [hb][t][e]
__device__ __half g_xh [NTOK*DMOD];
__device__ __half g_eh [NTOK*DMOD];
__device__ __half g_aoh[NTOK*DMOD];
__device__ __half g_hh [NTOK*DFF];
__device__ __half g_wb [(size_t)NL*WL_SIZE];

struct P6 { const float* p[6]; };

// ---------------- helpers (baseline PTX only: sm_80-class) ----------------
__device__ __forceinline__ uint32_t smem_u32(const void* p) {
    uint32_t a;
    asm("{ .reg .u64 t; cvta.to.shared.u64 t, %1; cvt.u32.u64 %0, t; }" : "=r"(a) : "l"(p));
    return a;
}
__device__ __forceinline__ void cp16(uint32_t saddr, const void* g) {
    asm volatile("cp.async.cg.shared.global [%0], [%1], 16;" :: "r"(saddr), "l"(g));
}
#define CP_COMMIT() asm volatile("cp.async.commit_group;" ::: "memory")
#define CP_WAIT1()  asm volatile("cp.async.wait_group 1;" ::: "memory")
#define CP_WAIT0()  asm volatile("cp.async.wait_group 0;" ::: "memory")

__device__ __forceinline__ void ldsm_x4(uint32_t* r, uint32_t addr) {
    asm volatile("ldmatrix.sync.aligned.m8n8.x4.shared.b16 {%0,%1,%2,%3}, [%4];"
                 : "=r"(r[0]), "=r"(r[1]), "=r"(r[2]), "=r"(r[3]) : "r"(addr));
}
__device__ __forceinline__ void ldsm_x4_t(uint32_t* r, uint32_t addr) {
    asm volatile("ldmatrix.sync.aligned.m8n8.x4.trans.shared.b16 {%0,%1,%2,%3}, [%4];"
                 : "=r"(r[0]), "=r"(r[1]), "=r"(r[2]), "=r"(r[3]) : "r"(addr));
}
__device__ __forceinline__ void mma16816(float* d, const uint32_t* a, const uint32_t* b) {
    asm volatile("mma.sync.aligned.m16n8k16.row.col.f32.f16.f16.f32 "
                 "{%0,%1,%2,%3}, {%4,%5,%6,%7}, {%8,%9}, {%0,%1,%2,%3};"
                 : "+f"(d[0]), "+f"(d[1]), "+f"(d[2]), "+f"(d[3])
                 : "r"(a[0]), "r"(a[1]), "r"(a[2]), "r"(a[3]), "r"(b[0]), "r"(b[1]));
}

__device__ __forceinline__ __half2 pack2(float a, float b) {
    return __floats2half2_rn(a, b);
}

// ---------------- embedding (fp32 x + fp16) ----------------
__global__ void embed_k(const int* __restrict__ seq, const int* __restrict__ pos,
                        const float* __restrict__ wemb, const float* __restrict__ pemb,
                        float* __restrict__ x, __half* __restrict__ xh) {
    int n = blockIdx.x;
    int s = seq[n], p = pos[n];
    const float* we = wemb + (size_t)s * DMOD;
    const float* pe = pemb + (size_t)p * DMOD;
    for (int c = threadIdx.x; c < DMOD; c += blockDim.x) {
        float v = we[c] + pe[c];
        x[(size_t)n * DMOD + c] = v;
        xh[(size_t)n * DMOD + c] = __float2half(v);
    }
}

// ---------------- fp32 -> fp16 (enc_output) ----------------
__global__ void conv_h_k(const float* __restrict__ src, __half* __restrict__ dst, int n) {
    int i = blockIdx.x * blockDim.x + threadIdx.x;
    if (i < n) dst[i] = __float2half(src[i]);
}

// ---------------- batched qkv weight repack (all 6 tensors x 6 layers) ----------------
__global__ void qkv_repack_all(P6 srcs, __half* __restrict__ d_b) {
    __shared__ float t[64][65];
    const int woff[6] = {WOFF_SQ, WOFF_SK, WOFF_SV, WOFF_EQ, WOFF_EK, WOFF_EV};
    int ti = blockIdx.y, l = blockIdx.z;
    const float* src = srcs.p[ti] + (size_t)l * (NH * DMOD * DKV);
    __half* dst = d_b + (size_t)l * WL_SIZE + woff[ti];

    int h = blockIdx.x >> 3, dt = blockIdx.x & 7;
    int d0 = dt * 64;
    int tid = threadIdx.x;
    for (int i = tid; i < 4096; i += 256) {
        int d = i >> 6, e = i & 63;
        t[e][d] = src[h * (DMOD * DKV) + (d0 + d) * DKV + e];
    }
    __syncthreads();
    for (int i = tid; i < 4096; i += 256) {
        int e = i >> 6, d = i & 63;
        dst[(size_t)(h * 64 + e) * DMOD + d0 + d] = __float2half(t[e][d]);
    }
}

// ---------------- batched projection-weight transpose ----------------
__global__ void pw_repack_all(const float* __restrict__ slf_pw, const float* __restrict__ enc_pw,
                              __half* __restrict__ d_b) {
    __shared__ float t[32][33];
    int z = blockIdx.z, l = z >> 1, te = z & 1;
    const float* src = (te ? enc_pw : slf_pw) + (size_t)l * DMOD * DMOD;
    __half* dst = d_b + (size_t)l * WL_SIZE + (te ? WOFF_EPW : WOFF_SPW);

    int c0 = blockIdx.x * 32, r0 = blockIdx.y * 32;
    int x = threadIdx.x, y = threadIdx.y;        // 32 x 8
    for (int yy = y; yy < 32; yy += 8)
        t[yy][x] = src[(size_t)(r0 + yy) * DMOD + c0 + x];
    __syncthreads();
    for (int yy = y; yy < 32; yy += 8)
        dst[(size_t)(c0 + yy) * DMOD + r0 + x] = __float2half(t[x][yy]);
}

// ---------------- batched FFN weight transpose: [R,C] -> [C,R] ----------------
__global__ void ffn_repack_all(const float* __restrict__ w, __half* __restrict__ d_b,
                               int R, int C, int woff) {
    __shared__ float t[32][33];
    int l = blockIdx.z;
    const float* src = w + (size_t)l * R * C;
    __half* dst = d_b + (size_t)l * WL_SIZE + woff;

    int c0 = blockIdx.x * 32, r0 = blockIdx.y * 32;
    int x = threadIdx.x, y = threadIdx.y;        // 32 x 8
    for (int yy = y; yy < 32; yy += 8)
        t[yy][x] = src[(size_t)(r0 + yy) * C + c0 + x];
    __syncthreads();
    for (int yy = y; yy < 32; yy += 8)
        dst[(size_t)(c0 + yy) * R + r0 + x] = __float2half(t[x][yy]);
}

// ---------------- mma.sync fp16 GEMM: C[M,N] = A[M,K] @ B[N,K]^T ----------------
// Single-pass fp16. 4 warps, warp tile 64x64, K-chunk 64, 2-stage double buffer.
// mode 1: +bias -> fp32 Cf;  mode 2: +bias,relu -> fp16 Ch;  mode 3: qkv scatter -> fp16 Ch.
#define GM_PITCH 72                  // fp16 elems per smem row (144B, conflict-free ldmatrix)
#define GM_TILEB (128*GM_PITCH*2)    // 18432 B per 128x64 tile
#define GM_STAGE (2*GM_TILEB)        // A|B = 36864 B
#define GM_SMEM  (2*GM_STAGE)        // 73728 B double buffered

__global__ __launch_bounds__(128, 1) void gemm_mma_k(
    const __half* __restrict__ A, const __half* __restrict__ B,
    const float* __restrict__ bias,
    float* __restrict__ Cf, __half* __restrict__ Ch,
    int M, int N, int K, int mode)
{
    extern __shared__ __align__(16) char smem[];
    uint32_t sb = smem_u32(smem);
    const int tid = threadIdx.x, lane = tid & 31, w = tid >> 5;
    const int wm = w >> 1, wn = w & 1;          // warp grid 2 x 2 -> 64 x 64 tiles
    const int n0 = blockIdx.x * 128, m0 = blockIdx.y * 128;

    const __half* srcs[2] = { A + (size_t)m0 * K, B + (size_t)n0 * K };

    const int lrow = tid >> 3, lc8 = (tid & 7) * 8;

    auto load_chunk = [&](int kc, int st) {
        const int k0 = kc * 64;
        uint32_t stb = sb + st * GM_STAGE;
#pragma unroll
        for (int t = 0; t < 2; t++) {
            uint32_t tb = stb + t * GM_TILEB;
            const __half* src = srcs[t] + k0 + lc8;
#pragma unroll
            for (int j = 0; j < 8; j++) {
                int r = lrow + j * 16;
                cp16(tb + (r * GM_PITCH + lc8) * 2, src + (size_t)r * K);
            }
        }
    };

    float acc[4][8][4];
#pragma unroll
    for (int a = 0; a < 4; a++)
#pragma unroll
        for (int b = 0; b < 8; b++)
#pragma unroll
            for (int c = 0; c < 4; c++) acc[a][b][c] = 0.f;

    const int nch = K >> 6;
    load_chunk(0, 0); CP_COMMIT();

    const uint32_t a_off = ((wm * 64 + (lane & 15)) * GM_PITCH + ((lane >> 4) << 3)) * 2;
    const int b_lrow = (lane & 7) + ((lane & 16) ? 8 : 0);
    const int b_lcol = ((lane & 8) ? 8 : 0);

    for (int kc = 0; kc < nch; kc++) {
        if (kc + 1 < nch) { load_chunk(kc + 1, (kc + 1) & 1); CP_COMMIT(); CP_WAIT1(); }
        else { CP_WAIT0(); }
        __syncthreads();

        uint32_t stb = sb + (kc & 1) * GM_STAGE;
#pragma unroll
        for (int ks = 0; ks < 4; ks++) {
            const uint32_t kso = ks * 32;   // 16 elems * 2B
            uint32_t af[4][4];
#pragma unroll
            for (int mi = 0; mi < 4; mi++) {
                uint32_t off = a_off + mi * 16 * GM_PITCH * 2 + kso;
                ldsm_x4(af[mi], stb + off);
            }
#pragma unroll
            for (int ng = 0; ng < 2; ng++) {
                uint32_t bf[2][4];
#pragma unroll
                for (int np = 0; np < 2; np++) {
                    uint32_t off = ((wn * 64 + ng * 32 + np * 16 + b_lrow) * GM_PITCH
                                    + b_lcol) * 2 + kso;
                    ldsm_x4(bf[np], stb + GM_TILEB + off);
                }
#pragma unroll
                for (int mi = 0; mi < 4; mi++)
#pragma unroll
                    for (int nt = 0; nt < 4; nt++)
                        mma16816(acc[mi][ng * 4 + nt], af[mi], &bf[nt >> 1][(nt & 1) * 2]);
            }
        }
        __syncthreads();
    }

    // epilogue
#pragma unroll
    for (int mi = 0; mi < 4; mi++) {
        int r0 = m0 + wm * 64 + mi * 16 + (lane >> 2);
#pragma unroll
        for (int nj = 0; nj < 8; nj++) {
            int col = n0 + wn * 64 + nj * 8 + (lane & 3) * 2;
            float c0 = acc[mi][nj][0], c1 = acc[mi][nj][1];
            float c2 = acc[mi][nj][2], c3 = acc[mi][nj][3];
            if (mode == 3) {
                int m = col >> 9, hh_ = (col >> 6) & 7, e = col & 63;
#pragma unroll
                for (int rr = 0; rr < 2; rr++) {
                    int row = r0 + rr * 8;
                    int b_ = row >> 9, t = row & 511;
                    size_t off = (size_t)m * 2097152 +
                                 (((size_t)(hh_ * NB + b_) * SEQ + t) * DKV + e);
                    *(__half2*)(Ch + off) = pack2(rr ? c2 : c0, rr ? c3 : c1);
                }
            } else if (mode == 1) {
                float2 bv = *(const float2*)(bias + col);
                float2 v0; v0.x = c0 + bv.x; v0.y = c1 + bv.y;
                float2 v1; v1.x = c2 + bv.x; v1.y = c3 + bv.y;
                *(float2*)(Cf + (size_t)r0 * N + col)       = v0;
                *(float2*)(Cf + (size_t)(r0 + 8) * N + col) = v1;
            } else {
                float2 bv = *(const float2*)(bias + col);
                float p0 = fmaxf(c0 + bv.x, 0.f), p1 = fmaxf(c1 + bv.y, 0.f);
                float p2 = fmaxf(c2 + bv.x, 0.f), p3 = fmaxf(c3 + bv.y, 0.f);
                *(__half2*)(Ch + (size_t)r0 * N + col)       = pack2(p0, p1);
                *(__half2*)(Ch + (size_t)(r0 + 8) * N + col) = pack2(p2, p3);
            }
        }
    }
}

// ---------------- MMA attention (single-pass fp16) ----------------
// Block = (qt, hb): 64 queries x 512 keys. 8 warps: wm = w&3 (16 rows), wn = w>>2 (half).
#define PT 72                      // fp16 pitch (144 B)
#define SC_PITCH 520
#define SC_OFF   0                 // fp32 [64][520] = 133120 B
#define Q_OFF    133120            // fp16 [64][72] = 9216 B
#define KV_OFF   (Q_OFF + 9216)    // 2 stages x 9216
#define KV_STAGE 9216
#define PT_OFF   (KV_OFF + 2*KV_STAGE)
#define BIAS_OFF (PT_OFF + 9216)   // fp32 [512]
#define ATTN2_SMEM (BIAS_OFF + 2048)   // 172032 B

__global__ __launch_bounds__(256, 1) void attn_mma_k(
    const __half* __restrict__ Qh, const __half* __restrict__ Kh, const __half* __restrict__ Vh,
    const int* __restrict__ seq, float* __restrict__ probs,
    __half* __restrict__ Oh, int causal, int writeProbs)
{
    extern __shared__ __align__(16) char sm2[];
    uint32_t sbase = smem_u32(sm2);
    float* Sc = (float*)(sm2 + SC_OFF);
    float* biasS = (float*)(sm2 + BIAS_OFF);
    const int hb = blockIdx.y, qt = blockIdx.x;
    const int h = hb >> 3, b = hb & 7;
    const int tid = threadIdx.x, lane = tid & 31, w = tid >> 5;
    const int wm = w & 3, wn = w >> 2;
    const float scale = 0.044194173824159216f;   // 1/sqrt(512)

    for (int i = tid; i < 512; i += 256)
        biasS[i] = (seq[b * SEQ + i] == 0) ? -1e30f : 0.f;

    // Q tile -> smem
    {
        int row = tid >> 2, s0 = (tid & 3) * 16;
        size_t gq = ((size_t)hb * SEQ + qt * 64 + row) * DKV + s0;
        *(uint4*)(sm2 + Q_OFF + (row * PT + s0) * 2)     = *(const uint4*)(Qh + gq);
        *(uint4*)(sm2 + Q_OFF + (row * PT + s0 + 8) * 2) = *(const uint4*)(Qh + gq + 8);
    }

    auto load_kv = [&](const __half* Src, int st, int stage) {
        uint32_t sbst = sbase + KV_OFF + stage * KV_STAGE;
        size_t gbase = ((size_t)hb * SEQ + st * 64) * DKV;
#pragma unroll
        for (int j = 0; j < 2; j++) {
            int seg = tid + j * 256;
            int row = seg >> 3, c = (seg & 7) * 8;
            cp16(sbst + (row * PT + c) * 2, Src + gbase + row * DKV + c);
        }
    };

    load_kv(Kh, 0, 0); CP_COMMIT();
    __syncthreads();

    // resident Q fragments
    uint32_t qf[4][4];
#pragma unroll
    for (int ks = 0; ks < 4; ks++) {
        uint32_t addr = sbase + Q_OFF +
            ((wm * 16 + (lane & 15)) * PT + ks * 16 + ((lane >> 4) << 3)) * 2;
        ldsm_x4(qf[ks], addr);
    }

    // ---- score phase ----
    for (int st = 0; st < 8; st++) {
        __syncthreads();
        if (st < 7) { load_kv(Kh, st + 1, (st + 1) & 1); CP_COMMIT(); CP_WAIT1(); }
        else { CP_WAIT0(); }
        __syncthreads();

        uint32_t kb = sbase + KV_OFF + (st & 1) * KV_STAGE;
        float acc[4][4];
#pragma unroll
        for (int i = 0; i < 4; i++)
#pragma unroll
            for (int j = 0; j < 4; j++) acc[i][j] = 0.f;

#pragma unroll
        for (int ks = 0; ks < 4; ks++) {
            uint32_t bh[2][4];
#pragma unroll
            for (int np = 0; np < 2; np++) {
                uint32_t addr = kb + ((wn * 32 + np * 16 + (lane & 7) + ((lane & 16) ? 8 : 0)) * PT
                                      + ks * 16 + ((lane & 8) ? 8 : 0)) * 2;
                ldsm_x4(bh[np], addr);
            }
#pragma unroll
            for (int nt = 0; nt < 4; nt++)
                mma16816(acc[nt], qf[ks], &bh[nt >> 1][(nt & 1) * 2]);
        }

        int r0 = wm * 16 + (lane >> 2);
#pragma unroll
        for (int nt = 0; nt < 4; nt++) {
            int col = st * 64 + wn * 32 + nt * 8 + (lane & 3) * 2;
            float b0 = biasS[col], b1 = biasS[col + 1];
#pragma unroll
            for (int rr = 0; rr < 2; rr++) {
                int row = r0 + rr * 8;
                int tg = qt * 64 + row;
                float v0 = acc[nt][rr * 2 + 0] * scale + b0;
                float v1 = acc[nt][rr * 2 + 1] * scale + b1;
                if (causal) {
                    if (col > tg)     v0 = -1e30f;
                    if (col + 1 > tg) v1 = -1e30f;
                }
                float2 vv; vv.x = v0; vv.y = v1;
                *(float2*)(Sc + row * SC_PITCH + col) = vv;
            }
        }
    }
    __syncthreads();

    // ---- softmax (warp per 8 rows) + probs write ----
    {
        for (int r = 0; r < 8; r++) {
            int q = w * 8 + r;
            float* row = Sc + q * SC_PITCH;
            float mx = -3.0e38f;
            for (int c = lane; c < 512; c += 32) mx = fmaxf(mx, row[c]);
#pragma unroll
            for (int o = 16; o; o >>= 1) mx = fmaxf(mx, __shfl_xor_sync(0xffffffffu, mx, o));
            float sum = 0.f;
            for (int c = lane; c < 512; c += 32) {
                float e = __expf(row[c] - mx);
                row[c] = e;
                sum += e;
            }
#pragma unroll
            for (int o = 16; o; o >>= 1) sum += __shfl_xor_sync(0xffffffffu, sum, o);
            float inv = 1.f / sum;
            float* prow = probs + ((size_t)hb * SEQ + qt * 64 + q) * SEQ;
            for (int c = lane; c < 512; c += 32) {
                float p = row[c] * inv;
                row[c] = p;
                if (writeProbs) prow[c] = p;
            }
        }
    }

    // ---- P @ V phase ----
    load_kv(Vh, 0, 0); CP_COMMIT();
    float oacc[4][4];
#pragma unroll
    for (int i = 0; i < 4; i++)
#pragma unroll
        for (int j = 0; j < 4; j++) oacc[i][j] = 0.f;

    for (int st = 0; st < 8; st++) {
        __syncthreads();
        if (st < 7) { load_kv(Vh, st + 1, (st + 1) & 1); CP_COMMIT(); CP_WAIT1(); }
        else { CP_WAIT0(); }

        // convert P tile st -> fp16
        {
            int row = tid >> 2, cb = (tid & 3) * 16;
            const float* srow = Sc + row * SC_PITCH + st * 64 + cb;
            __half* ph = (__half*)(sm2 + PT_OFF) + row * PT + cb;
#pragma unroll
            for (int j2 = 0; j2 < 16; j2 += 4) {
                float4 p4 = *(const float4*)(srow + j2);
                *(__half2*)(ph + j2)     = pack2(p4.x, p4.y);
                *(__half2*)(ph + j2 + 2) = pack2(p4.z, p4.w);
            }
        }
        __syncthreads();

        uint32_t vb = sbase + KV_OFF + (st & 1) * KV_STAGE;
#pragma unroll
        for (int ks = 0; ks < 4; ks++) {
            uint32_t af[4], vbf[2][4];
            uint32_t aaddr = sbase + PT_OFF +
                ((wm * 16 + (lane & 15)) * PT + ks * 16 + ((lane >> 4) << 3)) * 2;
            ldsm_x4(af, aaddr);
#pragma unroll
            for (int np = 0; np < 2; np++) {
                uint32_t addr = vb + ((ks * 16 + (lane & 7) + ((lane & 8) ? 8 : 0)) * PT
                                      + wn * 32 + np * 16 + ((lane & 16) ? 8 : 0)) * 2;
                ldsm_x4_t(vbf[np], addr);
            }
#pragma unroll
            for (int nt = 0; nt < 4; nt++)
                mma16816(oacc[nt], af, &vbf[nt >> 1][(nt & 1) * 2]);
        }
    }

    // O epilogue -> fp16, layout [b*SEQ+t][h*64+e]
    int r0 = wm * 16 + (lane >> 2);
#pragma unroll
    for (int nt = 0; nt < 4; nt++) {
        int gc = h * DKV + wn * 32 + nt * 8 + (lane & 3) * 2;
#pragma unroll
        for (int rr = 0; rr < 2; rr++) {
            int row = b * SEQ + qt * 64 + r0 + rr * 8;
            *(__half2*)(Oh + (size_t)row * DMOD + gc) =
                pack2(oacc[nt][rr * 2 + 0], oacc[nt][rr * 2 + 1]);
        }
    }
}

// ---------------- layernorm(y + res) -> fp32 out + fp16 ----------------
__global__ __launch_bounds__(128) void ln_k(
    const float* __restrict__ y, const float* __restrict__ res,
    const float* __restrict__ g, const float* __restrict__ b,
    float* __restrict__ out, __half* __restrict__ oh)
{
    __shared__ float red[8];
    int n = blockIdx.x, tid = threadIdx.x;
    int c = tid * 4;
    float4 yv = *(const float4*)(y   + (size_t)n * DMOD + c);
    float4 rv = *(const float4*)(res + (size_t)n * DMOD + c);
    float v0 = yv.x + rv.x, v1 = yv.y + rv.y, v2 = yv.z + rv.z, v3 = yv.w + rv.w;

    float s = v0 + v1 + v2 + v3;
    int lane = tid & 31, warp = tid >> 5;
#pragma unroll
    for (int o = 16; o; o >>= 1) s += __shfl_xor_sync(0xffffffffu, s, o);
    if (lane == 0) red[warp] = s;
    __syncthreads();
    float mu = (red[0] + red[1] + red[2] + red[3]) * (1.f / DMOD);

    float d0 = v0 - mu, d1 = v1 - mu, d2 = v2 - mu, d3 = v3 - mu;
    float ss = d0 * d0 + d1 * d1 + d2 * d2 + d3 * d3;
#pragma unroll
    for (int o = 16; o; o >>= 1) ss += __shfl_xor_sync(0xffffffffu, ss, o);
    if (lane == 0) red[4 + warp] = ss;
    __syncthreads();
    float var = (red[4] + red[5] + red[6] + red[7]) * (1.f / DMOD);
    float is = rsqrtf(var + 1e-5f);

    float4 gv = *(const float4*)(g + c);
    float4 bv = *(const float4*)(b + c);
    float4 ov;
    ov.x = d0 * is * gv.x + bv.x;
    ov.y = d1 * is * gv.y + bv.y;
    ov.z = d2 * is * gv.z + bv.z;
    ov.w = d3 * is * gv.w + bv.w;
    *(float4*)(out + (size_t)n * DMOD + c) = ov;
    *(__half2*)(oh + (size_t)n * DMOD + c)     = pack2(ov.x, ov.y);
    *(__half2*)(oh + (size_t)n * DMOD + c + 2) = pack2(ov.z, ov.w);
}

// ---------------- host ----------------
extern "C" void kernel_launch(void* const* d_in, const int* in_sizes, int n_in,
                              void* d_out, int out_size)
{
    const int*   tgt_seq = (const int*)d_in[0];
    const int*   tgt_pos = (const int*)d_in[1];
    const int*   src_seq = (const int*)d_in[2];
    const float* enc_out = (const float*)d_in[3];
    const float* tgt_emb = (const float*)d_in[4];
    const float* pos_emb = (const float*)d_in[5];
    const float* slf_wq  = (const float*)d_in[6];
    const float* slf_wk  = (const float*)d_in[7];
    const float* slf_wv  = (const float*)d_in[8];
    const float* slf_pw  = (const float*)d_in[9];
    const float* slf_pb  = (const float*)d_in[10];
    const float* slf_g   = (const float*)d_in[11];
    const float* slf_b   = (const float*)d_in[12];
    const float* enc_wq  = (const float*)d_in[13];
    const float* enc_wk  = (const float*)d_in[14];
    const float* enc_wv  = (const float*)d_in[15];
    const float* enc_pw  = (const float*)d_in[16];
    const float* enc_pb  = (const float*)d_in[17];
    const float* enc_g   = (const float*)d_in[18];
    const float* enc_b   = (const float*)d_in[19];
    const float* ffn_w1  = (const float*)d_in[20];
    const float* ffn_b1  = (const float*)d_in[21];
    const float* ffn_w2  = (const float*)d_in[22];
    const float* ffn_b2  = (const float*)d_in[23];
    const float* ffn_g   = (const float*)d_in[24];
    const float* ffn_b   = (const float*)d_in[25];

    float *xp, *yp;
    __half *qkvh, *xh, *eh, *aoh, *hh, *wb;
    cudaGetSymbolAddress((void**)&xp,   g_x);
    cudaGetSymbolAddress((void**)&yp,   g_y);
    cudaGetSymbolAddress((void**)&qkvh, g_qkvh);
    cudaGetSymbolAddress((void**)&xh,   g_xh);
    cudaGetSymbolAddress((void**)&eh,   g_eh);
    cudaGetSymbolAddress((void**)&aoh,  g_aoh);
    cudaGetSymbolAddress((void**)&hh,   g_hh);
    cudaGetSymbolAddress((void**)&wb,   g_wb);

    cudaFuncSetAttribute(attn_mma_k, cudaFuncAttributeMaxDynamicSharedMemorySize, ATTN2_SMEM);
    cudaFuncSetAttribute(gemm_mma_k, cudaFuncAttributeMaxDynamicSharedMemorySize, GM_SMEM);

    const int full = (out_size >= (int)FULL_OUT) ? 1 : 0;
    float* out_f = (float*)d_out;
    float* probs_slf = out_f + SLF_OFF;
    float* probs_enc = out_f + ENC_OFF;

    __half* qh = qkvh;
    __half* kh = qkvh + 2097152;
    __half* vh = qkvh + 4194304;

    embed_k<<<NTOK, 128>>>(tgt_seq, tgt_pos, tgt_emb, pos_emb, xp, xh);
    conv_h_k<<<(NTOK * DMOD) / 256, 256>>>(enc_out, eh, NTOK * DMOD);

    // ---- batched weight prep: 4 launches ----
    {
        P6 srcs;
        srcs.p[0] = slf_wq; srcs.p[1] = slf_wk; srcs.p[2] = slf_wv;
        srcs.p[3] = enc_wq; srcs.p[4] = enc_wk; srcs.p[5] = enc_wv;
        qkv_repack_all<<<dim3(64, 6, 6), 256>>>(srcs, wb);
        pw_repack_all<<<dim3(16, 16, 12), dim3(32, 8)>>>(slf_pw, enc_pw, wb);
        ffn_repack_all<<<dim3(64, 16, 6), dim3(32, 8)>>>(ffn_w1, wb, DMOD, DFF, WOFF_W1);
        ffn_repack_all<<<dim3(16, 64, 6), dim3(32, 8)>>>(ffn_w2, wb, DFF, DMOD, WOFF_W2);
    }

    dim3 gAttn(8, NHB);

    for (int l = 0; l < NL; l++) {
        size_t LB = (size_t)l * WL_SIZE;

        // ---- self attention: fused QKV (N=1536) ----
        gemm_mma_k<<<dim3(12, 32), 128, GM_SMEM>>>(xh, wb + LB + WOFF_SQ,
            nullptr, nullptr, qkvh, NTOK, 1536, DMOD, 3);
        attn_mma_k<<<gAttn, 256, ATTN2_SMEM>>>(qh, kh, vh, tgt_seq,
            probs_slf + (size_t)l * ATT_PER_L, aoh, 1, full);
        gemm_mma_k<<<dim3(4, 32), 128, GM_SMEM>>>(aoh, wb + LB + WOFF_SPW,
            slf_pb + (size_t)l * DMOD, yp, nullptr, NTOK, DMOD, DMOD, 1);
        ln_k<<<NTOK, 128>>>(yp, xp, slf_g + (size_t)l * DMOD, slf_b + (size_t)l * DMOD,
                            xp, xh);

        // ---- cross attention: Q from x (N=512), fused KV from enc (N=1024) ----
        gemm_mma_k<<<dim3(4, 32), 128, GM_SMEM>>>(xh, wb + LB + WOFF_EQ,
            nullptr, nullptr, qkvh, NTOK, DMOD, DMOD, 3);
        gemm_mma_k<<<dim3(8, 32), 128, GM_SMEM>>>(eh, wb + LB + WOFF_EK,
            nullptr, nullptr, qkvh + 2097152, NTOK, 1024, DMOD, 3);
        attn_mma_k<<<gAttn, 256, ATTN2_SMEM>>>(qh, kh, vh, src_seq,
            probs_enc + (size_t)l * ATT_PER_L, aoh, 0, full);
        gemm_mma_k<<<dim3(4, 32), 128, GM_SMEM>>>(aoh, wb + LB + WOFF_EPW,
            enc_pb + (size_t)l * DMOD, yp, nullptr, NTOK, DMOD, DMOD, 1);
        ln_k<<<NTOK, 128>>>(yp, xp, enc_g + (size_t)l * DMOD, enc_b + (size_t)l * DMOD,
                            xp, xh);

        // ---- FFN ----
        gemm_mma_k<<<dim3(16, 32), 128, GM_SMEM>>>(xh, wb + LB + WOFF_W1,
            ffn_b1 + (size_t)l * DFF, nullptr, hh, NTOK, DFF, DMOD, 2);
        gemm_mma_k<<<dim3(4, 32), 128, GM_SMEM>>>(hh, wb + LB + WOFF_W2,
            ffn_b2 + (size_t)l * DMOD, yp, nullptr, NTOK, DMOD, DFF, 1);
        ln_k<<<NTOK, 128>>>(yp, xp, ffn_g + (size_t)l * DMOD, ffn_b + (size_t)l * DMOD,
                            xp, xh);
    }

    size_t copy_elems = (size_t)out_size < (size_t)X_ELEMS ? (size_t)out_size : (size_t)X_ELEMS;
    cudaMemcpyAsync(d_out, xp, copy_elems * sizeof(float), cudaMemcpyDeviceToDevice);
}

// round 16
// speedup vs baseline: 2.9673x; 1.0097x over previous
#include <cuda_runtime.h>
#include <cuda_fp16.h>
#include <cstdint>

// Problem constants
#define NL   6
#define NH   8
#define DMOD 512
#define DKV  64
#define DFF  2048
#define NB   8
#define SEQ  512
#define NTOK 4096          // NB*SEQ
#define NHB  64            // NH*NB

#define X_ELEMS   (NTOK*DMOD)                 // 2,097,152
#define ATT_PER_L ((size_t)NHB*SEQ*SEQ)       // 16,777,216
#define SLF_OFF   ((size_t)X_ELEMS)
#define ENC_OFF   (SLF_OFF + (size_t)NL*ATT_PER_L)
#define FULL_OUT  (ENC_OFF + (size_t)NL*ATT_PER_L)   // 203,423,744

// per-layer fp16 weight bank layout (element offsets)
#define WOFF_SQ   0
#define WOFF_SK   262144
#define WOFF_SV   524288
#define WOFF_SPW  786432
#define WOFF_EQ   1048576
#define WOFF_EK   1310720
#define WOFF_EV   1572864
#define WOFF_EPW  1835008
#define WOFF_W1   2097152
#define WOFF_W2   3145728
#define WL_SIZE   4194304

// ---------------- scratch (no allocations allowed) ----------------
__device__ float g_x  [NTOK*DMOD];
__device__ float g_y  [NTOK*DMOD];
__device__ __half g_qkvh[3*NHB*SEQ*DKV];   // q|k|v fp16, head-major [hb][t][e]
__device__ __half g_xh [NTOK*DMOD];
__device__ __half g_eh [NTOK*DMOD];
__device__ __half g_aoh[NTOK*DMOD];
__device__ __half g_hh [NTOK*DFF];
__device__ __half g_wb [(size_t)NL*WL_SIZE];

struct P6 { const float* p[6]; };

// ---------------- helpers (baseline PTX only: sm_80-class) ----------------
__device__ __forceinline__ uint32_t smem_u32(const void* p) {
    uint32_t a;
    asm("{ .reg .u64 t; cvta.to.shared.u64 t, %1; cvt.u32.u64 %0, t; }" : "=r"(a) : "l"(p));
    return a;
}
__device__ __forceinline__ void cp16(uint32_t saddr, const void* g) {
    asm volatile("cp.async.cg.shared.global [%0], [%1], 16;" :: "r"(saddr), "l"(g));
}
#define CP_COMMIT() asm volatile("cp.async.commit_group;" ::: "memory")
#define CP_WAIT1()  asm volatile("cp.async.wait_group 1;" ::: "memory")
#define CP_WAIT0()  asm volatile("cp.async.wait_group 0;" ::: "memory")

__device__ __forceinline__ void ldsm_x4(uint32_t* r, uint32_t addr) {
    asm volatile("ldmatrix.sync.aligned.m8n8.x4.shared.b16 {%0,%1,%2,%3}, [%4];"
                 : "=r"(r[0]), "=r"(r[1]), "=r"(r[2]), "=r"(r[3]) : "r"(addr));
}
__device__ __forceinline__ void ldsm_x4_t(uint32_t* r, uint32_t addr) {
    asm volatile("ldmatrix.sync.aligned.m8n8.x4.trans.shared.b16 {%0,%1,%2,%3}, [%4];"
                 : "=r"(r[0]), "=r"(r[1]), "=r"(r[2]), "=r"(r[3]) : "r"(addr));
}
__device__ __forceinline__ void mma16816(float* d, const uint32_t* a, const uint32_t* b) {
    asm volatile("mma.sync.aligned.m16n8k16.row.col.f32.f16.f16.f32 "
                 "{%0,%1,%2,%3}, {%4,%5,%6,%7}, {%8,%9}, {%0,%1,%2,%3};"
                 : "+f"(d[0]), "+f"(d[1]), "+f"(d[2]), "+f"(d[3])
                 : "r"(a[0]), "r"(a[1]), "r"(a[2]), "r"(a[3]), "r"(b[0]), "r"(b[1]));
}

__device__ __forceinline__ __half2 pack2(float a, float b) {
    return __floats2half2_rn(a, b);
}

// ---------------- embedding (fp32 x + fp16) ----------------
__global__ void embed_k(const int* __restrict__ seq, const int* __restrict__ pos,
                        const float* __restrict__ wemb, const float* __restrict__ pemb,
                        float* __restrict__ x, __half* __restrict__ xh) {
    int n = blockIdx.x;
    int s = seq[n], p = pos[n];
    const float* we = wemb + (size_t)s * DMOD;
    const float* pe = pemb + (size_t)p * DMOD;
    for (int c = threadIdx.x; c < DMOD; c += blockDim.x) {
        float v = we[c] + pe[c];
        x[(size_t)n * DMOD + c] = v;
        xh[(size_t)n * DMOD + c] = __float2half(v);
    }
}

// ---------------- fp32 -> fp16 (enc_output) ----------------
__global__ void conv_h_k(const float* __restrict__ src, __half* __restrict__ dst, int n) {
    int i = blockIdx.x * blockDim.x + threadIdx.x;
    if (i < n) dst[i] = __float2half(src[i]);
}

// ---------------- batched qkv weight repack (all 6 tensors x 6 layers) ----------------
__global__ void qkv_repack_all(P6 srcs, __half* __restrict__ d_b) {
    __shared__ float t[64][65];
    const int woff[6] = {WOFF_SQ, WOFF_SK, WOFF_SV, WOFF_EQ, WOFF_EK, WOFF_EV};
    int ti = blockIdx.y, l = blockIdx.z;
    const float* src = srcs.p[ti] + (size_t)l * (NH * DMOD * DKV);
    __half* dst = d_b + (size_t)l * WL_SIZE + woff[ti];

    int h = blockIdx.x >> 3, dt = blockIdx.x & 7;
    int d0 = dt * 64;
    int tid = threadIdx.x;
    for (int i = tid; i < 4096; i += 256) {
        int d = i >> 6, e = i & 63;
        t[e][d] = src[h * (DMOD * DKV) + (d0 + d) * DKV + e];
    }
    __syncthreads();
    for (int i = tid; i < 4096; i += 256) {
        int e = i >> 6, d = i & 63;
        dst[(size_t)(h * 64 + e) * DMOD + d0 + d] = __float2half(t[e][d]);
    }
}

// ---------------- batched projection-weight transpose ----------------
__global__ void pw_repack_all(const float* __restrict__ slf_pw, const float* __restrict__ enc_pw,
                              __half* __restrict__ d_b) {
    __shared__ float t[32][33];
    int z = blockIdx.z, l = z >> 1, te = z & 1;
    const float* src = (te ? enc_pw : slf_pw) + (size_t)l * DMOD * DMOD;
    __half* dst = d_b + (size_t)l * WL_SIZE + (te ? WOFF_EPW : WOFF_SPW);

    int c0 = blockIdx.x * 32, r0 = blockIdx.y * 32;
    int x = threadIdx.x, y = threadIdx.y;        // 32 x 8
    for (int yy = y; yy < 32; yy += 8)
        t[yy][x] = src[(size_t)(r0 + yy) * DMOD + c0 + x];
    __syncthreads();
    for (int yy = y; yy < 32; yy += 8)
        dst[(size_t)(c0 + yy) * DMOD + r0 + x] = __float2half(t[x][yy]);
}

// ---------------- batched FFN weight transpose: [R,C] -> [C,R] ----------------
__global__ void ffn_repack_all(const float* __restrict__ w, __half* __restrict__ d_b,
                               int R, int C, int woff) {
    __shared__ float t[32][33];
    int l = blockIdx.z;
    const float* src = w + (size_t)l * R * C;
    __half* dst = d_b + (size_t)l * WL_SIZE + woff;

    int c0 = blockIdx.x * 32, r0 = blockIdx.y * 32;
    int x = threadIdx.x, y = threadIdx.y;        // 32 x 8
    for (int yy = y; yy < 32; yy += 8)
        t[yy][x] = src[(size_t)(r0 + yy) * C + c0 + x];
    __syncthreads();
    for (int yy = y; yy < 32; yy += 8)
        dst[(size_t)(c0 + yy) * R + r0 + x] = __float2half(t[x][yy]);
}

// ---------------- mma.sync fp16 GEMM: C[M,N] = A[M,K] @ B[N,K]^T ----------------
// Single-pass fp16. 4 warps, warp tile 64x64, K-chunk 64, 2-stage double buffer.
// mode 1: +bias -> fp32 Cf;  mode 2: +bias,relu -> fp16 Ch;  mode 3: qkv scatter -> fp16 Ch.
#define GM_PITCH 72                  // fp16 elems per smem row (144B, conflict-free ldmatrix)
#define GM_TILEB (128*GM_PITCH*2)    // 18432 B per 128x64 tile
#define GM_STAGE (2*GM_TILEB)        // A|B = 36864 B
#define GM_SMEM  (2*GM_STAGE)        // 73728 B double buffered

__global__ __launch_bounds__(128, 1) void gemm_mma_k(
    const __half* __restrict__ A, const __half* __restrict__ B,
    const float* __restrict__ bias,
    float* __restrict__ Cf, __half* __restrict__ Ch,
    int M, int N, int K, int mode)
{
    extern __shared__ __align__(16) char smem[];
    uint32_t sb = smem_u32(smem);
    const int tid = threadIdx.x, lane = tid & 31, w = tid >> 5;
    const int wm = w >> 1, wn = w & 1;          // warp grid 2 x 2 -> 64 x 64 tiles
    const int n0 = blockIdx.x * 128, m0 = blockIdx.y * 128;

    const __half* srcs[2] = { A + (size_t)m0 * K, B + (size_t)n0 * K };

    const int lrow = tid >> 3, lc8 = (tid & 7) * 8;

    auto load_chunk = [&](int kc, int st) {
        const int k0 = kc * 64;
        uint32_t stb = sb + st * GM_STAGE;
#pragma unroll
        for (int t = 0; t < 2; t++) {
            uint32_t tb = stb + t * GM_TILEB;
            const __half* src = srcs[t] + k0 + lc8;
#pragma unroll
            for (int j = 0; j < 8; j++) {
                int r = lrow + j * 16;
                cp16(tb + (r * GM_PITCH + lc8) * 2, src + (size_t)r * K);
            }
        }
    };

    float acc[4][8][4];
#pragma unroll
    for (int a = 0; a < 4; a++)
#pragma unroll
        for (int b = 0; b < 8; b++)
#pragma unroll
            for (int c = 0; c < 4; c++) acc[a][b][c] = 0.f;

    const int nch = K >> 6;
    load_chunk(0, 0); CP_COMMIT();

    const uint32_t a_off = ((wm * 64 + (lane & 15)) * GM_PITCH + ((lane >> 4) << 3)) * 2;
    const int b_lrow = (lane & 7) + ((lane & 16) ? 8 : 0);
    const int b_lcol = ((lane & 8) ? 8 : 0);

    for (int kc = 0; kc < nch; kc++) {
        if (kc + 1 < nch) { load_chunk(kc + 1, (kc + 1) & 1); CP_COMMIT(); CP_WAIT1(); }
        else { CP_WAIT0(); }
        __syncthreads();

        uint32_t stb = sb + (kc & 1) * GM_STAGE;
#pragma unroll
        for (int ks = 0; ks < 4; ks++) {
            const uint32_t kso = ks * 32;   // 16 elems * 2B
            uint32_t af[4][4];
#pragma unroll
            for (int mi = 0; mi < 4; mi++) {
                uint32_t off = a_off + mi * 16 * GM_PITCH * 2 + kso;
                ldsm_x4(af[mi], stb + off);
            }
#pragma unroll
            for (int ng = 0; ng < 2; ng++) {
                uint32_t bf[2][4];
#pragma unroll
                for (int np = 0; np < 2; np++) {
                    uint32_t off = ((wn * 64 + ng * 32 + np * 16 + b_lrow) * GM_PITCH
                                    + b_lcol) * 2 + kso;
                    ldsm_x4(bf[np], stb + GM_TILEB + off);
                }
#pragma unroll
                for (int mi = 0; mi < 4; mi++)
#pragma unroll
                    for (int nt = 0; nt < 4; nt++)
                        mma16816(acc[mi][ng * 4 + nt], af[mi], &bf[nt >> 1][(nt & 1) * 2]);
            }
        }
        __syncthreads();
    }

    // epilogue
#pragma unroll
    for (int mi = 0; mi < 4; mi++) {
        int r0 = m0 + wm * 64 + mi * 16 + (lane >> 2);
#pragma unroll
        for (int nj = 0; nj < 8; nj++) {
            int col = n0 + wn * 64 + nj * 8 + (lane & 3) * 2;
            float c0 = acc[mi][nj][0], c1 = acc[mi][nj][1];
            float c2 = acc[mi][nj][2], c3 = acc[mi][nj][3];
            if (mode == 3) {
                int m = col >> 9, hh_ = (col >> 6) & 7, e = col & 63;
#pragma unroll
                for (int rr = 0; rr < 2; rr++) {
                    int row = r0 + rr * 8;
                    int b_ = row >> 9, t = row & 511;
                    size_t off = (size_t)m * 2097152 +
                                 (((size_t)(hh_ * NB + b_) * SEQ + t) * DKV + e);
                    *(__half2*)(Ch + off) = pack2(rr ? c2 : c0, rr ? c3 : c1);
                }
            } else if (mode == 1) {
                float2 bv = *(const float2*)(bias + col);
                float2 v0; v0.x = c0 + bv.x; v0.y = c1 + bv.y;
                float2 v1; v1.x = c2 + bv.x; v1.y = c3 + bv.y;
                *(float2*)(Cf + (size_t)r0 * N + col)       = v0;
                *(float2*)(Cf + (size_t)(r0 + 8) * N + col) = v1;
            } else {
                float2 bv = *(const float2*)(bias + col);
                float p0 = fmaxf(c0 + bv.x, 0.f), p1 = fmaxf(c1 + bv.y, 0.f);
                float p2 = fmaxf(c2 + bv.x, 0.f), p3 = fmaxf(c3 + bv.y, 0.f);
                *(__half2*)(Ch + (size_t)r0 * N + col)       = pack2(p0, p1);
                *(__half2*)(Ch + (size_t)(r0 + 8) * N + col) = pack2(p2, p3);
            }
        }
    }
}

// ---------------- MMA attention (single-pass fp16, causal tile skip, deferred norm) ----------------
// Block = (qt, hb): 64 queries x 512 keys. 8 warps: wm = w&3 (16 rows), wn = w>>2 (half).
#define PT 72                      // fp16 pitch (144 B)
#define SC_PITCH 520
#define SC_OFF   0                 // fp32 [64][520] = 133120 B
#define Q_OFF    133120            // fp16 [64][72] = 9216 B
#define KV_OFF   (Q_OFF + 9216)    // 2 stages x 9216
#define KV_STAGE 9216
#define PT_OFF   (KV_OFF + 2*KV_STAGE)
#define BIAS_OFF (PT_OFF + 9216)   // fp32 [512] bias + fp32 [64] inv
#define ATTN2_SMEM (BIAS_OFF + 2048 + 256)   // 172288 B

__global__ __launch_bounds__(256, 1) void attn_mma_k(
    const __half* __restrict__ Qh, const __half* __restrict__ Kh, const __half* __restrict__ Vh,
    const int* __restrict__ seq, float* __restrict__ probs,
    __half* __restrict__ Oh, int causal, int writeProbs)
{
    extern __shared__ __align__(16) char sm2[];
    uint32_t sbase = smem_u32(sm2);
    float* Sc = (float*)(sm2 + SC_OFF);
    float* biasS = (float*)(sm2 + BIAS_OFF);
    float* invS = biasS + 512;
    const int hb = blockIdx.y, qt = blockIdx.x;
    const int h = hb >> 3, b = hb & 7;
    const int tid = threadIdx.x, lane = tid & 31, w = tid >> 5;
    const int wm = w & 3, wn = w >> 2;
    const float scale = 0.044194173824159216f;   // 1/sqrt(512)

    const int nst = causal ? (qt + 1) : 8;       // active 64-key tiles
    const int bound = nst * 64;                  // active key columns

    for (int i = tid; i < 512; i += 256)
        biasS[i] = (seq[b * SEQ + i] == 0) ? -1e30f : 0.f;

    // Q tile -> smem
    {
        int row = tid >> 2, s0 = (tid & 3) * 16;
        size_t gq = ((size_t)hb * SEQ + qt * 64 + row) * DKV + s0;
        *(uint4*)(sm2 + Q_OFF + (row * PT + s0) * 2)     = *(const uint4*)(Qh + gq);
        *(uint4*)(sm2 + Q_OFF + (row * PT + s0 + 8) * 2) = *(const uint4*)(Qh + gq + 8);
    }

    auto load_kv = [&](const __half* Src, int st, int stage) {
        uint32_t sbst = sbase + KV_OFF + stage * KV_STAGE;
        size_t gbase = ((size_t)hb * SEQ + st * 64) * DKV;
#pragma unroll
        for (int j = 0; j < 2; j++) {
            int seg = tid + j * 256;
            int row = seg >> 3, c = (seg & 7) * 8;
            cp16(sbst + (row * PT + c) * 2, Src + gbase + row * DKV + c);
        }
    };

    load_kv(Kh, 0, 0); CP_COMMIT();
    __syncthreads();

    // resident Q fragments
    uint32_t qf[4][4];
#pragma unroll
    for (int ks = 0; ks < 4; ks++) {
        uint32_t addr = sbase + Q_OFF +
            ((wm * 16 + (lane & 15)) * PT + ks * 16 + ((lane >> 4) << 3)) * 2;
        ldsm_x4(qf[ks], addr);
    }

    // ---- score phase (active tiles only) ----
    for (int st = 0; st < nst; st++) {
        __syncthreads();
        if (st + 1 < nst) { load_kv(Kh, st + 1, (st + 1) & 1); CP_COMMIT(); CP_WAIT1(); }
        else { CP_WAIT0(); }
        __syncthreads();

        uint32_t kb = sbase + KV_OFF + (st & 1) * KV_STAGE;
        float acc[4][4];
#pragma unroll
        for (int i = 0; i < 4; i++)
#pragma unroll
            for (int j = 0; j < 4; j++) acc[i][j] = 0.f;

#pragma unroll
        for (int ks = 0; ks < 4; ks++) {
            uint32_t bh[2][4];
#pragma unroll
            for (int np = 0; np < 2; np++) {
                uint32_t addr = kb + ((wn * 32 + np * 16 + (lane & 7) + ((lane & 16) ? 8 : 0)) * PT
                                      + ks * 16 + ((lane & 8) ? 8 : 0)) * 2;
                ldsm_x4(bh[np], addr);
            }
#pragma unroll
            for (int nt = 0; nt < 4; nt++)
                mma16816(acc[nt], qf[ks], &bh[nt >> 1][(nt & 1) * 2]);
        }

        int r0 = wm * 16 + (lane >> 2);
#pragma unroll
        for (int nt = 0; nt < 4; nt++) {
            int col = st * 64 + wn * 32 + nt * 8 + (lane & 3) * 2;
            float b0 = biasS[col], b1 = biasS[col + 1];
#pragma unroll
            for (int rr = 0; rr < 2; rr++) {
                int row = r0 + rr * 8;
                int tg = qt * 64 + row;
                float v0 = acc[nt][rr * 2 + 0] * scale + b0;
                float v1 = acc[nt][rr * 2 + 1] * scale + b1;
                if (causal) {
                    if (col > tg)     v0 = -1e30f;
                    if (col + 1 > tg) v1 = -1e30f;
                }
                float2 vv; vv.x = v0; vv.y = v1;
                *(float2*)(Sc + row * SC_PITCH + col) = vv;
            }
        }
    }
    __syncthreads();

    // ---- softmax over active cols (unnormalized e kept in smem; inv saved) ----
    {
        for (int r = 0; r < 8; r++) {
            int q = w * 8 + r;
            float* row = Sc + q * SC_PITCH;
            float mx = -3.0e38f;
            for (int c = lane; c < bound; c += 32) mx = fmaxf(mx, row[c]);
#pragma unroll
            for (int o = 16; o; o >>= 1) mx = fmaxf(mx, __shfl_xor_sync(0xffffffffu, mx, o));
            float sum = 0.f;
            for (int c = lane; c < bound; c += 32) {
                float e = __expf(row[c] - mx);
                row[c] = e;
                sum += e;
            }
#pragma unroll
            for (int o = 16; o; o >>= 1) sum += __shfl_xor_sync(0xffffffffu, sum, o);
            float inv = 1.f / sum;
            if (lane == 0) invS[q] = inv;
            float* prow = probs + ((size_t)hb * SEQ + qt * 64 + q) * SEQ;
            if (writeProbs) {
                for (int c = lane; c < bound; c += 32) prow[c] = row[c] * inv;
                for (int c = bound + lane; c < 512; c += 32) prow[c] = 0.f;
            }
        }
    }

    // ---- P @ V phase (unnormalized; scale at epilogue) ----
    load_kv(Vh, 0, 0); CP_COMMIT();
    float oacc[4][4];
#pragma unroll
    for (int i = 0; i < 4; i++)
#pragma unroll
        for (int j = 0; j < 4; j++) oacc[i][j] = 0.f;

    for (int st = 0; st < nst; st++) {
        __syncthreads();
        if (st + 1 < nst) { load_kv(Vh, st + 1, (st + 1) & 1); CP_COMMIT(); CP_WAIT1(); }
        else { CP_WAIT0(); }

        // convert P tile st -> fp16
        {
            int row = tid >> 2, cb = (tid & 3) * 16;
            const float* srow = Sc + row * SC_PITCH + st * 64 + cb;
            __half* ph = (__half*)(sm2 + PT_OFF) + row * PT + cb;
#pragma unroll
            for (int j2 = 0; j2 < 16; j2 += 4) {
                float4 p4 = *(const float4*)(srow + j2);
                *(__half2*)(ph + j2)     = pack2(p4.x, p4.y);
                *(__half2*)(ph + j2 + 2) = pack2(p4.z, p4.w);
            }
        }
        __syncthreads();

        uint32_t vb = sbase + KV_OFF + (st & 1) * KV_STAGE;
#pragma unroll
        for (int ks = 0; ks < 4; ks++) {
            uint32_t af[4], vbf[2][4];
            uint32_t aaddr = sbase + PT_OFF +
                ((wm * 16 + (lane & 15)) * PT + ks * 16 + ((lane >> 4) << 3)) * 2;
            ldsm_x4(af, aaddr);
#pragma unroll
            for (int np = 0; np < 2; np++) {
                uint32_t addr = vb + ((ks * 16 + (lane & 7) + ((lane & 8) ? 8 : 0)) * PT
                                      + wn * 32 + np * 16 + ((lane & 16) ? 8 : 0)) * 2;
                ldsm_x4_t(vbf[np], addr);
            }
#pragma unroll
            for (int nt = 0; nt < 4; nt++)
                mma16816(oacc[nt], af, &vbf[nt >> 1][(nt & 1) * 2]);
        }
    }

    // O epilogue -> fp16 (scale by per-row inv), layout [b*SEQ+t][h*64+e]
    int r0 = wm * 16 + (lane >> 2);
    float inv0 = invS[r0], inv1 = invS[r0 + 8];
#pragma unroll
    for (int nt = 0; nt < 4; nt++) {
        int gc = h * DKV + wn * 32 + nt * 8 + (lane & 3) * 2;
#pragma unroll
        for (int rr = 0; rr < 2; rr++) {
            int row = b * SEQ + qt * 64 + r0 + rr * 8;
            float iv = rr ? inv1 : inv0;
            *(__half2*)(Oh + (size_t)row * DMOD + gc) =
                pack2(oacc[nt][rr * 2 + 0] * iv, oacc[nt][rr * 2 + 1] * iv);
        }
    }
}

// ---------------- layernorm(y + res) -> fp32 out + fp16 ----------------
__global__ __launch_bounds__(128) void ln_k(
    const float* __restrict__ y, const float* __restrict__ res,
    const float* __restrict__ g, const float* __restrict__ b,
    float* __restrict__ out, __half* __restrict__ oh)
{
    __shared__ float red[8];
    int n = blockIdx.x, tid = threadIdx.x;
    int c = tid * 4;
    float4 yv = *(const float4*)(y   + (size_t)n * DMOD + c);
    float4 rv = *(const float4*)(res + (size_t)n * DMOD + c);
    float v0 = yv.x + rv.x, v1 = yv.y + rv.y, v2 = yv.z + rv.z, v3 = yv.w + rv.w;

    float s = v0 + v1 + v2 + v3;
    int lane = tid & 31, warp = tid >> 5;
#pragma unroll
    for (int o = 16; o; o >>= 1) s += __shfl_xor_sync(0xffffffffu, s, o);
    if (lane == 0) red[warp] = s;
    __syncthreads();
    float mu = (red[0] + red[1] + red[2] + red[3]) * (1.f / DMOD);

    float d0 = v0 - mu, d1 = v1 - mu, d2 = v2 - mu, d3 = v3 - mu;
    float ss = d0 * d0 + d1 * d1 + d2 * d2 + d3 * d3;
#pragma unroll
    for (int o = 16; o; o >>= 1) ss += __shfl_xor_sync(0xffffffffu, ss, o);
    if (lane == 0) red[4 + warp] = ss;
    __syncthreads();
    float var = (red[4] + red[5] + red[6] + red[7]) * (1.f / DMOD);
    float is = rsqrtf(var + 1e-5f);

    float4 gv = *(const float4*)(g + c);
    float4 bv = *(const float4*)(b + c);
    float4 ov;
    ov.x = d0 * is * gv.x + bv.x;
    ov.y = d1 * is * gv.y + bv.y;
    ov.z = d2 * is * gv.z + bv.z;
    ov.w = d3 * is * gv.w + bv.w;
    *(float4*)(out + (size_t)n * DMOD + c) = ov;
    *(__half2*)(oh + (size_t)n * DMOD + c)     = pack2(ov.x, ov.y);
    *(__half2*)(oh + (size_t)n * DMOD + c + 2) = pack2(ov.z, ov.w);
}

// ---------------- host ----------------
extern "C" void kernel_launch(void* const* d_in, const int* in_sizes, int n_in,
                              void* d_out, int out_size)
{
    const int*   tgt_seq = (const int*)d_in[0];
    const int*   tgt_pos = (const int*)d_in[1];
    const int*   src_seq = (const int*)d_in[2];
    const float* enc_out = (const float*)d_in[3];
    const float* tgt_emb = (const float*)d_in[4];
    const float* pos_emb = (const float*)d_in[5];
    const float* slf_wq  = (const float*)d_in[6];
    const float* slf_wk  = (const float*)d_in[7];
    const float* slf_wv  = (const float*)d_in[8];
    const float* slf_pw  = (const float*)d_in[9];
    const float* slf_pb  = (const float*)d_in[10];
    const float* slf_g   = (const float*)d_in[11];
    const float* slf_b   = (const float*)d_in[12];
    const float* enc_wq  = (const float*)d_in[13];
    const float* enc_wk  = (const float*)d_in[14];
    const float* enc_wv  = (const float*)d_in[15];
    const float* enc_pw  = (const float*)d_in[16];
    const float* enc_pb  = (const float*)d_in[17];
    const float* enc_g   = (const float*)d_in[18];
    const float* enc_b   = (const float*)d_in[19];
    const float* ffn_w1  = (const float*)d_in[20];
    const float* ffn_b1  = (const float*)d_in[21];
    const float* ffn_w2  = (const float*)d_in[22];
    const float* ffn_b2  = (const float*)d_in[23];
    const float* ffn_g   = (const float*)d_in[24];
    const float* ffn_b   = (const float*)d_in[25];

    float *xp, *yp;
    __half *qkvh, *xh, *eh, *aoh, *hh, *wb;
    cudaGetSymbolAddress((void**)&xp,   g_x);
    cudaGetSymbolAddress((void**)&yp,   g_y);
    cudaGetSymbolAddress((void**)&qkvh, g_qkvh);
    cudaGetSymbolAddress((void**)&xh,   g_xh);
    cudaGetSymbolAddress((void**)&eh,   g_eh);
    cudaGetSymbolAddress((void**)&aoh,  g_aoh);
    cudaGetSymbolAddress((void**)&hh,   g_hh);
    cudaGetSymbolAddress((void**)&wb,   g_wb);

    cudaFuncSetAttribute(attn_mma_k, cudaFuncAttributeMaxDynamicSharedMemorySize, ATTN2_SMEM);
    cudaFuncSetAttribute(gemm_mma_k, cudaFuncAttributeMaxDynamicSharedMemorySize, GM_SMEM);

    const int full = (out_size >= (int)FULL_OUT) ? 1 : 0;
    float* out_f = (float*)d_out;
    float* probs_slf = out_f + SLF_OFF;
    float* probs_enc = out_f + ENC_OFF;

    __half* qh = qkvh;
    __half* kh = qkvh + 2097152;
    __half* vh = qkvh + 4194304;

    embed_k<<<NTOK, 128>>>(tgt_seq, tgt_pos, tgt_emb, pos_emb, xp, xh);
    conv_h_k<<<(NTOK * DMOD) / 256, 256>>>(enc_out, eh, NTOK * DMOD);

    // ---- batched weight prep: 4 launches ----
    {
        P6 srcs;
        srcs.p[0] = slf_wq; srcs.p[1] = slf_wk; srcs.p[2] = slf_wv;
        srcs.p[3] = enc_wq; srcs.p[4] = enc_wk; srcs.p[5] = enc_wv;
        qkv_repack_all<<<dim3(64, 6, 6), 256>>>(srcs, wb);
        pw_repack_all<<<dim3(16, 16, 12), dim3(32, 8)>>>(slf_pw, enc_pw, wb);
        ffn_repack_all<<<dim3(64, 16, 6), dim3(32, 8)>>>(ffn_w1, wb, DMOD, DFF, WOFF_W1);
        ffn_repack_all<<<dim3(16, 64, 6), dim3(32, 8)>>>(ffn_w2, wb, DFF, DMOD, WOFF_W2);
    }

    dim3 gAttn(8, NHB);

    for (int l = 0; l < NL; l++) {
        size_t LB = (size_t)l * WL_SIZE;

        // ---- self attention: fused QKV (N=1536) ----
        gemm_mma_k<<<dim3(12, 32), 128, GM_SMEM>>>(xh, wb + LB + WOFF_SQ,
            nullptr, nullptr, qkvh, NTOK, 1536, DMOD, 3);
        attn_mma_k<<<gAttn, 256, ATTN2_SMEM>>>(qh, kh, vh, tgt_seq,
            probs_slf + (size_t)l * ATT_PER_L, aoh, 1, full);
        gemm_mma_k<<<dim3(4, 32), 128, GM_SMEM>>>(aoh, wb + LB + WOFF_SPW,
            slf_pb + (size_t)l * DMOD, yp, nullptr, NTOK, DMOD, DMOD, 1);
        ln_k<<<NTOK, 128>>>(yp, xp, slf_g + (size_t)l * DMOD, slf_b + (size_t)l * DMOD,
                            xp, xh);

        // ---- cross attention: Q from x (N=512), fused KV from enc (N=1024) ----
        gemm_mma_k<<<dim3(4, 32), 128, GM_SMEM>>>(xh, wb + LB + WOFF_EQ,
            nullptr, nullptr, qkvh, NTOK, DMOD, DMOD, 3);
        gemm_mma_k<<<dim3(8, 32), 128, GM_SMEM>>>(eh, wb + LB + WOFF_EK,
            nullptr, nullptr, qkvh + 2097152, NTOK, 1024, DMOD, 3);
        attn_mma_k<<<gAttn, 256, ATTN2_SMEM>>>(qh, kh, vh, src_seq,
            probs_enc + (size_t)l * ATT_PER_L, aoh, 0, full);
        gemm_mma_k<<<dim3(4, 32), 128, GM_SMEM>>>(aoh, wb + LB + WOFF_EPW,
            enc_pb + (size_t)l * DMOD, yp, nullptr, NTOK, DMOD, DMOD, 1);
        ln_k<<<NTOK, 128>>>(yp, xp, enc_g + (size_t)l * DMOD, enc_b + (size_t)l * DMOD,
                            xp, xh);

        // ---- FFN ----
        gemm_mma_k<<<dim3(16, 32), 128, GM_SMEM>>>(xh, wb + LB + WOFF_W1,
            ffn_b1 + (size_t)l * DFF, nullptr, hh, NTOK, DFF, DMOD, 2);
        gemm_mma_k<<<dim3(4, 32), 128, GM_SMEM>>>(hh, wb + LB + WOFF_W2,
            ffn_b2 + (size_t)l * DMOD, yp, nullptr, NTOK, DMOD, DFF, 1);
        ln_k<<<NTOK, 128>>>(yp, xp, ffn_g + (size_t)l * DMOD, ffn_b + (size_t)l * DMOD,
                            xp, xh);
    }

    size_t copy_elems = (size_t)out_size < (size_t)X_ELEMS ? (size_t)out_size : (size_t)X_ELEMS;
    cudaMemcpyAsync(d_out, xp, copy_elems * sizeof(float), cudaMemcpyDeviceToDevice);
}

// round 17
// speedup vs baseline: 2.9914x; 1.0081x over previous
#include <cuda_runtime.h>
#include <cuda_fp16.h>
#include <cstdint>

// Problem constants
#define NL   6
#define NH   8
#define DMOD 512
#define DKV  64
#define DFF  2048
#define NB   8
#define SEQ  512
#define NTOK 4096          // NB*SEQ
#define NHB  64            // NH*NB

#define X_ELEMS   (NTOK*DMOD)                 // 2,097,152
#define ATT_PER_L ((size_t)NHB*SEQ*SEQ)       // 16,777,216
#define SLF_OFF   ((size_t)X_ELEMS)
#define ENC_OFF   (SLF_OFF + (size_t)NL*ATT_PER_L)
#define FULL_OUT  (ENC_OFF + (size_t)NL*ATT_PER_L)   // 203,423,744

// per-layer fp16 weight bank layout (element offsets)
#define WOFF_SQ   0
#define WOFF_SK   262144
#define WOFF_SV   524288
#define WOFF_SPW  786432
#define WOFF_EQ   1048576
#define WOFF_EK   1310720
#define WOFF_EV   1572864
#define WOFF_EPW  1835008
#define WOFF_W1   2097152
#define WOFF_W2   3145728
#define WL_SIZE   4194304

// ---------------- scratch (no allocations allowed) ----------------
__device__ float g_x  [NTOK*DMOD];
__device__ float g_y  [NTOK*DMOD];
__device__ __half g_qkvh[3*NHB*SEQ*DKV];   // q|k|v fp16, head-major [hb][t][e]
__device__ __half g_xh [NTOK*DMOD];
__device__ __half g_eh [NTOK*DMOD];
__device__ __half g_aoh[NTOK*DMOD];
__device__ __half g_hh [NTOK*DFF];
__device__ __half g_wb [(size_t)NL*WL_SIZE];

struct P6 { const float* p[6]; };

// ---------------- helpers (baseline PTX only: sm_80-class) ----------------
__device__ __forceinline__ uint32_t smem_u32(const void* p) {
    uint32_t a;
    asm("{ .reg .u64 t; cvta.to.shared.u64 t, %1; cvt.u32.u64 %0, t; }" : "=r"(a) : "l"(p));
    return a;
}
__device__ __forceinline__ void cp16(uint32_t saddr, const void* g) {
    asm volatile("cp.async.cg.shared.global [%0], [%1], 16;" :: "r"(saddr), "l"(g));
}
#define CP_COMMIT() asm volatile("cp.async.commit_group;" ::: "memory")
#define CP_WAIT2()  asm volatile("cp.async.wait_group 2;" ::: "memory")
#define CP_WAIT1()  asm volatile("cp.async.wait_group 1;" ::: "memory")
#define CP_WAIT0()  asm volatile("cp.async.wait_group 0;" ::: "memory")

__device__ __forceinline__ void ldsm_x4(uint32_t* r, uint32_t addr) {
    asm volatile("ldmatrix.sync.aligned.m8n8.x4.shared.b16 {%0,%1,%2,%3}, [%4];"
                 : "=r"(r[0]), "=r"(r[1]), "=r"(r[2]), "=r"(r[3]) : "r"(addr));
}
__device__ __forceinline__ void ldsm_x4_t(uint32_t* r, uint32_t addr) {
    asm volatile("ldmatrix.sync.aligned.m8n8.x4.trans.shared.b16 {%0,%1,%2,%3}, [%4];"
                 : "=r"(r[0]), "=r"(r[1]), "=r"(r[2]), "=r"(r[3]) : "r"(addr));
}
__device__ __forceinline__ void mma16816(float* d, const uint32_t* a, const uint32_t* b) {
    asm volatile("mma.sync.aligned.m16n8k16.row.col.f32.f16.f16.f32 "
                 "{%0,%1,%2,%3}, {%4,%5,%6,%7}, {%8,%9}, {%0,%1,%2,%3};"
                 : "+f"(d[0]), "+f"(d[1]), "+f"(d[2]), "+f"(d[3])
                 : "r"(a[0]), "r"(a[1]), "r"(a[2]), "r"(a[3]), "r"(b[0]), "r"(b[1]));
}

__device__ __forceinline__ __half2 pack2(float a, float b) {
    return __floats2half2_rn(a, b);
}

// ---------------- embedding (fp32 x + fp16) ----------------
__global__ void embed_k(const int* __restrict__ seq, const int* __restrict__ pos,
                        const float* __restrict__ wemb, const float* __restrict__ pemb,
                        float* __restrict__ x, __half* __restrict__ xh) {
    int n = blockIdx.x;
    int s = seq[n], p = pos[n];
    const float* we = wemb + (size_t)s * DMOD;
    const float* pe = pemb + (size_t)p * DMOD;
    for (int c = threadIdx.x; c < DMOD; c += blockDim.x) {
        float v = we[c] + pe[c];
        x[(size_t)n * DMOD + c] = v;
        xh[(size_t)n * DMOD + c] = __float2half(v);
    }
}

// ---------------- fp32 -> fp16 (enc_output) ----------------
__global__ void conv_h_k(const float* __restrict__ src, __half* __restrict__ dst, int n) {
    int i = blockIdx.x * blockDim.x + threadIdx.x;
    if (i < n) dst[i] = __float2half(src[i]);
}

// ---------------- batched qkv weight repack (all 6 tensors x 6 layers) ----------------
__global__ void qkv_repack_all(P6 srcs, __half* __restrict__ d_b) {
    __shared__ float t[64][65];
    const int woff[6] = {WOFF_SQ, WOFF_SK, WOFF_SV, WOFF_EQ, WOFF_EK, WOFF_EV};
    int ti = blockIdx.y, l = blockIdx.z;
    const float* src = srcs.p[ti] + (size_t)l * (NH * DMOD * DKV);
    __half* dst = d_b + (size_t)l * WL_SIZE + woff[ti];

    int h = blockIdx.x >> 3, dt = blockIdx.x & 7;
    int d0 = dt * 64;
    int tid = threadIdx.x;
    for (int i = tid; i < 4096; i += 256) {
        int d = i >> 6, e = i & 63;
        t[e][d] = src[h * (DMOD * DKV) + (d0 + d) * DKV + e];
    }
    __syncthreads();
    for (int i = tid; i < 4096; i += 256) {
        int e = i >> 6, d = i & 63;
        dst[(size_t)(h * 64 + e) * DMOD + d0 + d] = __float2half(t[e][d]);
    }
}

// ---------------- batched projection-weight transpose ----------------
__global__ void pw_repack_all(const float* __restrict__ slf_pw, const float* __restrict__ enc_pw,
                              __half* __restrict__ d_b) {
    __shared__ float t[32][33];
    int z = blockIdx.z, l = z >> 1, te = z & 1;
    const float* src = (te ? enc_pw : slf_pw) + (size_t)l * DMOD * DMOD;
    __half* dst = d_b + (size_t)l * WL_SIZE + (te ? WOFF_EPW : WOFF_SPW);

    int c0 = blockIdx.x * 32, r0 = blockIdx.y * 32;
    int x = threadIdx.x, y = threadIdx.y;        // 32 x 8
    for (int yy = y; yy < 32; yy += 8)
        t[yy][x] = src[(size_t)(r0 + yy) * DMOD + c0 + x];
    __syncthreads();
    for (int yy = y; yy < 32; yy += 8)
        dst[(size_t)(c0 + yy) * DMOD + r0 + x] = __float2half(t[x][yy]);
}

// ---------------- batched FFN weight transpose: [R,C] -> [C,R] ----------------
__global__ void ffn_repack_all(const float* __restrict__ w, __half* __restrict__ d_b,
                               int R, int C, int woff) {
    __shared__ float t[32][33];
    int l = blockIdx.z;
    const float* src = w + (size_t)l * R * C;
    __half* dst = d_b + (size_t)l * WL_SIZE + woff;

    int c0 = blockIdx.x * 32, r0 = blockIdx.y * 32;
    int x = threadIdx.x, y = threadIdx.y;        // 32 x 8
    for (int yy = y; yy < 32; yy += 8)
        t[yy][x] = src[(size_t)(r0 + yy) * C + c0 + x];
    __syncthreads();
    for (int yy = y; yy < 32; yy += 8)
        dst[(size_t)(c0 + yy) * R + r0 + x] = __float2half(t[x][yy]);
}

// ---------------- mma.sync fp16 GEMM: C[M,N] = A[M,K] @ B[N,K]^T ----------------
// Single-pass fp16, 3-stage cp.async pipeline. 4 warps, warp tile 64x64, K-chunk 64.
// A2: alternate A matrix for columns >= 512 (merged cross-attn Q|KV); pass A2=A otherwise.
// mode 1: +bias -> fp32 Cf;  mode 2: +bias,relu -> fp16 Ch;  mode 3: qkv scatter -> fp16 Ch.
#define GM_PITCH 72                  // fp16 elems per smem row (144B, conflict-free ldmatrix)
#define GM_TILEB (128*GM_PITCH*2)    // 18432 B per 128x64 tile
#define GM_STAGE (2*GM_TILEB)        // A|B = 36864 B
#define GM_SMEM  (3*GM_STAGE)        // 110592 B, 3-stage

__global__ __launch_bounds__(128, 1) void gemm_mma_k(
    const __half* __restrict__ A, const __half* __restrict__ A2,
    const __half* __restrict__ B,
    const float* __restrict__ bias,
    float* __restrict__ Cf, __half* __restrict__ Ch,
    int M, int N, int K, int mode)
{
    extern __shared__ __align__(16) char smem[];
    uint32_t sb = smem_u32(smem);
    const int tid = threadIdx.x, lane = tid & 31, w = tid >> 5;
    const int wm = w >> 1, wn = w & 1;          // warp grid 2 x 2 -> 64 x 64 tiles
    const int n0 = blockIdx.x * 128, m0 = blockIdx.y * 128;

    const __half* Abase = (n0 < 512) ? A : A2;
    const __half* srcs[2] = { Abase + (size_t)m0 * K, B + (size_t)n0 * K };

    const int lrow = tid >> 3, lc8 = (tid & 7) * 8;

    auto load_chunk = [&](int kc, int st) {
        const int k0 = kc * 64;
        uint32_t stb = sb + st * GM_STAGE;
#pragma unroll
        for (int t = 0; t < 2; t++) {
            uint32_t tb = stb + t * GM_TILEB;
            const __half* src = srcs[t] + k0 + lc8;
#pragma unroll
            for (int j = 0; j < 8; j++) {
                int r = lrow + j * 16;
                cp16(tb + (r * GM_PITCH + lc8) * 2, src + (size_t)r * K);
            }
        }
    };

    float acc[4][8][4];
#pragma unroll
    for (int a = 0; a < 4; a++)
#pragma unroll
        for (int b = 0; b < 8; b++)
#pragma unroll
            for (int c = 0; c < 4; c++) acc[a][b][c] = 0.f;

    const int nch = K >> 6;
    load_chunk(0, 0); CP_COMMIT();
    if (nch > 1) { load_chunk(1, 1); CP_COMMIT(); }

    const uint32_t a_off = ((wm * 64 + (lane & 15)) * GM_PITCH + ((lane >> 4) << 3)) * 2;
    const int b_lrow = (lane & 7) + ((lane & 16) ? 8 : 0);
    const int b_lcol = ((lane & 8) ? 8 : 0);

    int st3 = 0;           // kc % 3
    for (int kc = 0; kc < nch; kc++) {
        if (kc + 2 < nch) {
            int ns = st3 + 2; if (ns >= 3) ns -= 3;
            load_chunk(kc + 2, ns); CP_COMMIT(); CP_WAIT2();
        } else if (kc + 1 < nch) { CP_WAIT1(); }
        else { CP_WAIT0(); }
        __syncthreads();

        uint32_t stb = sb + st3 * GM_STAGE;
#pragma unroll
        for (int ks = 0; ks < 4; ks++) {
            const uint32_t kso = ks * 32;   // 16 elems * 2B
            uint32_t af[4][4];
#pragma unroll
            for (int mi = 0; mi < 4; mi++) {
                uint32_t off = a_off + mi * 16 * GM_PITCH * 2 + kso;
                ldsm_x4(af[mi], stb + off);
            }
#pragma unroll
            for (int ng = 0; ng < 2; ng++) {
                uint32_t bf[2][4];
#pragma unroll
                for (int np = 0; np < 2; np++) {
                    uint32_t off = ((wn * 64 + ng * 32 + np * 16 + b_lrow) * GM_PITCH
                                    + b_lcol) * 2 + kso;
                    ldsm_x4(bf[np], stb + GM_TILEB + off);
                }
#pragma unroll
                for (int mi = 0; mi < 4; mi++)
#pragma unroll
                    for (int nt = 0; nt < 4; nt++)
                        mma16816(acc[mi][ng * 4 + nt], af[mi], &bf[nt >> 1][(nt & 1) * 2]);
            }
        }
        __syncthreads();
        if (++st3 == 3) st3 = 0;
    }

    // epilogue
#pragma unroll
    for (int mi = 0; mi < 4; mi++) {
        int r0 = m0 + wm * 64 + mi * 16 + (lane >> 2);
#pragma unroll
        for (int nj = 0; nj < 8; nj++) {
            int col = n0 + wn * 64 + nj * 8 + (lane & 3) * 2;
            float c0 = acc[mi][nj][0], c1 = acc[mi][nj][1];
            float c2 = acc[mi][nj][2], c3 = acc[mi][nj][3];
            if (mode == 3) {
                int m = col >> 9, hh_ = (col >> 6) & 7, e = col & 63;
#pragma unroll
                for (int rr = 0; rr < 2; rr++) {
                    int row = r0 + rr * 8;
                    int b_ = row >> 9, t = row & 511;
                    size_t off = (size_t)m * 2097152 +
                                 (((size_t)(hh_ * NB + b_) * SEQ + t) * DKV + e);
                    *(__half2*)(Ch + off) = pack2(rr ? c2 : c0, rr ? c3 : c1);
                }
            } else if (mode == 1) {
                float2 bv = *(const float2*)(bias + col);
                float2 v0; v0.x = c0 + bv.x; v0.y = c1 + bv.y;
                float2 v1; v1.x = c2 + bv.x; v1.y = c3 + bv.y;
                *(float2*)(Cf + (size_t)r0 * N + col)       = v0;
                *(float2*)(Cf + (size_t)(r0 + 8) * N + col) = v1;
            } else {
                float2 bv = *(const float2*)(bias + col);
                float p0 = fmaxf(c0 + bv.x, 0.f), p1 = fmaxf(c1 + bv.y, 0.f);
                float p2 = fmaxf(c2 + bv.x, 0.f), p3 = fmaxf(c3 + bv.y, 0.f);
                *(__half2*)(Ch + (size_t)r0 * N + col)       = pack2(p0, p1);
                *(__half2*)(Ch + (size_t)(r0 + 8) * N + col) = pack2(p2, p3);
            }
        }
    }
}

// ---------------- MMA attention (single-pass fp16, causal tile skip, deferred norm) ----------------
// Block = (qt, hb): 64 queries x 512 keys. 8 warps: wm = w&3 (16 rows), wn = w>>2 (half).
#define PT 72                      // fp16 pitch (144 B)
#define SC_PITCH 520
#define SC_OFF   0                 // fp32 [64][520] = 133120 B
#define Q_OFF    133120            // fp16 [64][72] = 9216 B
#define KV_OFF   (Q_OFF + 9216)    // 2 stages x 9216
#define KV_STAGE 9216
#define PT_OFF   (KV_OFF + 2*KV_STAGE)
#define BIAS_OFF (PT_OFF + 9216)   // fp32 [512] bias + fp32 [64] inv
#define ATTN2_SMEM (BIAS_OFF + 2048 + 256)   // 172288 B

__global__ __launch_bounds__(256, 1) void attn_mma_k(
    const __half* __restrict__ Qh, const __half* __restrict__ Kh, const __half* __restrict__ Vh,
    const int* __restrict__ seq, float* __restrict__ probs,
    __half* __restrict__ Oh, int causal, int writeProbs)
{
    extern __shared__ __align__(16) char sm2[];
    uint32_t sbase = smem_u32(sm2);
    float* Sc = (float*)(sm2 + SC_OFF);
    float* biasS = (float*)(sm2 + BIAS_OFF);
    float* invS = biasS + 512;
    const int hb = blockIdx.y, qt = blockIdx.x;
    const int h = hb >> 3, b = hb & 7;
    const int tid = threadIdx.x, lane = tid & 31, w = tid >> 5;
    const int wm = w & 3, wn = w >> 2;
    const float scale = 0.044194173824159216f;   // 1/sqrt(512)

    const int nst = causal ? (qt + 1) : 8;       // active 64-key tiles
    const int bound = nst * 64;                  // active key columns

    for (int i = tid; i < 512; i += 256)
        biasS[i] = (seq[b * SEQ + i] == 0) ? -1e30f : 0.f;

    // Q tile -> smem
    {
        int row = tid >> 2, s0 = (tid & 3) * 16;
        size_t gq = ((size_t)hb * SEQ + qt * 64 + row) * DKV + s0;
        *(uint4*)(sm2 + Q_OFF + (row * PT + s0) * 2)     = *(const uint4*)(Qh + gq);
        *(uint4*)(sm2 + Q_OFF + (row * PT + s0 + 8) * 2) = *(const uint4*)(Qh + gq + 8);
    }

    auto load_kv = [&](const __half* Src, int st, int stage) {
        uint32_t sbst = sbase + KV_OFF + stage * KV_STAGE;
        size_t gbase = ((size_t)hb * SEQ + st * 64) * DKV;
#pragma unroll
        for (int j = 0; j < 2; j++) {
            int seg = tid + j * 256;
            int row = seg >> 3, c = (seg & 7) * 8;
            cp16(sbst + (row * PT + c) * 2, Src + gbase + row * DKV + c);
        }
    };

    load_kv(Kh, 0, 0); CP_COMMIT();
    __syncthreads();

    // resident Q fragments
    uint32_t qf[4][4];
#pragma unroll
    for (int ks = 0; ks < 4; ks++) {
        uint32_t addr = sbase + Q_OFF +
            ((wm * 16 + (lane & 15)) * PT + ks * 16 + ((lane >> 4) << 3)) * 2;
        ldsm_x4(qf[ks], addr);
    }

    // ---- score phase (active tiles only) ----
    for (int st = 0; st < nst; st++) {
        __syncthreads();
        if (st + 1 < nst) { load_kv(Kh, st + 1, (st + 1) & 1); CP_COMMIT(); CP_WAIT1(); }
        else { CP_WAIT0(); }
        __syncthreads();

        uint32_t kb = sbase + KV_OFF + (st & 1) * KV_STAGE;
        float acc[4][4];
#pragma unroll
        for (int i = 0; i < 4; i++)
#pragma unroll
            for (int j = 0; j < 4; j++) acc[i][j] = 0.f;

#pragma unroll
        for (int ks = 0; ks < 4; ks++) {
            uint32_t bh[2][4];
#pragma unroll
            for (int np = 0; np < 2; np++) {
                uint32_t addr = kb + ((wn * 32 + np * 16 + (lane & 7) + ((lane & 16) ? 8 : 0)) * PT
                                      + ks * 16 + ((lane & 8) ? 8 : 0)) * 2;
                ldsm_x4(bh[np], addr);
            }
#pragma unroll
            for (int nt = 0; nt < 4; nt++)
                mma16816(acc[nt], qf[ks], &bh[nt >> 1][(nt & 1) * 2]);
        }

        int r0 = wm * 16 + (lane >> 2);
#pragma unroll
        for (int nt = 0; nt < 4; nt++) {
            int col = st * 64 + wn * 32 + nt * 8 + (lane & 3) * 2;
            float b0 = biasS[col], b1 = biasS[col + 1];
#pragma unroll
            for (int rr = 0; rr < 2; rr++) {
                int row = r0 + rr * 8;
                int tg = qt * 64 + row;
                float v0 = acc[nt][rr * 2 + 0] * scale + b0;
                float v1 = acc[nt][rr * 2 + 1] * scale + b1;
                if (causal) {
                    if (col > tg)     v0 = -1e30f;
                    if (col + 1 > tg) v1 = -1e30f;
                }
                float2 vv; vv.x = v0; vv.y = v1;
                *(float2*)(Sc + row * SC_PITCH + col) = vv;
            }
        }
    }
    __syncthreads();

    // ---- softmax over active cols (unnormalized e kept in smem; inv saved) ----
    {
        for (int r = 0; r < 8; r++) {
            int q = w * 8 + r;
            float* row = Sc + q * SC_PITCH;
            float mx = -3.0e38f;
            for (int c = lane; c < bound; c += 32) mx = fmaxf(mx, row[c]);
#pragma unroll
            for (int o = 16; o; o >>= 1) mx = fmaxf(mx, __shfl_xor_sync(0xffffffffu, mx, o));
            float sum = 0.f;
            for (int c = lane; c < bound; c += 32) {
                float e = __expf(row[c] - mx);
                row[c] = e;
                sum += e;
            }
#pragma unroll
            for (int o = 16; o; o >>= 1) sum += __shfl_xor_sync(0xffffffffu, sum, o);
            float inv = 1.f / sum;
            if (lane == 0) invS[q] = inv;
            float* prow = probs + ((size_t)hb * SEQ + qt * 64 + q) * SEQ;
            if (writeProbs) {
                for (int c = lane; c < bound; c += 32) prow[c] = row[c] * inv;
                for (int c = bound + lane; c < 512; c += 32) prow[c] = 0.f;
            }
        }
    }

    // ---- P @ V phase (unnormalized; scale at epilogue) ----
    load_kv(Vh, 0, 0); CP_COMMIT();
    float oacc[4][4];
#pragma unroll
    for (int i = 0; i < 4; i++)
#pragma unroll
        for (int j = 0; j < 4; j++) oacc[i][j] = 0.f;

    for (int st = 0; st < nst; st++) {
        __syncthreads();
        if (st + 1 < nst) { load_kv(Vh, st + 1, (st + 1) & 1); CP_COMMIT(); CP_WAIT1(); }
        else { CP_WAIT0(); }

        // convert P tile st -> fp16
        {
            int row = tid >> 2, cb = (tid & 3) * 16;
            const float* srow = Sc + row * SC_PITCH + st * 64 + cb;
            __half* ph = (__half*)(sm2 + PT_OFF) + row * PT + cb;
#pragma unroll
            for (int j2 = 0; j2 < 16; j2 += 4) {
                float4 p4 = *(const float4*)(srow + j2);
                *(__half2*)(ph + j2)     = pack2(p4.x, p4.y);
                *(__half2*)(ph + j2 + 2) = pack2(p4.z, p4.w);
            }
        }
        __syncthreads();

        uint32_t vb = sbase + KV_OFF + (st & 1) * KV_STAGE;
#pragma unroll
        for (int ks = 0; ks < 4; ks++) {
            uint32_t af[4], vbf[2][4];
            uint32_t aaddr = sbase + PT_OFF +
                ((wm * 16 + (lane & 15)) * PT + ks * 16 + ((lane >> 4) << 3)) * 2;
            ldsm_x4(af, aaddr);
#pragma unroll
            for (int np = 0; np < 2; np++) {
                uint32_t addr = vb + ((ks * 16 + (lane & 7) + ((lane & 8) ? 8 : 0)) * PT
                                      + wn * 32 + np * 16 + ((lane & 16) ? 8 : 0)) * 2;
                ldsm_x4_t(vbf[np], addr);
            }
#pragma unroll
            for (int nt = 0; nt < 4; nt++)
                mma16816(oacc[nt], af, &vbf[nt >> 1][(nt & 1) * 2]);
        }
    }

    // O epilogue -> fp16 (scale by per-row inv), layout [b*SEQ+t][h*64+e]
    int r0 = wm * 16 + (lane >> 2);
    float inv0 = invS[r0], inv1 = invS[r0 + 8];
#pragma unroll
    for (int nt = 0; nt < 4; nt++) {
        int gc = h * DKV + wn * 32 + nt * 8 + (lane & 3) * 2;
#pragma unroll
        for (int rr = 0; rr < 2; rr++) {
            int row = b * SEQ + qt * 64 + r0 + rr * 8;
            float iv = rr ? inv1 : inv0;
            *(__half2*)(Oh + (size_t)row * DMOD + gc) =
                pack2(oacc[nt][rr * 2 + 0] * iv, oacc[nt][rr * 2 + 1] * iv);
        }
    }
}

// ---------------- layernorm(y + res) -> fp32 out + fp16 ----------------
__global__ __launch_bounds__(128) void ln_k(
    const float* __restrict__ y, const float* __restrict__ res,
    const float* __restrict__ g, const float* __restrict__ b,
    float* __restrict__ out, __half* __restrict__ oh)
{
    __shared__ float red[8];
    int n = blockIdx.x, tid = threadIdx.x;
    int c = tid * 4;
    float4 yv = *(const float4*)(y   + (size_t)n * DMOD + c);
    float4 rv = *(const float4*)(res + (size_t)n * DMOD + c);
    float v0 = yv.x + rv.x, v1 = yv.y + rv.y, v2 = yv.z + rv.z, v3 = yv.w + rv.w;

    float s = v0 + v1 + v2 + v3;
    int lane = tid & 31, warp = tid >> 5;
#pragma unroll
    for (int o = 16; o; o >>= 1) s += __shfl_xor_sync(0xffffffffu, s, o);
    if (lane == 0) red[warp] = s;
    __syncthreads();
    float mu = (red[0] + red[1] + red[2] + red[3]) * (1.f / DMOD);

    float d0 = v0 - mu, d1 = v1 - mu, d2 = v2 - mu, d3 = v3 - mu;
    float ss = d0 * d0 + d1 * d1 + d2 * d2 + d3 * d3;
#pragma unroll
    for (int o = 16; o; o >>= 1) ss += __shfl_xor_sync(0xffffffffu, ss, o);
    if (lane == 0) red[4 + warp] = ss;
    __syncthreads();
    float var = (red[4] + red[5] + red[6] + red[7]) * (1.f / DMOD);
    float is = rsqrtf(var + 1e-5f);

    float4 gv = *(const float4*)(g + c);
    float4 bv = *(const float4*)(b + c);
    float4 ov;
    ov.x = d0 * is * gv.x + bv.x;
    ov.y = d1 * is * gv.y + bv.y;
    ov.z = d2 * is * gv.z + bv.z;
    ov.w = d3 * is * gv.w + bv.w;
    *(float4*)(out + (size_t)n * DMOD + c) = ov;
    *(__half2*)(oh + (size_t)n * DMOD + c)     = pack2(ov.x, ov.y);
    *(__half2*)(oh + (size_t)n * DMOD + c + 2) = pack2(ov.z, ov.w);
}

// ---------------- host ----------------
extern "C" void kernel_launch(void* const* d_in, const int* in_sizes, int n_in,
                              void* d_out, int out_size)
{
    const int*   tgt_seq = (const int*)d_in[0];
    const int*   tgt_pos = (const int*)d_in[1];
    const int*   src_seq = (const int*)d_in[2];
    const float* enc_out = (const float*)d_in[3];
    const float* tgt_emb = (const float*)d_in[4];
    const float* pos_emb = (const float*)d_in[5];
    const float* slf_wq  = (const float*)d_in[6];
    const float* slf_wk  = (const float*)d_in[7];
    const float* slf_wv  = (const float*)d_in[8];
    const float* slf_pw  = (const float*)d_in[9];
    const float* slf_pb  = (const float*)d_in[10];
    const float* slf_g   = (const float*)d_in[11];
    const float* slf_b   = (const float*)d_in[12];
    const float* enc_wq  = (const float*)d_in[13];
    const float* enc_wk  = (const float*)d_in[14];
    const float* enc_wv  = (const float*)d_in[15];
    const float* enc_pw  = (const float*)d_in[16];
    const float* enc_pb  = (const float*)d_in[17];
    const float* enc_g   = (const float*)d_in[18];
    const float* enc_b   = (const float*)d_in[19];
    const float* ffn_w1  = (const float*)d_in[20];
    const float* ffn_b1  = (const float*)d_in[21];
    const float* ffn_w2  = (const float*)d_in[22];
    const float* ffn_b2  = (const float*)d_in[23];
    const float* ffn_g   = (const float*)d_in[24];
    const float* ffn_b   = (const float*)d_in[25];

    float *xp, *yp;
    __half *qkvh, *xh, *eh, *aoh, *hh, *wb;
    cudaGetSymbolAddress((void**)&xp,   g_x);
    cudaGetSymbolAddress((void**)&yp,   g_y);
    cudaGetSymbolAddress((void**)&qkvh, g_qkvh);
    cudaGetSymbolAddress((void**)&xh,   g_xh);
    cudaGetSymbolAddress((void**)&eh,   g_eh);
    cudaGetSymbolAddress((void**)&aoh,  g_aoh);
    cudaGetSymbolAddress((void**)&hh,   g_hh);
    cudaGetSymbolAddress((void**)&wb,   g_wb);

    cudaFuncSetAttribute(attn_mma_k, cudaFuncAttributeMaxDynamicSharedMemorySize, ATTN2_SMEM);
    cudaFuncSetAttribute(gemm_mma_k, cudaFuncAttributeMaxDynamicSharedMemorySize, GM_SMEM);

    const int full = (out_size >= (int)FULL_OUT) ? 1 : 0;
    float* out_f = (float*)d_out;
    float* probs_slf = out_f + SLF_OFF;
    float* probs_enc = out_f + ENC_OFF;

    __half* qh = qkvh;
    __half* kh = qkvh + 2097152;
    __half* vh = qkvh + 4194304;

    embed_k<<<NTOK, 128>>>(tgt_seq, tgt_pos, tgt_emb, pos_emb, xp, xh);
    conv_h_k<<<(NTOK * DMOD) / 256, 256>>>(enc_out, eh, NTOK * DMOD);

    // ---- batched weight prep: 4 launches ----
    {
        P6 srcs;
        srcs.p[0] = slf_wq; srcs.p[1] = slf_wk; srcs.p[2] = slf_wv;
        srcs.p[3] = enc_wq; srcs.p[4] = enc_wk; srcs.p[5] = enc_wv;
        qkv_repack_all<<<dim3(64, 6, 6), 256>>>(srcs, wb);
        pw_repack_all<<<dim3(16, 16, 12), dim3(32, 8)>>>(slf_pw, enc_pw, wb);
        ffn_repack_all<<<dim3(64, 16, 6), dim3(32, 8)>>>(ffn_w1, wb, DMOD, DFF, WOFF_W1);
        ffn_repack_all<<<dim3(16, 64, 6), dim3(32, 8)>>>(ffn_w2, wb, DFF, DMOD, WOFF_W2);
    }

    dim3 gAttn(8, NHB);

    for (int l = 0; l < NL; l++) {
        size_t LB = (size_t)l * WL_SIZE;

        // ---- self attention: fused QKV (N=1536) ----
        gemm_mma_k<<<dim3(12, 32), 128, GM_SMEM>>>(xh, xh, wb + LB + WOFF_SQ,
            nullptr, nullptr, qkvh, NTOK, 1536, DMOD, 3);
        attn_mma_k<<<gAttn, 256, ATTN2_SMEM>>>(qh, kh, vh, tgt_seq,
            probs_slf + (size_t)l * ATT_PER_L, aoh, 1, full);
        gemm_mma_k<<<dim3(4, 32), 128, GM_SMEM>>>(aoh, aoh, wb + LB + WOFF_SPW,
            slf_pb + (size_t)l * DMOD, yp, nullptr, NTOK, DMOD, DMOD, 1);
        ln_k<<<NTOK, 128>>>(yp, xp, slf_g + (size_t)l * DMOD, slf_b + (size_t)l * DMOD,
                            xp, xh);

        // ---- cross attention: merged Q|K|V (N=1536; A = xh for q cols, eh for kv cols) ----
        gemm_mma_k<<<dim3(12, 32), 128, GM_SMEM>>>(xh, eh, wb + LB + WOFF_EQ,
            nullptr, nullptr, qkvh, NTOK, 1536, DMOD, 3);
        attn_mma_k<<<gAttn, 256, ATTN2_SMEM>>>(qh, kh, vh, src_seq,
            probs_enc + (size_t)l * ATT_PER_L, aoh, 0, full);
        gemm_mma_k<<<dim3(4, 32), 128, GM_SMEM>>>(aoh, aoh, wb + LB + WOFF_EPW,
            enc_pb + (size_t)l * DMOD, yp, nullptr, NTOK, DMOD, DMOD, 1);
        ln_k<<<NTOK, 128>>>(yp, xp, enc_g + (size_t)l * DMOD, enc_b + (size_t)l * DMOD,
                            xp, xh);

        // ---- FFN ----
        gemm_mma_k<<<dim3(16, 32), 128, GM_SMEM>>>(xh, xh, wb + LB + WOFF_W1,
            ffn_b1 + (size_t)l * DFF, nullptr, hh, NTOK, DFF, DMOD, 2);
        gemm_mma_k<<<dim3(4, 32), 128, GM_SMEM>>>(hh, hh, wb + LB + WOFF_W2,
            ffn_b2 + (size_t)l * DMOD, yp, nullptr, NTOK, DMOD, DFF, 1);
        ln_k<<<NTOK, 128>>>(yp, xp, ffn_g + (size_t)l * DMOD, ffn_b + (size_t)l * DMOD,
                            xp, xh);
    }

    size_t copy_elems = (size_t)out_size < (size_t)X_ELEMS ? (size_t)out_size : (size_t)X_ELEMS;
    cudaMemcpyAsync(d_out, xp, copy_elems * sizeof(float), cudaMemcpyDeviceToDevice);
}